// round 10
// baseline (speedup 1.0000x reference)
#include <cuda_runtime.h>
#include <cuda_bf16.h>
#include <math.h>
#include <stdint.h>

// Problem constants
#define BB   4
#define NSEQ 4096
#define EE   1024
#define HH   16
#define DD   64
#define MM   256
#define TT   (BB*NSEQ)     // 16384
#define BHn  (BB*HH)       // 64
#define NSEG 8

#define RATIO 0.0625f
#define EPSK  1e-4f
#define SCQ   0.3535533905932738f   // 64^-0.25

// ---------------- device scratch ----------------
__device__ float g_q[(size_t)BHn*NSEQ*DD];
__device__ float g_k[(size_t)BHn*NSEQ*DD];
__device__ float g_v[(size_t)BHn*NSEQ*DD];
__device__ float g_ksum[BHn*MM];
__device__ float g_ksump[(size_t)NSEG*BHn*MM];
__device__ float g_svp[(size_t)NSEG*BHn*DD];
__device__ float g_ctxp[(size_t)NSEG*BHn*MM*DD];
__device__ float g_ctx[BHn*MM*DD];
__device__ float g_dinv[(size_t)BHn*NSEQ];
__device__ float g_kstab;
__device__ __nv_bfloat16 g_ah[(size_t)TT*EE];
__device__ __nv_bfloat16 g_al[(size_t)TT*EE];
__device__ __nv_bfloat16 g_wh[(size_t)2*EE*EE];   // two weight slots (Wk@0, Wv@E*E; reused)
__device__ __nv_bfloat16 g_wl[(size_t)2*EE*EE];
__device__ __nv_bfloat16 g_qfh[(size_t)BHn*NSEQ*MM];
__device__ __nv_bfloat16 g_qfl[(size_t)BHn*NSEQ*MM];

// ---------------- helpers ----------------
__device__ __forceinline__ void atomicMaxFloat(float* addr, float v) {
    if (v >= 0.f) atomicMax((int*)addr, __float_as_int(v));
    else          atomicMin((unsigned int*)addr, __float_as_uint(v));
}

__global__ void init_kernel() {
    if (blockIdx.x == 0 && threadIdx.x == 0) g_kstab = -INFINITY;
}

__device__ __forceinline__ uint32_t smem_u32(const void* p) {
    uint32_t a;
    asm("{ .reg .u64 t; cvta.to.shared.u64 t, %1; cvt.u32.u64 %0, t; }" : "=r"(a) : "l"(p));
    return a;
}

__device__ __forceinline__ void mma16816(float* c, const uint32_t* a, const uint32_t* b) {
    asm volatile(
        "mma.sync.aligned.m16n8k16.row.col.f32.bf16.bf16.f32 "
        "{%0,%1,%2,%3},{%4,%5,%6,%7},{%8,%9},{%0,%1,%2,%3};"
        : "+f"(c[0]), "+f"(c[1]), "+f"(c[2]), "+f"(c[3])
        : "r"(a[0]), "r"(a[1]), "r"(a[2]), "r"(a[3]), "r"(b[0]), "r"(b[1]));
}

__device__ __forceinline__ void ldmx4(uint32_t* r, uint32_t addr) {
    asm volatile("ldmatrix.sync.aligned.m8n8.x4.shared.b16 {%0,%1,%2,%3}, [%4];"
        : "=r"(r[0]), "=r"(r[1]), "=r"(r[2]), "=r"(r[3]) : "r"(addr));
}

// packed fp32x2
__device__ __forceinline__ void fma2(unsigned long long& d, unsigned long long a, unsigned long long b) {
    asm("fma.rn.f32x2 %0, %1, %2, %0;" : "+l"(d) : "l"(a), "l"(b));
}
__device__ __forceinline__ unsigned long long pack2(float x) {
    unsigned long long r;
    asm("mov.b64 %0, {%1, %1};" : "=l"(r) : "f"(x));
    return r;
}
__device__ __forceinline__ float2 unpack2(unsigned long long v) {
    float2 f;
    asm("mov.b64 {%0, %1}, %2;" : "=f"(f.x), "=f"(f.y) : "l"(v));
    return f;
}
__device__ __forceinline__ float f4c(const float4& v, int j) {
    return j == 0 ? v.x : j == 1 ? v.y : j == 2 ? v.z : v.w;
}

// ---------------- fp32 -> bf16 hi/lo split ----------------
__device__ __forceinline__ void split_body(const float* __restrict__ src,
    __nv_bfloat16* __restrict__ hi, __nv_bfloat16* __restrict__ lo,
    int n4, int start, int stride)
{
    const float4* s4 = (const float4*)src;
    uint2* h2 = (uint2*)hi;
    uint2* l2 = (uint2*)lo;
    for (int i = start; i < n4; i += stride) {
        float4 v = s4[i];
        __nv_bfloat16 h0 = __float2bfloat16(v.x);
        __nv_bfloat16 h1 = __float2bfloat16(v.y);
        __nv_bfloat16 h2b = __float2bfloat16(v.z);
        __nv_bfloat16 h3 = __float2bfloat16(v.w);
        __nv_bfloat16 l0 = __float2bfloat16(v.x - __bfloat162float(h0));
        __nv_bfloat16 l1 = __float2bfloat16(v.y - __bfloat162float(h1));
        __nv_bfloat16 l2b = __float2bfloat16(v.z - __bfloat162float(h2b));
        __nv_bfloat16 l3 = __float2bfloat16(v.w - __bfloat162float(h3));
        uint2 hv, lv;
        hv.x = ((uint32_t)__bfloat16_as_ushort(h1) << 16) | __bfloat16_as_ushort(h0);
        hv.y = ((uint32_t)__bfloat16_as_ushort(h3) << 16) | __bfloat16_as_ushort(h2b);
        lv.x = ((uint32_t)__bfloat16_as_ushort(l1) << 16) | __bfloat16_as_ushort(l0);
        lv.y = ((uint32_t)__bfloat16_as_ushort(l3) << 16) | __bfloat16_as_ushort(l2b);
        h2[i] = hv;
        l2[i] = lv;
    }
}

__global__ __launch_bounds__(256) void split_kernel(
    const float* __restrict__ src, __nv_bfloat16* __restrict__ hi,
    __nv_bfloat16* __restrict__ lo, int n4)
{
    split_body(src, hi, lo, n4, blockIdx.x * 256 + threadIdx.x, gridDim.x * 256);
}

// two matrices in one launch (Wk -> slot0, Wv -> slot1)
__global__ __launch_bounds__(256) void split2_kernel(
    const float* __restrict__ s0, __nv_bfloat16* __restrict__ h0, __nv_bfloat16* __restrict__ l0,
    const float* __restrict__ s1, __nv_bfloat16* __restrict__ h1, __nv_bfloat16* __restrict__ l1,
    int n4)
{
    int half = blockIdx.x >> 9;          // 1024 blocks: 0-511 -> s0, 512-1023 -> s1
    int bid  = blockIdx.x & 511;
    if (half == 0) split_body(s0, h0, l0, n4, bid * 256 + threadIdx.x, 512 * 256);
    else           split_body(s1, h1, l1, n4, bid * 256 + threadIdx.x, 512 * 256);
}

// ---------------- bf16-split mma.sync GEMM: K-chunk 64, 3-stage, ldmatrix ----------------
// Change this round: removed redundant trailing __syncthreads in the mainloop.
#define NCHUNK 48          // 3 passes * 1024/64
#define STG_BYTES 32768    // A(16K) + B(16K) per stage

template<int OUT_MODE>
__global__ __launch_bounds__(256) void gemm_mma(
    const __nv_bfloat16* __restrict__ Ah, const __nv_bfloat16* __restrict__ Al,
    const __nv_bfloat16* __restrict__ Wh, const __nv_bfloat16* __restrict__ Wl,
    const float* __restrict__ bias, float* __restrict__ C)
{
    extern __shared__ __align__(128) char gsm[];

    const int tid  = threadIdx.x;
    const int lane = tid & 31;
    const int wid  = tid >> 5;
    const int wm   = wid & 1;
    const int wn   = wid >> 1;
    const int bm   = blockIdx.y * 128;
    const int bn   = blockIdx.x * 128;

    const __nv_bfloat16* pA[3] = {Ah, Ah, Al};
    const __nv_bfloat16* pB[3] = {Wh, Wl, Wh};

    float c[4][4][4];
#pragma unroll
    for (int i = 0; i < 4; i++)
#pragma unroll
        for (int j = 0; j < 4; j++)
#pragma unroll
            for (int q = 0; q < 4; q++) c[i][j][q] = 0.f;

    const uint32_t smem_base = smem_u32(gsm);

    auto prefetch = [&](int s, int stage) {
        if (s < NCHUNK) {
            const int ph = s >> 4;
            const int kk = (s & 15) << 6;
            const __nv_bfloat16* gA = pA[ph];
            const __nv_bfloat16* gB = pB[ph];
            const uint32_t aB = smem_base + stage * STG_BYTES;
            const uint32_t bB = aB + 16384;
#pragma unroll
            for (int it = 0; it < 4; it++) {
                int idx = it * 256 + tid;
                int row = idx >> 3;
                int pb  = idx & 7;
                uint32_t doff = row * 128 + ((pb ^ (row & 7)) << 4);
                const void* srcA = gA + (size_t)(bm + row) * EE + kk + pb * 8;
                const void* srcB = gB + (size_t)(bn + row) * EE + kk + pb * 8;
                asm volatile("cp.async.cg.shared.global [%0], [%1], 16;" :: "r"(aB + doff), "l"(srcA));
                asm volatile("cp.async.cg.shared.global [%0], [%1], 16;" :: "r"(bB + doff), "l"(srcB));
            }
        }
        asm volatile("cp.async.commit_group;" ::: "memory");
    };

    prefetch(0, 0);
    prefetch(1, 1);

    for (int s = 0; s < NCHUNK; s++) {
        const int stage = s % 3;
        asm volatile("cp.async.wait_group 1;" ::: "memory");
        __syncthreads();
        // prefetch(s+2) targets buffer (s+2)%3 == (s-1)%3; every warp past the
        // sync above has finished compute(s-1) in program order -> safe.
        prefetch(s + 2, (s + 2) % 3);

        const uint32_t cA = smem_base + stage * STG_BYTES;
        const uint32_t cB = cA + 16384;
#pragma unroll
        for (int ks = 0; ks < 4; ks++) {
            uint32_t bf[4][2];
#pragma unroll
            for (int jb = 0; jb < 2; jb++) {
                int row = wn * 32 + jb * 16 + ((lane >> 4) << 3) + (lane & 7);
                int pb  = ks * 2 + ((lane >> 3) & 1);
                uint32_t ad = cB + row * 128 + ((pb ^ (row & 7)) << 4);
                uint32_t t4[4];
                ldmx4(t4, ad);
                bf[jb * 2][0] = t4[0]; bf[jb * 2][1] = t4[1];
                bf[jb * 2 + 1][0] = t4[2]; bf[jb * 2 + 1][1] = t4[3];
            }
#pragma unroll
            for (int i = 0; i < 4; i++) {
                int r0 = wm * 64 + i * 16;
                int row = r0 + (((lane >> 3) & 1) << 3) + (lane & 7);
                int pb  = ks * 2 + ((lane >> 4) & 1);
                uint32_t ad = cA + row * 128 + ((pb ^ (row & 7)) << 4);
                uint32_t af[4];
                ldmx4(af, ad);
#pragma unroll
                for (int j = 0; j < 4; j++)
                    mma16816(c[i][j], af, bf[j]);
            }
        }
        // (end-of-iteration __syncthreads removed)
    }

#pragma unroll
    for (int i = 0; i < 4; i++) {
        int r = bm + wm * 64 + i * 16 + (lane >> 2);
#pragma unroll
        for (int j = 0; j < 4; j++) {
            int col = bn + wn * 32 + j * 8 + (lane & 3) * 2;
            float b0 = bias[col], b1 = bias[col + 1];
            float2 v0 = make_float2(c[i][j][0] + b0, c[i][j][1] + b1);
            float2 v1 = make_float2(c[i][j][2] + b0, c[i][j][3] + b1);
            if (OUT_MODE == 0) {
                *(float2*)(C + (size_t)r * EE + col)       = v0;
                *(float2*)(C + (size_t)(r + 8) * EE + col) = v1;
            } else {
                int h_ = col >> 6, d0 = col & 63;
                int b_ = r >> 12, n_ = r & 4095;
                size_t base = ((size_t)(b_ * HH + h_) * NSEQ);
                *(float2*)(C + (base + n_)     * DD + d0) = v0;
                *(float2*)(C + (base + n_ + 8) * DD + d0) = v1;
            }
        }
    }
}

// ---------------- fused: unstabilized k-features + context/ksum/sv partials + global dd max ----------------
// Change this round: dd loop fully unrolled (reg budget 128 at occ 2).
__global__ __launch_bounds__(256, 2) void ctx_fused(
    const float* __restrict__ K, const float* __restrict__ V,
    const float* __restrict__ proj)
{
    extern __shared__ float sm[];
    float* sPT = sm;               // [64][256]   64 KB
    float* sKF = sPT + DD * MM;    // [32][256]   32 KB
    float* sXk = sKF + 32 * MM;    // [32][64]     8 KB
    float* sV  = sXk + 32 * DD;    // [32][64]     8 KB
    __shared__ float swm[8];

    const int tid = threadIdx.x;
    const int bh  = blockIdx.x;
    const int seg = blockIdx.y;
    const int lane = tid & 31;
    const int w    = tid >> 5;
    const int m0   = lane * 8;
    const int tx   = tid & 15;     // d group (4 d)
    const int ty   = tid >> 4;     // m group (16 m)

    {
        const float4* pr = (const float4*)(proj + tid * DD);
#pragma unroll
        for (int t = 0; t < 16; t++) {
            float4 v = pr[t];
            int d = t * 4;
            sPT[(d + 0) * MM + tid] = v.x;
            sPT[(d + 1) * MM + tid] = v.y;
            sPT[(d + 2) * MM + tid] = v.z;
            sPT[(d + 3) * MM + tid] = v.w;
        }
    }

    unsigned long long cacc[16][2];
#pragma unroll
    for (int i = 0; i < 16; i++) { cacc[i][0] = 0ull; cacc[i][1] = 0ull; }
    float kacc = 0.f;
    float svacc = 0.f;
    float ddmax = -1e30f;

    for (int it = 0; it < 16; it++) {
        const int n0 = seg * 512 + it * 32;
        __syncthreads();
        {
            const float4* kr = (const float4*)(K + ((size_t)bh * NSEQ + n0) * DD);
            const float4* vr = (const float4*)(V + ((size_t)bh * NSEQ + n0) * DD);
            float4* sk4 = (float4*)sXk;
            float4* sv4 = (float4*)sV;
#pragma unroll
            for (int i = 0; i < 2; i++) {
                int f = tid * 2 + i;
                float4 kv = kr[f];
                sk4[f] = make_float4(kv.x * SCQ, kv.y * SCQ, kv.z * SCQ, kv.w * SCQ);
                sv4[f] = vr[f];
            }
        }
        __syncthreads();

        // dd + unstabilized exp -> sKF (4 rows per warp); FULL unroll over d
        {
            unsigned long long a2[4][4];
#pragma unroll
            for (int r = 0; r < 4; r++)
#pragma unroll
                for (int j = 0; j < 4; j++) a2[r][j] = 0ull;

#pragma unroll
            for (int d0 = 0; d0 < DD; d0 += 4) {
                float4 xv[4];
#pragma unroll
                for (int r = 0; r < 4; r++)
                    xv[r] = *(const float4*)&sXk[(w * 4 + r) * DD + d0];
#pragma unroll
                for (int dd = 0; dd < 4; dd++) {
                    const ulonglong2* bp = (const ulonglong2*)&sPT[(d0 + dd) * MM + m0];
                    ulonglong2 b01 = bp[0], b23 = bp[1];
#pragma unroll
                    for (int r = 0; r < 4; r++) {
                        unsigned long long av = pack2(f4c(xv[r], dd));
                        fma2(a2[r][0], av, b01.x); fma2(a2[r][1], av, b01.y);
                        fma2(a2[r][2], av, b23.x); fma2(a2[r][3], av, b23.y);
                    }
                }
            }
#pragma unroll
            for (int r = 0; r < 4; r++) {
                const float* xr = &sXk[(w * 4 + r) * DD];
                float x0 = xr[lane * 2], x1 = xr[lane * 2 + 1];
                float p = x0 * x0 + x1 * x1;
#pragma unroll
                for (int o = 16; o > 0; o >>= 1) p += __shfl_xor_sync(0xffffffffu, p, o);
                float sub = 0.5f * p;
                float o8[8];
#pragma unroll
                for (int j = 0; j < 4; j++) {
                    float2 f = unpack2(a2[r][j]);
                    ddmax = fmaxf(ddmax, fmaxf(f.x, f.y));
                    o8[j * 2]     = __expf(f.x - sub);
                    o8[j * 2 + 1] = __expf(f.y - sub);
                }
                float4* dst = (float4*)&sKF[(w * 4 + r) * MM + m0];
                dst[0] = *(float4*)(o8);
                dst[1] = *(float4*)(o8 + 4);
            }
        }
        __syncthreads();

#pragma unroll
        for (int r = 0; r < 32; r++) kacc += sKF[r * MM + tid];

        if (tid < 64) {
#pragma unroll
            for (int r = 0; r < 32; r++) svacc += sV[r * DD + tid];
        }

        const ulonglong2* sV2 = (const ulonglong2*)sV;
#pragma unroll 4
        for (int r = 0; r < 32; r++) {
            ulonglong2 bv = sV2[r * 16 + tx];
            const float4* kf4 = (const float4*)&sKF[r * MM + ty * 16];
            float4 kq[4];
            kq[0] = kf4[0]; kq[1] = kf4[1]; kq[2] = kf4[2]; kq[3] = kf4[3];
#pragma unroll
            for (int q = 0; q < 4; q++) {
#pragma unroll
                for (int j = 0; j < 4; j++) {
                    unsigned long long av = pack2(f4c(kq[q], j));
                    fma2(cacc[q * 4 + j][0], av, bv.x);
                    fma2(cacc[q * 4 + j][1], av, bv.y);
                }
            }
        }
    }

    g_ksump[((size_t)seg * BHn + bh) * MM + tid] = kacc;
    if (tid < 64) g_svp[((size_t)seg * BHn + bh) * DD + tid] = svacc;

    float* cp = g_ctxp + ((size_t)seg * BHn + bh) * MM * DD;
#pragma unroll
    for (int i = 0; i < 16; i++) {
        float2 f0 = unpack2(cacc[i][0]);
        float2 f1 = unpack2(cacc[i][1]);
        *(float4*)(cp + (ty * 16 + i) * DD + tx * 4) = make_float4(f0.x, f0.y, f1.x, f1.y);
    }

#pragma unroll
    for (int o = 16; o > 0; o >>= 1)
        ddmax = fmaxf(ddmax, __shfl_xor_sync(0xffffffffu, ddmax, o));
    if (lane == 0) swm[w] = ddmax;
    __syncthreads();
    if (tid == 0) {
        float m = swm[0];
#pragma unroll
        for (int i = 1; i < 8; i++) m = fmaxf(m, swm[i]);
        atomicMaxFloat(&g_kstab, m);
    }
}

// ---------------- assemble ctx + ksum from unstabilized partials ----------------
__global__ __launch_bounds__(256) void ctx_reduce_kernel() {
    const float escale = __expf(-g_kstab);
    int i = blockIdx.x * 256 + threadIdx.x;
    if (i < BHn * MM * DD) {
        int bh = i >> 14;
        int d  = i & 63;
        float U = 0.f, Sv = 0.f;
#pragma unroll
        for (int seg = 0; seg < NSEG; seg++) {
            U  += g_ctxp[(size_t)seg * BHn * MM * DD + i];
            Sv += g_svp[((size_t)seg * BHn + bh) * DD + d];
        }
        g_ctx[i] = RATIO * (escale * U + EPSK * Sv);
    }
    if (i < BHn * MM) {
        float T = 0.f;
#pragma unroll
        for (int seg = 0; seg < NSEG; seg++)
            T += g_ksump[(size_t)seg * BHn * MM + i];
        g_ksum[i] = RATIO * (escale * T + EPSK * (float)NSEQ);
    }
}

// ---------------- query features only: qf (bf16 hi/lo) + dinv (unchanged from R9) ----------------
__global__ __launch_bounds__(256, 3) void qf_kernel(
    const float* __restrict__ Q, const float* __restrict__ proj,
    __nv_bfloat16* __restrict__ QFh, __nv_bfloat16* __restrict__ QFl,
    float* __restrict__ Dinv)
{
    extern __shared__ float sm[];
    float* sPT = sm;              // [64][256]  64 KB
    float* sX  = sPT + DD * MM;   // [32][64]    8 KB
    float* sKs = sX + 32 * DD;    // [256]       1 KB

    const int tid = threadIdx.x;
    const int bh  = blockIdx.x;
    const int nblk = blockIdx.y * 256;
    const int lane = tid & 31;
    const int w    = tid >> 5;
    const int m0   = lane * 8;

    {
        const float4* pr = (const float4*)(proj + tid * DD);
#pragma unroll
        for (int t = 0; t < 16; t++) {
            float4 v = pr[t];
            int d = t * 4;
            sPT[(d + 0) * MM + tid] = v.x;
            sPT[(d + 1) * MM + tid] = v.y;
            sPT[(d + 2) * MM + tid] = v.z;
            sPT[(d + 3) * MM + tid] = v.w;
        }
        sKs[tid] = g_ksum[bh * MM + tid];
    }

    for (int it = 0; it < 8; it++) {
        const int n0 = nblk + it * 32;
        __syncthreads();
        {
            const float4* xr = (const float4*)(Q + ((size_t)bh * NSEQ + n0) * DD);
            float4* sx4 = (float4*)sX;
#pragma unroll
            for (int i = 0; i < 2; i++) {
                int f = tid * 2 + i;
                float4 v = xr[f];
                sx4[f] = make_float4(v.x * SCQ, v.y * SCQ, v.z * SCQ, v.w * SCQ);
            }
        }
        __syncthreads();

        unsigned long long a2[4][4];
#pragma unroll
        for (int r = 0; r < 4; r++)
#pragma unroll
            for (int j = 0; j < 4; j++) a2[r][j] = 0ull;

#pragma unroll 2
        for (int d0 = 0; d0 < DD; d0 += 4) {
            float4 xv[4];
#pragma unroll
            for (int r = 0; r < 4; r++)
                xv[r] = *(const float4*)&sX[(w * 4 + r) * DD + d0];
#pragma unroll
            for (int dd = 0; dd < 4; dd++) {
                const ulonglong2* bp = (const ulonglong2*)&sPT[(d0 + dd) * MM + m0];
                ulonglong2 b01 = bp[0], b23 = bp[1];
#pragma unroll
                for (int r = 0; r < 4; r++) {
                    unsigned long long av = pack2(f4c(xv[r], dd));
                    fma2(a2[r][0], av, b01.x); fma2(a2[r][1], av, b01.y);
                    fma2(a2[r][2], av, b23.x); fma2(a2[r][3], av, b23.y);
                }
            }
        }

#pragma unroll
        for (int r = 0; r < 4; r++) {
            float v8[8];
#pragma unroll
            for (int j = 0; j < 4; j++) {
                float2 f = unpack2(a2[r][j]);
                v8[j * 2] = f.x; v8[j * 2 + 1] = f.y;
            }
            float mx = v8[0];
#pragma unroll
            for (int j = 1; j < 8; j++) mx = fmaxf(mx, v8[j]);
#pragma unroll
            for (int o = 16; o > 0; o >>= 1)
                mx = fmaxf(mx, __shfl_xor_sync(0xffffffffu, mx, o));

            const float* xr = &sX[(w * 4 + r) * DD];
            float x0 = xr[lane * 2], x1 = xr[lane * 2 + 1];
            float p = x0 * x0 + x1 * x1;
#pragma unroll
            for (int o = 16; o > 0; o >>= 1) p += __shfl_xor_sync(0xffffffffu, p, o);
            float sub = 0.5f * p + mx;

            float o8[8];
            float dp = 0.f;
            ushort hb[8], lb[8];
#pragma unroll
            for (int j = 0; j < 8; j++) {
                o8[j] = RATIO * (__expf(v8[j] - sub) + EPSK);
                dp += o8[j] * sKs[m0 + j];
                __nv_bfloat16 h = __float2bfloat16(o8[j]);
                hb[j] = __bfloat16_as_ushort(h);
                lb[j] = __bfloat16_as_ushort(__float2bfloat16(o8[j] - __bfloat162float(h)));
            }
#pragma unroll
            for (int o = 16; o > 0; o >>= 1) dp += __shfl_xor_sync(0xffffffffu, dp, o);

            const int n = n0 + w * 4 + r;
            size_t base = ((size_t)bh * NSEQ + n) * MM + m0;
            uint4 hv, lv;
            hv.x = ((uint32_t)hb[1] << 16) | hb[0]; hv.y = ((uint32_t)hb[3] << 16) | hb[2];
            hv.z = ((uint32_t)hb[5] << 16) | hb[4]; hv.w = ((uint32_t)hb[7] << 16) | hb[6];
            lv.x = ((uint32_t)lb[1] << 16) | lb[0]; lv.y = ((uint32_t)lb[3] << 16) | lb[2];
            lv.z = ((uint32_t)lb[5] << 16) | lb[4]; lv.w = ((uint32_t)lb[7] << 16) | lb[6];
            *(uint4*)(QFh + base) = hv;
            *(uint4*)(QFl + base) = lv;
            if (lane == 0) Dinv[(size_t)bh * NSEQ + n] = 1.f / dp;
        }
    }
}

// ---------------- yv_gemm: per-head y = qf @ ctx^T, * dinv, bf16-split output (unchanged) ----------------
#define YV_NCHUNK 12       // 3 passes * 256/64
#define YV_ASTG  16384     // A stage: 128 rows x 128B

__global__ __launch_bounds__(256, 2) void yv_gemm(
    const __nv_bfloat16* __restrict__ QFh, const __nv_bfloat16* __restrict__ QFl,
    __nv_bfloat16* __restrict__ OutH, __nv_bfloat16* __restrict__ OutL)
{
    extern __shared__ __align__(128) char gsm[];
    const uint32_t smem_base = smem_u32(gsm);
    const uint32_t sBH = smem_base + 49152;
    const uint32_t sBL = smem_base + 81920;

    const int tid  = threadIdx.x;
    const int lane = tid & 31;
    const int wid  = tid >> 5;
    const int wm   = wid & 1;
    const int wn   = wid >> 1;
    const int bh   = blockIdx.y;
    const int bm   = blockIdx.x * 128;
    const int b_   = bh >> 4;
    const int h_   = bh & 15;

    {
        const float* cbase = g_ctx + (size_t)bh * MM * DD;
#pragma unroll
        for (int t = 0; t < 64; t++) {
            int e = t * 256 + tid;
            int m = e >> 6, d = e & 63;
            float val = cbase[e];
            __nv_bfloat16 h = __float2bfloat16(val);
            __nv_bfloat16 l = __float2bfloat16(val - __bfloat162float(h));
            int mc = m & 63;
            uint32_t off = (uint32_t)((m >> 6) * 8192 + d * 128 + (((mc >> 3) ^ (d & 7)) << 4) + (mc & 7) * 2);
            *(ushort*)((char*)gsm + 49152 + off) = __bfloat16_as_ushort(h);
            *(ushort*)((char*)gsm + 81920 + off) = __bfloat16_as_ushort(l);
        }
    }

    const __nv_bfloat16* pA[3] = {QFh, QFh, QFl};

    float c[4][2][4];
#pragma unroll
    for (int i = 0; i < 4; i++)
#pragma unroll
        for (int j = 0; j < 2; j++)
#pragma unroll
            for (int q = 0; q < 4; q++) c[i][j][q] = 0.f;

    auto prefetchA = [&](int s, int stage) {
        if (s < YV_NCHUNK) {
            const int ph = s >> 2;
            const int kk = (s & 3) << 6;
            const __nv_bfloat16* gA = pA[ph] + (size_t)bh * NSEQ * MM;
            const uint32_t aB = smem_base + stage * YV_ASTG;
#pragma unroll
            for (int it = 0; it < 4; it++) {
                int idx = it * 256 + tid;
                int row = idx >> 3;
                int pb  = idx & 7;
                uint32_t doff = row * 128 + ((pb ^ (row & 7)) << 4);
                const void* srcA = gA + (size_t)(bm + row) * MM + kk + pb * 8;
                asm volatile("cp.async.cg.shared.global [%0], [%1], 16;" :: "r"(aB + doff), "l"(srcA));
            }
        }
        asm volatile("cp.async.commit_group;" ::: "memory");
    };

    prefetchA(0, 0);
    prefetchA(1, 1);
    __syncthreads();

    for (int s = 0; s < YV_NCHUNK; s++) {
        const int stage = s % 3;
        asm volatile("cp.async.wait_group 1;" ::: "memory");
        __syncthreads();
        prefetchA(s + 2, (s + 2) % 3);

        const uint32_t cA = smem_base + stage * YV_ASTG;
        const int ph = s >> 2;
        const uint32_t cBbase = (ph == 1) ? sBL : sBH;
        const uint32_t cB = cBbase + (uint32_t)((s & 3) * 8192);

#pragma unroll
        for (int ks = 0; ks < 4; ks++) {
            uint32_t bf[2][2];
            {
                int row = wn * 16 + ((lane >> 4) << 3) + (lane & 7);
                int pb  = ks * 2 + ((lane >> 3) & 1);
                uint32_t ad = cB + row * 128 + ((pb ^ (row & 7)) << 4);
                uint32_t t4[4];
                ldmx4(t4, ad);
                bf[0][0] = t4[0]; bf[0][1] = t4[1];
                bf[1][0] = t4[2]; bf[1][1] = t4[3];
            }
#pragma unroll
            for (int i = 0; i < 4; i++) {
                int r0 = wm * 64 + i * 16;
                int row = r0 + (((lane >> 3) & 1) << 3) + (lane & 7);
                int pb  = ks * 2 + ((lane >> 4) & 1);
                uint32_t ad = cA + row * 128 + ((pb ^ (row & 7)) << 4);
                uint32_t af[4];
                ldmx4(af, ad);
#pragma unroll
                for (int j = 0; j < 2; j++)
                    mma16816(c[i][j], af, bf[j]);
            }
        }
        __syncthreads();
    }

#pragma unroll
    for (int i = 0; i < 4; i++) {
        int rl = wm * 64 + i * 16 + (lane >> 2);
        int nA = bm + rl;
        int nB = nA + 8;
        float dA = g_dinv[(size_t)bh * NSEQ + nA];
        float dB = g_dinv[(size_t)bh * NSEQ + nB];
#pragma unroll
        for (int j = 0; j < 2; j++) {
            int col = wn * 16 + j * 8 + (lane & 3) * 2;
            float vA0 = c[i][j][0] * dA, vA1 = c[i][j][1] * dA;
            float vB0 = c[i][j][2] * dB, vB1 = c[i][j][3] * dB;
            __nv_bfloat16 hA0 = __float2bfloat16(vA0), hA1 = __float2bfloat16(vA1);
            __nv_bfloat16 hB0 = __float2bfloat16(vB0), hB1 = __float2bfloat16(vB1);
            uint32_t hvA = ((uint32_t)__bfloat16_as_ushort(hA1) << 16) | __bfloat16_as_ushort(hA0);
            uint32_t lvA = ((uint32_t)__bfloat16_as_ushort(__float2bfloat16(vA1 - __bfloat162float(hA1))) << 16)
                         | __bfloat16_as_ushort(__float2bfloat16(vA0 - __bfloat162float(hA0)));
            uint32_t hvB = ((uint32_t)__bfloat16_as_ushort(hB1) << 16) | __bfloat16_as_ushort(hB0);
            uint32_t lvB = ((uint32_t)__bfloat16_as_ushort(__float2bfloat16(vB1 - __bfloat162float(hB1))) << 16)
                         | __bfloat16_as_ushort(__float2bfloat16(vB0 - __bfloat162float(hB0)));
            size_t idxA = ((size_t)(b_ * NSEQ + nA)) * EE + h_ * DD + col;
            size_t idxB = ((size_t)(b_ * NSEQ + nB)) * EE + h_ * DD + col;
            *(uint32_t*)(OutH + idxA) = hvA;
            *(uint32_t*)(OutL + idxA) = lvA;
            *(uint32_t*)(OutH + idxB) = hvB;
            *(uint32_t*)(OutL + idxB) = lvB;
        }
    }
}

// ---------------- launch ----------------
extern "C" void kernel_launch(void* const* d_in, const int* in_sizes, int n_in,
                              void* d_out, int out_size) {
    const float* x    = (const float*)d_in[0];
    const float* Wq   = (const float*)d_in[1];
    const float* bq   = (const float*)d_in[2];
    const float* Wk   = (const float*)d_in[3];
    const float* bk   = (const float*)d_in[4];
    const float* Wv   = (const float*)d_in[5];
    const float* bv   = (const float*)d_in[6];
    const float* Wo   = (const float*)d_in[7];
    const float* bo   = (const float*)d_in[8];
    const float* proj = (const float*)d_in[9];
    float* out = (float*)d_out;

    float *pq, *pk, *pv, *pdinv;
    __nv_bfloat16 *pah, *pal, *pwh, *pwl, *pqfh, *pqfl;
    cudaGetSymbolAddress((void**)&pq,   g_q);
    cudaGetSymbolAddress((void**)&pk,   g_k);
    cudaGetSymbolAddress((void**)&pv,   g_v);
    cudaGetSymbolAddress((void**)&pdinv, g_dinv);
    cudaGetSymbolAddress((void**)&pah,  g_ah);
    cudaGetSymbolAddress((void**)&pal,  g_al);
    cudaGetSymbolAddress((void**)&pwh,  g_wh);
    cudaGetSymbolAddress((void**)&pwl,  g_wl);
    cudaGetSymbolAddress((void**)&pqfh, g_qfh);
    cudaGetSymbolAddress((void**)&pqfl, g_qfl);

    __nv_bfloat16* pwh1 = pwh + (size_t)EE * EE;
    __nv_bfloat16* pwl1 = pwl + (size_t)EE * EE;

    const int GEMM_SMEM = 3 * STG_BYTES;                                                 // 98304
    const int CTXF_SMEM = (DD * MM + 32 * MM + 32 * DD + 32 * DD) * (int)sizeof(float);  // 114688
    const int QF_SMEM   = (DD * MM + 32 * DD + MM) * (int)sizeof(float);                 // 74752
    const int YV_SMEM   = 3 * YV_ASTG + 2 * 32768;                                       // 114688
    cudaFuncSetAttribute(gemm_mma<0>, cudaFuncAttributeMaxDynamicSharedMemorySize, GEMM_SMEM);
    cudaFuncSetAttribute(gemm_mma<1>, cudaFuncAttributeMaxDynamicSharedMemorySize, GEMM_SMEM);
    cudaFuncSetAttribute(ctx_fused,  cudaFuncAttributeMaxDynamicSharedMemorySize, CTXF_SMEM);
    cudaFuncSetAttribute(qf_kernel,  cudaFuncAttributeMaxDynamicSharedMemorySize, QF_SMEM);
    cudaFuncSetAttribute(yv_gemm,    cudaFuncAttributeMaxDynamicSharedMemorySize, YV_SMEM);

    dim3 gg(EE / 128, TT / 128);

    // Launch order arranged so ctx_fused is the 6th launch (ncu -s 5 -c 1 profiles it).
    init_kernel<<<1, 32>>>();                                                 // 1
    split_kernel<<<2048, 256>>>(x, pah, pal, TT * EE / 4);                    // 2
    split2_kernel<<<1024, 256>>>(Wk, pwh, pwl, Wv, pwh1, pwl1, EE * EE / 4);  // 3
    gemm_mma<1><<<gg, 256, GEMM_SMEM>>>(pah, pal, pwh,  pwl,  bk, pk);        // 4
    gemm_mma<1><<<gg, 256, GEMM_SMEM>>>(pah, pal, pwh1, pwl1, bv, pv);        // 5
    ctx_fused<<<dim3(BHn, NSEG), 256, CTXF_SMEM>>>(pk, pv, proj);             // 6  <- profiled
    split_kernel<<<512, 256>>>(Wq, pwh, pwl, EE * EE / 4);                    // 7
    gemm_mma<1><<<gg, 256, GEMM_SMEM>>>(pah, pal, pwh, pwl, bq, pq);          // 8
    ctx_reduce_kernel<<<(BHn * MM * DD + 255) / 256, 256>>>();                // 9
    qf_kernel<<<dim3(BHn, 16), 256, QF_SMEM>>>(pq, proj, pqfh, pqfl, pdinv);  // 10
    yv_gemm<<<dim3(NSEQ / 128, BHn), 256, YV_SMEM>>>(pqfh, pqfl, pah, pal);   // 11
    split_kernel<<<512, 256>>>(Wo, pwh, pwl, EE * EE / 4);                    // 12
    gemm_mma<0><<<gg, 256, GEMM_SMEM>>>(pah, pal, pwh, pwl, bo, out);         // 13
}

// round 11
// speedup vs baseline: 1.1068x; 1.1068x over previous
#include <cuda_runtime.h>
#include <cuda_bf16.h>
#include <math.h>
#include <stdint.h>

// Problem constants
#define BB   4
#define NSEQ 4096
#define EE   1024
#define HH   16
#define DD   64
#define MM   256
#define TT   (BB*NSEQ)     // 16384
#define BHn  (BB*HH)       // 64
#define NSEG 8

#define RATIO 0.0625f
#define EPSK  1e-4f
#define SCQ   0.3535533905932738f   // 64^-0.25

// ---------------- device scratch ----------------
__device__ float g_q[(size_t)BHn*NSEQ*DD];
__device__ float g_k[(size_t)BHn*NSEQ*DD];
__device__ float g_v[(size_t)BHn*NSEQ*DD];
__device__ float g_ksum[BHn*MM];
__device__ float g_ksump[(size_t)NSEG*BHn*MM];
__device__ float g_svp[(size_t)NSEG*BHn*DD];
__device__ float g_ctxp[(size_t)NSEG*BHn*MM*DD];
__device__ float g_ctx[BHn*MM*DD];
__device__ float g_dinv[(size_t)BHn*NSEQ];
__device__ float g_kstab;
__device__ __nv_bfloat16 g_ah[(size_t)TT*EE];
__device__ __nv_bfloat16 g_al[(size_t)TT*EE];
__device__ __nv_bfloat16 g_wh[(size_t)EE*EE];
__device__ __nv_bfloat16 g_wl[(size_t)EE*EE];
__device__ __nv_bfloat16 g_qfh[(size_t)BHn*NSEQ*MM];
__device__ __nv_bfloat16 g_qfl[(size_t)BHn*NSEQ*MM];

// ---------------- helpers ----------------
__device__ __forceinline__ void atomicMaxFloat(float* addr, float v) {
    if (v >= 0.f) atomicMax((int*)addr, __float_as_int(v));
    else          atomicMin((unsigned int*)addr, __float_as_uint(v));
}

__global__ void init_kernel() {
    if (blockIdx.x == 0 && threadIdx.x == 0) g_kstab = -INFINITY;
}

__device__ __forceinline__ uint32_t smem_u32(const void* p) {
    uint32_t a;
    asm("{ .reg .u64 t; cvta.to.shared.u64 t, %1; cvt.u32.u64 %0, t; }" : "=r"(a) : "l"(p));
    return a;
}

__device__ __forceinline__ void mma16816(float* c, const uint32_t* a, const uint32_t* b) {
    asm volatile(
        "mma.sync.aligned.m16n8k16.row.col.f32.bf16.bf16.f32 "
        "{%0,%1,%2,%3},{%4,%5,%6,%7},{%8,%9},{%0,%1,%2,%3};"
        : "+f"(c[0]), "+f"(c[1]), "+f"(c[2]), "+f"(c[3])
        : "r"(a[0]), "r"(a[1]), "r"(a[2]), "r"(a[3]), "r"(b[0]), "r"(b[1]));
}

__device__ __forceinline__ void ldmx4(uint32_t* r, uint32_t addr) {
    asm volatile("ldmatrix.sync.aligned.m8n8.x4.shared.b16 {%0,%1,%2,%3}, [%4];"
        : "=r"(r[0]), "=r"(r[1]), "=r"(r[2]), "=r"(r[3]) : "r"(addr));
}

// packed fp32x2
__device__ __forceinline__ void fma2(unsigned long long& d, unsigned long long a, unsigned long long b) {
    asm("fma.rn.f32x2 %0, %1, %2, %0;" : "+l"(d) : "l"(a), "l"(b));
}
__device__ __forceinline__ unsigned long long pack2(float x) {
    unsigned long long r;
    asm("mov.b64 %0, {%1, %1};" : "=l"(r) : "f"(x));
    return r;
}
__device__ __forceinline__ float2 unpack2(unsigned long long v) {
    float2 f;
    asm("mov.b64 {%0, %1}, %2;" : "=f"(f.x), "=f"(f.y) : "l"(v));
    return f;
}
__device__ __forceinline__ float f4c(const float4& v, int j) {
    return j == 0 ? v.x : j == 1 ? v.y : j == 2 ? v.z : v.w;
}
__device__ __forceinline__ ushort bfu(float x) {
    return __bfloat16_as_ushort(__float2bfloat16(x));
}

// ---------------- fp32 -> bf16 hi/lo split ----------------
__global__ __launch_bounds__(256) void split_kernel(
    const float* __restrict__ src, __nv_bfloat16* __restrict__ hi,
    __nv_bfloat16* __restrict__ lo, int n4)
{
    const float4* s4 = (const float4*)src;
    uint2* h2 = (uint2*)hi;
    uint2* l2 = (uint2*)lo;
    for (int i = blockIdx.x * 256 + threadIdx.x; i < n4; i += gridDim.x * 256) {
        float4 v = s4[i];
        __nv_bfloat16 h0 = __float2bfloat16(v.x);
        __nv_bfloat16 h1 = __float2bfloat16(v.y);
        __nv_bfloat16 h2b = __float2bfloat16(v.z);
        __nv_bfloat16 h3 = __float2bfloat16(v.w);
        __nv_bfloat16 l0 = __float2bfloat16(v.x - __bfloat162float(h0));
        __nv_bfloat16 l1 = __float2bfloat16(v.y - __bfloat162float(h1));
        __nv_bfloat16 l2b = __float2bfloat16(v.z - __bfloat162float(h2b));
        __nv_bfloat16 l3 = __float2bfloat16(v.w - __bfloat162float(h3));
        uint2 hv, lv;
        hv.x = ((uint32_t)__bfloat16_as_ushort(h1) << 16) | __bfloat16_as_ushort(h0);
        hv.y = ((uint32_t)__bfloat16_as_ushort(h3) << 16) | __bfloat16_as_ushort(h2b);
        lv.x = ((uint32_t)__bfloat16_as_ushort(l1) << 16) | __bfloat16_as_ushort(l0);
        lv.y = ((uint32_t)__bfloat16_as_ushort(l3) << 16) | __bfloat16_as_ushort(l2b);
        h2[i] = hv;
        l2[i] = lv;
    }
}

// ---------------- bf16-split mma.sync GEMM: K-chunk 64, 3-stage, ldmatrix ----------------
#define NCHUNK 48          // 3 passes * 1024/64
#define STG_BYTES 32768    // A(16K) + B(16K) per stage

template<int OUT_MODE>
__global__ __launch_bounds__(256) void gemm_mma(
    const __nv_bfloat16* __restrict__ Ah, const __nv_bfloat16* __restrict__ Al,
    const __nv_bfloat16* __restrict__ Wh, const __nv_bfloat16* __restrict__ Wl,
    const float* __restrict__ bias, float* __restrict__ C)
{
    extern __shared__ __align__(128) char gsm[];

    const int tid  = threadIdx.x;
    const int lane = tid & 31;
    const int wid  = tid >> 5;
    const int wm   = wid & 1;
    const int wn   = wid >> 1;
    const int bm   = blockIdx.y * 128;
    const int bn   = blockIdx.x * 128;

    const __nv_bfloat16* pA[3] = {Ah, Ah, Al};
    const __nv_bfloat16* pB[3] = {Wh, Wl, Wh};

    float c[4][4][4];
#pragma unroll
    for (int i = 0; i < 4; i++)
#pragma unroll
        for (int j = 0; j < 4; j++)
#pragma unroll
            for (int q = 0; q < 4; q++) c[i][j][q] = 0.f;

    const uint32_t smem_base = smem_u32(gsm);

    auto prefetch = [&](int s, int stage) {
        if (s < NCHUNK) {
            const int ph = s >> 4;
            const int kk = (s & 15) << 6;
            const __nv_bfloat16* gA = pA[ph];
            const __nv_bfloat16* gB = pB[ph];
            const uint32_t aB = smem_base + stage * STG_BYTES;
            const uint32_t bB = aB + 16384;
#pragma unroll
            for (int it = 0; it < 4; it++) {
                int idx = it * 256 + tid;
                int row = idx >> 3;
                int pb  = idx & 7;
                uint32_t doff = row * 128 + ((pb ^ (row & 7)) << 4);
                const void* srcA = gA + (size_t)(bm + row) * EE + kk + pb * 8;
                const void* srcB = gB + (size_t)(bn + row) * EE + kk + pb * 8;
                asm volatile("cp.async.cg.shared.global [%0], [%1], 16;" :: "r"(aB + doff), "l"(srcA));
                asm volatile("cp.async.cg.shared.global [%0], [%1], 16;" :: "r"(bB + doff), "l"(srcB));
            }
        }
        asm volatile("cp.async.commit_group;" ::: "memory");
    };

    prefetch(0, 0);
    prefetch(1, 1);

    for (int s = 0; s < NCHUNK; s++) {
        const int stage = s % 3;
        asm volatile("cp.async.wait_group 1;" ::: "memory");
        __syncthreads();
        // prefetch(s+2) targets buffer (s-1)%3: all warps past the sync have
        // finished compute(s-1) in program order -> safe without a 2nd barrier.
        prefetch(s + 2, (s + 2) % 3);

        const uint32_t cA = smem_base + stage * STG_BYTES;
        const uint32_t cB = cA + 16384;
#pragma unroll
        for (int ks = 0; ks < 4; ks++) {
            uint32_t bf[4][2];
#pragma unroll
            for (int jb = 0; jb < 2; jb++) {
                int row = wn * 32 + jb * 16 + ((lane >> 4) << 3) + (lane & 7);
                int pb  = ks * 2 + ((lane >> 3) & 1);
                uint32_t ad = cB + row * 128 + ((pb ^ (row & 7)) << 4);
                uint32_t t4[4];
                ldmx4(t4, ad);
                bf[jb * 2][0] = t4[0]; bf[jb * 2][1] = t4[1];
                bf[jb * 2 + 1][0] = t4[2]; bf[jb * 2 + 1][1] = t4[3];
            }
#pragma unroll
            for (int i = 0; i < 4; i++) {
                int r0 = wm * 64 + i * 16;
                int row = r0 + (((lane >> 3) & 1) << 3) + (lane & 7);
                int pb  = ks * 2 + ((lane >> 4) & 1);
                uint32_t ad = cA + row * 128 + ((pb ^ (row & 7)) << 4);
                uint32_t af[4];
                ldmx4(af, ad);
#pragma unroll
                for (int j = 0; j < 4; j++)
                    mma16816(c[i][j], af, bf[j]);
            }
        }
    }

#pragma unroll
    for (int i = 0; i < 4; i++) {
        int r = bm + wm * 64 + i * 16 + (lane >> 2);
#pragma unroll
        for (int j = 0; j < 4; j++) {
            int col = bn + wn * 32 + j * 8 + (lane & 3) * 2;
            float b0 = bias[col], b1 = bias[col + 1];
            float2 v0 = make_float2(c[i][j][0] + b0, c[i][j][1] + b1);
            float2 v1 = make_float2(c[i][j][2] + b0, c[i][j][3] + b1);
            if (OUT_MODE == 0) {
                *(float2*)(C + (size_t)r * EE + col)       = v0;
                *(float2*)(C + (size_t)(r + 8) * EE + col) = v1;
            } else {
                int h_ = col >> 6, d0 = col & 63;
                int b_ = r >> 12, n_ = r & 4095;
                size_t base = ((size_t)(b_ * HH + h_) * NSEQ);
                *(float2*)(C + (base + n_)     * DD + d0) = v0;
                *(float2*)(C + (base + n_ + 8) * DD + d0) = v1;
            }
        }
    }
}

// ---------------- ctx_fused v2: dd on tensor cores ----------------
// grid (BHn, NSEG=8), block 256. Each block: 512 n-rows as 32 tiles of 16.
// dd[16 x 256] = Xk_bf16split @ projT_bf16split (3-pass mma), exp in fragments,
// U/ksum/sv phases unchanged (fma2). proj resident bf16 hi/lo (64 KB).
#define CF_STRIDE 260       // sKF row stride in floats (bank-skewed, 16B-aligned)
// smem layout (bytes): sPTh@0 (32768), sPTl@32768 (32768), sXh@65536 (2048),
// sXl@67584 (2048), sKF@69632 (16640), sV@86272 (4096), sDiag@90368 (64) = 90432
#define CTXF_SMEM_BYTES 90432

__global__ __launch_bounds__(256, 2) void ctx_fused(
    const float* __restrict__ K, const float* __restrict__ V,
    const float* __restrict__ proj)
{
    extern __shared__ __align__(128) char csm[];
    const uint32_t smem_base = smem_u32(csm);
    const uint32_t sPTh = smem_base;
    const uint32_t sPTl = smem_base + 32768;
    const uint32_t sXh  = smem_base + 65536;
    const uint32_t sXl  = smem_base + 67584;
    float* sKF   = (float*)(csm + 69632);
    float* sV    = (float*)(csm + 86272);
    float* sDiag = (float*)(csm + 90368);
    __shared__ float swm[8];

    const int tid = threadIdx.x;
    const int bh  = blockIdx.x;
    const int seg = blockIdx.y;
    const int lane = tid & 31;
    const int w    = tid >> 5;
    const int tx   = tid & 15;     // d group (4 d) for U phase
    const int ty   = tid >> 4;     // m group (16 m) for U phase

    // convert proj -> resident bf16 hi/lo, K-major [m=256 rows][64 d], swizzled
    {
        const float4* pr = (const float4*)(proj + tid * DD);
#pragma unroll
        for (int t = 0; t < 16; t++) {
            float4 v = pr[t];
            ushort h0 = bfu(v.x), h1 = bfu(v.y), h2 = bfu(v.z), h3 = bfu(v.w);
            ushort l0 = bfu(v.x - __bfloat162float(__ushort_as_bfloat16(h0)));
            ushort l1 = bfu(v.y - __bfloat162float(__ushort_as_bfloat16(h1)));
            ushort l2 = bfu(v.z - __bfloat162float(__ushort_as_bfloat16(h2)));
            ushort l3 = bfu(v.w - __bfloat162float(__ushort_as_bfloat16(h3)));
            uint2 hv, lv;
            hv.x = ((uint32_t)h1 << 16) | h0; hv.y = ((uint32_t)h3 << 16) | h2;
            lv.x = ((uint32_t)l1 << 16) | l0; lv.y = ((uint32_t)l3 << 16) | l2;
            uint32_t off = (uint32_t)(tid * 128 + (((t >> 1) ^ (tid & 7)) << 4) + (t & 1) * 8);
            *(uint2*)(csm + off)         = hv;
            *(uint2*)(csm + 32768 + off) = lv;
        }
    }

    unsigned long long cacc[16][2];   // U acc: 16 m x 4 d per thread
#pragma unroll
    for (int i = 0; i < 16; i++) { cacc[i][0] = 0ull; cacc[i][1] = 0ull; }
    float kacc = 0.f;
    float svacc = 0.f;
    float ddmax = -1e30f;

    for (int it = 0; it < 32; it++) {
        const int n0 = seg * 512 + it * 16;
        __syncthreads();   // prior U/ksum reads done (and proj ready on it=0)

        // load 16 rows of K (scaled) and V; diag; bf16 hi/lo K tile
        {
            int row = tid >> 4;        // 0..15
            int t   = tid & 15;        // float4 within row
            const float* kp = K + ((size_t)bh * NSEQ + n0 + row) * DD + t * 4;
            const float* vp = V + ((size_t)bh * NSEQ + n0 + row) * DD + t * 4;
            float4 kv = *(const float4*)kp;
            float4 vv = *(const float4*)vp;
            kv.x *= SCQ; kv.y *= SCQ; kv.z *= SCQ; kv.w *= SCQ;
            float ssq = kv.x * kv.x + kv.y * kv.y + kv.z * kv.z + kv.w * kv.w;
#pragma unroll
            for (int o = 8; o > 0; o >>= 1) ssq += __shfl_xor_sync(0xffffffffu, ssq, o);
            if (t == 0) sDiag[row] = 0.5f * ssq;

            ushort h0 = bfu(kv.x), h1 = bfu(kv.y), h2 = bfu(kv.z), h3 = bfu(kv.w);
            ushort l0 = bfu(kv.x - __bfloat162float(__ushort_as_bfloat16(h0)));
            ushort l1 = bfu(kv.y - __bfloat162float(__ushort_as_bfloat16(h1)));
            ushort l2 = bfu(kv.z - __bfloat162float(__ushort_as_bfloat16(h2)));
            ushort l3 = bfu(kv.w - __bfloat162float(__ushort_as_bfloat16(h3)));
            uint2 hv, lv;
            hv.x = ((uint32_t)h1 << 16) | h0; hv.y = ((uint32_t)h3 << 16) | h2;
            lv.x = ((uint32_t)l1 << 16) | l0; lv.y = ((uint32_t)l3 << 16) | l2;
            uint32_t off = (uint32_t)(row * 128 + (((t >> 1) ^ (row & 7)) << 4) + (t & 1) * 8);
            *(uint2*)(csm + 65536 + off) = hv;
            *(uint2*)(csm + 67584 + off) = lv;
            *(float4*)(sV + row * 64 + t * 4) = vv;
        }
        __syncthreads();

        // dd-mma: 3 passes, M=16 (n), N=256 (m, warp slice 32), K=64
        {
            float c[4][4];
#pragma unroll
            for (int j = 0; j < 4; j++)
#pragma unroll
                for (int q = 0; q < 4; q++) c[j][q] = 0.f;

            const uint32_t pASrc[3] = {sXh, sXh, sXl};
            const uint32_t pBSrc[3] = {sPTh, sPTl, sPTh};
#pragma unroll
            for (int ph = 0; ph < 3; ph++) {
                const uint32_t cA = pASrc[ph];
                const uint32_t cB = pBSrc[ph];
#pragma unroll
                for (int ks = 0; ks < 4; ks++) {
                    int rowA = (((lane >> 3) & 1) << 3) + (lane & 7);
                    int pbA  = ks * 2 + ((lane >> 4) & 1);
                    uint32_t adA = cA + rowA * 128 + ((pbA ^ (rowA & 7)) << 4);
                    uint32_t af[4];
                    ldmx4(af, adA);
                    uint32_t bf[4][2];
#pragma unroll
                    for (int jb = 0; jb < 2; jb++) {
                        int rowB = w * 32 + jb * 16 + ((lane >> 4) << 3) + (lane & 7);
                        int pbB  = ks * 2 + ((lane >> 3) & 1);
                        uint32_t adB = cB + rowB * 128 + ((pbB ^ (rowB & 7)) << 4);
                        uint32_t t4[4];
                        ldmx4(t4, adB);
                        bf[jb * 2][0] = t4[0]; bf[jb * 2][1] = t4[1];
                        bf[jb * 2 + 1][0] = t4[2]; bf[jb * 2 + 1][1] = t4[3];
                    }
#pragma unroll
                    for (int j = 0; j < 4; j++)
                        mma16816(c[j], af, bf[j]);
                }
            }

            // exp in fragments -> sKF
            const int r0 = lane >> 2;
            const int mb = w * 32 + (lane & 3) * 2;
            const float dg0 = sDiag[r0];
            const float dg1 = sDiag[r0 + 8];
#pragma unroll
            for (int j = 0; j < 4; j++) {
                int m = mb + j * 8;
                float v0 = c[j][0], v1 = c[j][1], v2 = c[j][2], v3 = c[j][3];
                ddmax = fmaxf(ddmax, fmaxf(fmaxf(v0, v1), fmaxf(v2, v3)));
                *(float2*)&sKF[r0 * CF_STRIDE + m] =
                    make_float2(__expf(v0 - dg0), __expf(v1 - dg0));
                *(float2*)&sKF[(r0 + 8) * CF_STRIDE + m] =
                    make_float2(__expf(v2 - dg1), __expf(v3 - dg1));
            }
        }
        __syncthreads();

        // ksum partial (column tid)
#pragma unroll
        for (int r = 0; r < 16; r++) kacc += sKF[r * CF_STRIDE + tid];

        // Sv partial
        if (tid < 64) {
#pragma unroll
            for (int r = 0; r < 16; r++) svacc += sV[r * 64 + tid];
        }

        // U partial: thread (ty, tx): 16 m x 4 d
        const ulonglong2* sV2 = (const ulonglong2*)sV;
#pragma unroll 4
        for (int r = 0; r < 16; r++) {
            ulonglong2 bv = sV2[r * 16 + tx];
            const float4* kf4 = (const float4*)&sKF[r * CF_STRIDE + ty * 16];
            float4 kq[4];
            kq[0] = kf4[0]; kq[1] = kf4[1]; kq[2] = kf4[2]; kq[3] = kf4[3];
#pragma unroll
            for (int q = 0; q < 4; q++) {
#pragma unroll
                for (int j = 0; j < 4; j++) {
                    unsigned long long av = pack2(f4c(kq[q], j));
                    fma2(cacc[q * 4 + j][0], av, bv.x);
                    fma2(cacc[q * 4 + j][1], av, bv.y);
                }
            }
        }
    }

    g_ksump[((size_t)seg * BHn + bh) * MM + tid] = kacc;
    if (tid < 64) g_svp[((size_t)seg * BHn + bh) * DD + tid] = svacc;

    float* cp = g_ctxp + ((size_t)seg * BHn + bh) * MM * DD;
#pragma unroll
    for (int i = 0; i < 16; i++) {
        float2 f0 = unpack2(cacc[i][0]);
        float2 f1 = unpack2(cacc[i][1]);
        *(float4*)(cp + (ty * 16 + i) * DD + tx * 4) = make_float4(f0.x, f0.y, f1.x, f1.y);
    }

#pragma unroll
    for (int o = 16; o > 0; o >>= 1)
        ddmax = fmaxf(ddmax, __shfl_xor_sync(0xffffffffu, ddmax, o));
    if (lane == 0) swm[w] = ddmax;
    __syncthreads();
    if (tid == 0) {
        float m = swm[0];
#pragma unroll
        for (int i = 1; i < 8; i++) m = fmaxf(m, swm[i]);
        atomicMaxFloat(&g_kstab, m);
    }
}

// ---------------- assemble ctx + ksum from unstabilized partials ----------------
__global__ __launch_bounds__(256) void ctx_reduce_kernel() {
    const float escale = __expf(-g_kstab);
    int i = blockIdx.x * 256 + threadIdx.x;
    if (i < BHn * MM * DD) {
        int bh = i >> 14;
        int d  = i & 63;
        float U = 0.f, Sv = 0.f;
#pragma unroll
        for (int seg = 0; seg < NSEG; seg++) {
            U  += g_ctxp[(size_t)seg * BHn * MM * DD + i];
            Sv += g_svp[((size_t)seg * BHn + bh) * DD + d];
        }
        g_ctx[i] = RATIO * (escale * U + EPSK * Sv);
    }
    if (i < BHn * MM) {
        float T = 0.f;
#pragma unroll
        for (int seg = 0; seg < NSEG; seg++)
            T += g_ksump[(size_t)seg * BHn * MM + i];
        g_ksum[i] = RATIO * (escale * T + EPSK * (float)NSEQ);
    }
}

// ---------------- query features only: qf (bf16 hi/lo) + dinv (R9, unchanged) ----------------
__global__ __launch_bounds__(256, 3) void qf_kernel(
    const float* __restrict__ Q, const float* __restrict__ proj,
    __nv_bfloat16* __restrict__ QFh, __nv_bfloat16* __restrict__ QFl,
    float* __restrict__ Dinv)
{
    extern __shared__ float sm[];
    float* sPT = sm;              // [64][256]  64 KB
    float* sX  = sPT + DD * MM;   // [32][64]    8 KB
    float* sKs = sX + 32 * DD;    // [256]       1 KB

    const int tid = threadIdx.x;
    const int bh  = blockIdx.x;
    const int nblk = blockIdx.y * 256;
    const int lane = tid & 31;
    const int w    = tid >> 5;
    const int m0   = lane * 8;

    {
        const float4* pr = (const float4*)(proj + tid * DD);
#pragma unroll
        for (int t = 0; t < 16; t++) {
            float4 v = pr[t];
            int d = t * 4;
            sPT[(d + 0) * MM + tid] = v.x;
            sPT[(d + 1) * MM + tid] = v.y;
            sPT[(d + 2) * MM + tid] = v.z;
            sPT[(d + 3) * MM + tid] = v.w;
        }
        sKs[tid] = g_ksum[bh * MM + tid];
    }

    for (int it = 0; it < 8; it++) {
        const int n0 = nblk + it * 32;
        __syncthreads();
        {
            const float4* xr = (const float4*)(Q + ((size_t)bh * NSEQ + n0) * DD);
            float4* sx4 = (float4*)sX;
#pragma unroll
            for (int i = 0; i < 2; i++) {
                int f = tid * 2 + i;
                float4 v = xr[f];
                sx4[f] = make_float4(v.x * SCQ, v.y * SCQ, v.z * SCQ, v.w * SCQ);
            }
        }
        __syncthreads();

        unsigned long long a2[4][4];
#pragma unroll
        for (int r = 0; r < 4; r++)
#pragma unroll
            for (int j = 0; j < 4; j++) a2[r][j] = 0ull;

#pragma unroll 2
        for (int d0 = 0; d0 < DD; d0 += 4) {
            float4 xv[4];
#pragma unroll
            for (int r = 0; r < 4; r++)
                xv[r] = *(const float4*)&sX[(w * 4 + r) * DD + d0];
#pragma unroll
            for (int dd = 0; dd < 4; dd++) {
                const ulonglong2* bp = (const ulonglong2*)&sPT[(d0 + dd) * MM + m0];
                ulonglong2 b01 = bp[0], b23 = bp[1];
#pragma unroll
                for (int r = 0; r < 4; r++) {
                    unsigned long long av = pack2(f4c(xv[r], dd));
                    fma2(a2[r][0], av, b01.x); fma2(a2[r][1], av, b01.y);
                    fma2(a2[r][2], av, b23.x); fma2(a2[r][3], av, b23.y);
                }
            }
        }

#pragma unroll
        for (int r = 0; r < 4; r++) {
            float v8[8];
#pragma unroll
            for (int j = 0; j < 4; j++) {
                float2 f = unpack2(a2[r][j]);
                v8[j * 2] = f.x; v8[j * 2 + 1] = f.y;
            }
            float mx = v8[0];
#pragma unroll
            for (int j = 1; j < 8; j++) mx = fmaxf(mx, v8[j]);
#pragma unroll
            for (int o = 16; o > 0; o >>= 1)
                mx = fmaxf(mx, __shfl_xor_sync(0xffffffffu, mx, o));

            const float* xr = &sX[(w * 4 + r) * DD];
            float x0 = xr[lane * 2], x1 = xr[lane * 2 + 1];
            float p = x0 * x0 + x1 * x1;
#pragma unroll
            for (int o = 16; o > 0; o >>= 1) p += __shfl_xor_sync(0xffffffffu, p, o);
            float sub = 0.5f * p + mx;

            float o8[8];
            float dp = 0.f;
            ushort hb[8], lb[8];
#pragma unroll
            for (int j = 0; j < 8; j++) {
                o8[j] = RATIO * (__expf(v8[j] - sub) + EPSK);
                dp += o8[j] * sKs[m0 + j];
                __nv_bfloat16 h = __float2bfloat16(o8[j]);
                hb[j] = __bfloat16_as_ushort(h);
                lb[j] = __bfloat16_as_ushort(__float2bfloat16(o8[j] - __bfloat162float(h)));
            }
#pragma unroll
            for (int o = 16; o > 0; o >>= 1) dp += __shfl_xor_sync(0xffffffffu, dp, o);

            const int n = n0 + w * 4 + r;
            size_t base = ((size_t)bh * NSEQ + n) * MM + m0;
            uint4 hv, lv;
            hv.x = ((uint32_t)hb[1] << 16) | hb[0]; hv.y = ((uint32_t)hb[3] << 16) | hb[2];
            hv.z = ((uint32_t)hb[5] << 16) | hb[4]; hv.w = ((uint32_t)hb[7] << 16) | hb[6];
            lv.x = ((uint32_t)lb[1] << 16) | lb[0]; lv.y = ((uint32_t)lb[3] << 16) | lb[2];
            lv.z = ((uint32_t)lb[5] << 16) | lb[4]; lv.w = ((uint32_t)lb[7] << 16) | lb[6];
            *(uint4*)(QFh + base) = hv;
            *(uint4*)(QFl + base) = lv;
            if (lane == 0) Dinv[(size_t)bh * NSEQ + n] = 1.f / dp;
        }
    }
}

// ---------------- yv_gemm: per-head y = qf @ ctx^T, * dinv, bf16-split output (R9, unchanged) ----------------
#define YV_NCHUNK 12       // 3 passes * 256/64
#define YV_ASTG  16384     // A stage: 128 rows x 128B

__global__ __launch_bounds__(256, 2) void yv_gemm(
    const __nv_bfloat16* __restrict__ QFh, const __nv_bfloat16* __restrict__ QFl,
    __nv_bfloat16* __restrict__ OutH, __nv_bfloat16* __restrict__ OutL)
{
    extern __shared__ __align__(128) char gsm[];
    const uint32_t smem_base = smem_u32(gsm);
    const uint32_t sBH = smem_base + 49152;
    const uint32_t sBL = smem_base + 81920;

    const int tid  = threadIdx.x;
    const int lane = tid & 31;
    const int wid  = tid >> 5;
    const int wm   = wid & 1;
    const int wn   = wid >> 1;
    const int bh   = blockIdx.y;
    const int bm   = blockIdx.x * 128;
    const int b_   = bh >> 4;
    const int h_   = bh & 15;

    {
        const float* cbase = g_ctx + (size_t)bh * MM * DD;
#pragma unroll
        for (int t = 0; t < 64; t++) {
            int e = t * 256 + tid;
            int m = e >> 6, d = e & 63;
            float val = cbase[e];
            __nv_bfloat16 h = __float2bfloat16(val);
            __nv_bfloat16 l = __float2bfloat16(val - __bfloat162float(h));
            int mc = m & 63;
            uint32_t off = (uint32_t)((m >> 6) * 8192 + d * 128 + (((mc >> 3) ^ (d & 7)) << 4) + (mc & 7) * 2);
            *(ushort*)((char*)gsm + 49152 + off) = __bfloat16_as_ushort(h);
            *(ushort*)((char*)gsm + 81920 + off) = __bfloat16_as_ushort(l);
        }
    }

    const __nv_bfloat16* pA[3] = {QFh, QFh, QFl};

    float c[4][2][4];
#pragma unroll
    for (int i = 0; i < 4; i++)
#pragma unroll
        for (int j = 0; j < 2; j++)
#pragma unroll
            for (int q = 0; q < 4; q++) c[i][j][q] = 0.f;

    auto prefetchA = [&](int s, int stage) {
        if (s < YV_NCHUNK) {
            const int ph = s >> 2;
            const int kk = (s & 3) << 6;
            const __nv_bfloat16* gA = pA[ph] + (size_t)bh * NSEQ * MM;
            const uint32_t aB = smem_base + stage * YV_ASTG;
#pragma unroll
            for (int it = 0; it < 4; it++) {
                int idx = it * 256 + tid;
                int row = idx >> 3;
                int pb  = idx & 7;
                uint32_t doff = row * 128 + ((pb ^ (row & 7)) << 4);
                const void* srcA = gA + (size_t)(bm + row) * MM + kk + pb * 8;
                asm volatile("cp.async.cg.shared.global [%0], [%1], 16;" :: "r"(aB + doff), "l"(srcA));
            }
        }
        asm volatile("cp.async.commit_group;" ::: "memory");
    };

    prefetchA(0, 0);
    prefetchA(1, 1);
    __syncthreads();

    for (int s = 0; s < YV_NCHUNK; s++) {
        const int stage = s % 3;
        asm volatile("cp.async.wait_group 1;" ::: "memory");
        __syncthreads();
        prefetchA(s + 2, (s + 2) % 3);

        const uint32_t cA = smem_base + stage * YV_ASTG;
        const int ph = s >> 2;
        const uint32_t cBbase = (ph == 1) ? sBL : sBH;
        const uint32_t cB = cBbase + (uint32_t)((s & 3) * 8192);

#pragma unroll
        for (int ks = 0; ks < 4; ks++) {
            uint32_t bf[2][2];
            {
                int row = wn * 16 + ((lane >> 4) << 3) + (lane & 7);
                int pb  = ks * 2 + ((lane >> 3) & 1);
                uint32_t ad = cB + row * 128 + ((pb ^ (row & 7)) << 4);
                uint32_t t4[4];
                ldmx4(t4, ad);
                bf[0][0] = t4[0]; bf[0][1] = t4[1];
                bf[1][0] = t4[2]; bf[1][1] = t4[3];
            }
#pragma unroll
            for (int i = 0; i < 4; i++) {
                int r0 = wm * 64 + i * 16;
                int row = r0 + (((lane >> 3) & 1) << 3) + (lane & 7);
                int pb  = ks * 2 + ((lane >> 4) & 1);
                uint32_t ad = cA + row * 128 + ((pb ^ (row & 7)) << 4);
                uint32_t af[4];
                ldmx4(af, ad);
#pragma unroll
                for (int j = 0; j < 2; j++)
                    mma16816(c[i][j], af, bf[j]);
            }
        }
        __syncthreads();
    }

#pragma unroll
    for (int i = 0; i < 4; i++) {
        int rl = wm * 64 + i * 16 + (lane >> 2);
        int nA = bm + rl;
        int nB = nA + 8;
        float dA = g_dinv[(size_t)bh * NSEQ + nA];
        float dB = g_dinv[(size_t)bh * NSEQ + nB];
#pragma unroll
        for (int j = 0; j < 2; j++) {
            int col = wn * 16 + j * 8 + (lane & 3) * 2;
            float vA0 = c[i][j][0] * dA, vA1 = c[i][j][1] * dA;
            float vB0 = c[i][j][2] * dB, vB1 = c[i][j][3] * dB;
            __nv_bfloat16 hA0 = __float2bfloat16(vA0), hA1 = __float2bfloat16(vA1);
            __nv_bfloat16 hB0 = __float2bfloat16(vB0), hB1 = __float2bfloat16(vB1);
            uint32_t hvA = ((uint32_t)__bfloat16_as_ushort(hA1) << 16) | __bfloat16_as_ushort(hA0);
            uint32_t lvA = ((uint32_t)__bfloat16_as_ushort(__float2bfloat16(vA1 - __bfloat162float(hA1))) << 16)
                         | __bfloat16_as_ushort(__float2bfloat16(vA0 - __bfloat162float(hA0)));
            uint32_t hvB = ((uint32_t)__bfloat16_as_ushort(hB1) << 16) | __bfloat16_as_ushort(hB0);
            uint32_t lvB = ((uint32_t)__bfloat16_as_ushort(__float2bfloat16(vB1 - __bfloat162float(hB1))) << 16)
                         | __bfloat16_as_ushort(__float2bfloat16(vB0 - __bfloat162float(hB0)));
            size_t idxA = ((size_t)(b_ * NSEQ + nA)) * EE + h_ * DD + col;
            size_t idxB = ((size_t)(b_ * NSEQ + nB)) * EE + h_ * DD + col;
            *(uint32_t*)(OutH + idxA) = hvA;
            *(uint32_t*)(OutL + idxA) = lvA;
            *(uint32_t*)(OutH + idxB) = hvB;
            *(uint32_t*)(OutL + idxB) = lvB;
        }
    }
}

// ---------------- launch (R9 order) ----------------
extern "C" void kernel_launch(void* const* d_in, const int* in_sizes, int n_in,
                              void* d_out, int out_size) {
    const float* x    = (const float*)d_in[0];
    const float* Wq   = (const float*)d_in[1];
    const float* bq   = (const float*)d_in[2];
    const float* Wk   = (const float*)d_in[3];
    const float* bk   = (const float*)d_in[4];
    const float* Wv   = (const float*)d_in[5];
    const float* bv   = (const float*)d_in[6];
    const float* Wo   = (const float*)d_in[7];
    const float* bo   = (const float*)d_in[8];
    const float* proj = (const float*)d_in[9];
    float* out = (float*)d_out;

    float *pq, *pk, *pv, *pdinv;
    __nv_bfloat16 *pah, *pal, *pwh, *pwl, *pqfh, *pqfl;
    cudaGetSymbolAddress((void**)&pq,   g_q);
    cudaGetSymbolAddress((void**)&pk,   g_k);
    cudaGetSymbolAddress((void**)&pv,   g_v);
    cudaGetSymbolAddress((void**)&pdinv, g_dinv);
    cudaGetSymbolAddress((void**)&pah,  g_ah);
    cudaGetSymbolAddress((void**)&pal,  g_al);
    cudaGetSymbolAddress((void**)&pwh,  g_wh);
    cudaGetSymbolAddress((void**)&pwl,  g_wl);
    cudaGetSymbolAddress((void**)&pqfh, g_qfh);
    cudaGetSymbolAddress((void**)&pqfl, g_qfl);

    const int GEMM_SMEM = 3 * STG_BYTES;                                      // 98304
    const int QF_SMEM   = (DD * MM + 32 * DD + MM) * (int)sizeof(float);      // 74752
    const int YV_SMEM   = 3 * YV_ASTG + 2 * 32768;                            // 114688
    cudaFuncSetAttribute(gemm_mma<0>, cudaFuncAttributeMaxDynamicSharedMemorySize, GEMM_SMEM);
    cudaFuncSetAttribute(gemm_mma<1>, cudaFuncAttributeMaxDynamicSharedMemorySize, GEMM_SMEM);
    cudaFuncSetAttribute(ctx_fused,  cudaFuncAttributeMaxDynamicSharedMemorySize, CTXF_SMEM_BYTES);
    cudaFuncSetAttribute(qf_kernel,  cudaFuncAttributeMaxDynamicSharedMemorySize, QF_SMEM);
    cudaFuncSetAttribute(yv_gemm,    cudaFuncAttributeMaxDynamicSharedMemorySize, YV_SMEM);

    dim3 gg(EE / 128, TT / 128);

    init_kernel<<<1, 32>>>();

    split_kernel<<<2048, 256>>>(x, pah, pal, TT * EE / 4);

    split_kernel<<<512, 256>>>(Wq, pwh, pwl, EE * EE / 4);
    gemm_mma<1><<<gg, 256, GEMM_SMEM>>>(pah, pal, pwh, pwl, bq, pq);
    split_kernel<<<512, 256>>>(Wk, pwh, pwl, EE * EE / 4);
    gemm_mma<1><<<gg, 256, GEMM_SMEM>>>(pah, pal, pwh, pwl, bk, pk);
    split_kernel<<<512, 256>>>(Wv, pwh, pwl, EE * EE / 4);
    gemm_mma<1><<<gg, 256, GEMM_SMEM>>>(pah, pal, pwh, pwl, bv, pv);

    ctx_fused<<<dim3(BHn, NSEG), 256, CTXF_SMEM_BYTES>>>(pk, pv, proj);
    ctx_reduce_kernel<<<(BHn * MM * DD + 255) / 256, 256>>>();

    qf_kernel<<<dim3(BHn, 16), 256, QF_SMEM>>>(pq, proj, pqfh, pqfl, pdinv);

    yv_gemm<<<dim3(NSEQ / 128, BHn), 256, YV_SMEM>>>(pqfh, pqfl, pah, pal);

    split_kernel<<<512, 256>>>(Wo, pwh, pwl, EE * EE / 4);
    gemm_mma<0><<<gg, 256, GEMM_SMEM>>>(pah, pal, pwh, pwl, bo, out);
}

// round 12
// speedup vs baseline: 1.1650x; 1.0526x over previous
#include <cuda_runtime.h>
#include <cuda_bf16.h>
#include <math.h>
#include <stdint.h>

// Problem constants
#define BB   4
#define NSEQ 4096
#define EE   1024
#define HH   16
#define DD   64
#define MM   256
#define TT   (BB*NSEQ)     // 16384
#define BHn  (BB*HH)       // 64
#define NSEG 8

#define RATIO 0.0625f
#define EPSK  1e-4f
#define SCQ   0.3535533905932738f   // 64^-0.25

// ---------------- device scratch ----------------
__device__ float g_q[(size_t)BHn*NSEQ*DD];
__device__ float g_k[(size_t)BHn*NSEQ*DD];
__device__ float g_v[(size_t)BHn*NSEQ*DD];
__device__ float g_ksum[BHn*MM];
__device__ float g_ksump[(size_t)NSEG*BHn*MM];
__device__ float g_svp[(size_t)NSEG*BHn*DD];
__device__ float g_ctxp[(size_t)NSEG*BHn*MM*DD];
__device__ float g_ctx[BHn*MM*DD];
__device__ float g_dinv[(size_t)BHn*NSEQ];
__device__ float g_kstab;
__device__ __nv_bfloat16 g_ah[(size_t)TT*EE];
__device__ __nv_bfloat16 g_al[(size_t)TT*EE];
__device__ __nv_bfloat16 g_wh[(size_t)EE*EE];
__device__ __nv_bfloat16 g_wl[(size_t)EE*EE];
__device__ __nv_bfloat16 g_qfh[(size_t)BHn*NSEQ*MM];
__device__ __nv_bfloat16 g_qfl[(size_t)BHn*NSEQ*MM];

// ---------------- helpers ----------------
__device__ __forceinline__ void atomicMaxFloat(float* addr, float v) {
    if (v >= 0.f) atomicMax((int*)addr, __float_as_int(v));
    else          atomicMin((unsigned int*)addr, __float_as_uint(v));
}

__global__ void init_kernel() {
    if (blockIdx.x == 0 && threadIdx.x == 0) g_kstab = -INFINITY;
}

__device__ __forceinline__ uint32_t smem_u32(const void* p) {
    uint32_t a;
    asm("{ .reg .u64 t; cvta.to.shared.u64 t, %1; cvt.u32.u64 %0, t; }" : "=r"(a) : "l"(p));
    return a;
}

__device__ __forceinline__ void mma16816(float* c, const uint32_t* a, const uint32_t* b) {
    asm volatile(
        "mma.sync.aligned.m16n8k16.row.col.f32.bf16.bf16.f32 "
        "{%0,%1,%2,%3},{%4,%5,%6,%7},{%8,%9},{%0,%1,%2,%3};"
        : "+f"(c[0]), "+f"(c[1]), "+f"(c[2]), "+f"(c[3])
        : "r"(a[0]), "r"(a[1]), "r"(a[2]), "r"(a[3]), "r"(b[0]), "r"(b[1]));
}

__device__ __forceinline__ void ldmx4(uint32_t* r, uint32_t addr) {
    asm volatile("ldmatrix.sync.aligned.m8n8.x4.shared.b16 {%0,%1,%2,%3}, [%4];"
        : "=r"(r[0]), "=r"(r[1]), "=r"(r[2]), "=r"(r[3]) : "r"(addr));
}

// packed fp32x2
__device__ __forceinline__ void fma2(unsigned long long& d, unsigned long long a, unsigned long long b) {
    asm("fma.rn.f32x2 %0, %1, %2, %0;" : "+l"(d) : "l"(a), "l"(b));
}
__device__ __forceinline__ unsigned long long pack2(float x) {
    unsigned long long r;
    asm("mov.b64 %0, {%1, %1};" : "=l"(r) : "f"(x));
    return r;
}
__device__ __forceinline__ float2 unpack2(unsigned long long v) {
    float2 f;
    asm("mov.b64 {%0, %1}, %2;" : "=f"(f.x), "=f"(f.y) : "l"(v));
    return f;
}
__device__ __forceinline__ float f4c(const float4& v, int j) {
    return j == 0 ? v.x : j == 1 ? v.y : j == 2 ? v.z : v.w;
}
__device__ __forceinline__ ushort bfu(float x) {
    return __bfloat16_as_ushort(__float2bfloat16(x));
}

// ---------------- fp32 -> bf16 hi/lo split ----------------
__global__ __launch_bounds__(256) void split_kernel(
    const float* __restrict__ src, __nv_bfloat16* __restrict__ hi,
    __nv_bfloat16* __restrict__ lo, int n4)
{
    const float4* s4 = (const float4*)src;
    uint2* h2 = (uint2*)hi;
    uint2* l2 = (uint2*)lo;
    for (int i = blockIdx.x * 256 + threadIdx.x; i < n4; i += gridDim.x * 256) {
        float4 v = s4[i];
        __nv_bfloat16 h0 = __float2bfloat16(v.x);
        __nv_bfloat16 h1 = __float2bfloat16(v.y);
        __nv_bfloat16 h2b = __float2bfloat16(v.z);
        __nv_bfloat16 h3 = __float2bfloat16(v.w);
        __nv_bfloat16 l0 = __float2bfloat16(v.x - __bfloat162float(h0));
        __nv_bfloat16 l1 = __float2bfloat16(v.y - __bfloat162float(h1));
        __nv_bfloat16 l2b = __float2bfloat16(v.z - __bfloat162float(h2b));
        __nv_bfloat16 l3 = __float2bfloat16(v.w - __bfloat162float(h3));
        uint2 hv, lv;
        hv.x = ((uint32_t)__bfloat16_as_ushort(h1) << 16) | __bfloat16_as_ushort(h0);
        hv.y = ((uint32_t)__bfloat16_as_ushort(h3) << 16) | __bfloat16_as_ushort(h2b);
        lv.x = ((uint32_t)__bfloat16_as_ushort(l1) << 16) | __bfloat16_as_ushort(l0);
        lv.y = ((uint32_t)__bfloat16_as_ushort(l3) << 16) | __bfloat16_as_ushort(l2b);
        h2[i] = hv;
        l2[i] = lv;
    }
}

// ---------------- bf16-split mma.sync GEMM: K-chunk 64, 3-stage, ldmatrix ----------------
#define NCHUNK 48          // 3 passes * 1024/64
#define STG_BYTES 32768    // A(16K) + B(16K) per stage

template<int OUT_MODE>
__global__ __launch_bounds__(256) void gemm_mma(
    const __nv_bfloat16* __restrict__ Ah, const __nv_bfloat16* __restrict__ Al,
    const __nv_bfloat16* __restrict__ Wh, const __nv_bfloat16* __restrict__ Wl,
    const float* __restrict__ bias, float* __restrict__ C)
{
    extern __shared__ __align__(128) char gsm[];

    const int tid  = threadIdx.x;
    const int lane = tid & 31;
    const int wid  = tid >> 5;
    const int wm   = wid & 1;
    const int wn   = wid >> 1;
    const int bm   = blockIdx.y * 128;
    const int bn   = blockIdx.x * 128;

    const __nv_bfloat16* pA[3] = {Ah, Ah, Al};
    const __nv_bfloat16* pB[3] = {Wh, Wl, Wh};

    float c[4][4][4];
#pragma unroll
    for (int i = 0; i < 4; i++)
#pragma unroll
        for (int j = 0; j < 4; j++)
#pragma unroll
            for (int q = 0; q < 4; q++) c[i][j][q] = 0.f;

    const uint32_t smem_base = smem_u32(gsm);

    auto prefetch = [&](int s, int stage) {
        if (s < NCHUNK) {
            const int ph = s >> 4;
            const int kk = (s & 15) << 6;
            const __nv_bfloat16* gA = pA[ph];
            const __nv_bfloat16* gB = pB[ph];
            const uint32_t aB = smem_base + stage * STG_BYTES;
            const uint32_t bB = aB + 16384;
#pragma unroll
            for (int it = 0; it < 4; it++) {
                int idx = it * 256 + tid;
                int row = idx >> 3;
                int pb  = idx & 7;
                uint32_t doff = row * 128 + ((pb ^ (row & 7)) << 4);
                const void* srcA = gA + (size_t)(bm + row) * EE + kk + pb * 8;
                const void* srcB = gB + (size_t)(bn + row) * EE + kk + pb * 8;
                asm volatile("cp.async.cg.shared.global [%0], [%1], 16;" :: "r"(aB + doff), "l"(srcA));
                asm volatile("cp.async.cg.shared.global [%0], [%1], 16;" :: "r"(bB + doff), "l"(srcB));
            }
        }
        asm volatile("cp.async.commit_group;" ::: "memory");
    };

    prefetch(0, 0);
    prefetch(1, 1);

    for (int s = 0; s < NCHUNK; s++) {
        const int stage = s % 3;
        asm volatile("cp.async.wait_group 1;" ::: "memory");
        __syncthreads();
        prefetch(s + 2, (s + 2) % 3);

        const uint32_t cA = smem_base + stage * STG_BYTES;
        const uint32_t cB = cA + 16384;
#pragma unroll
        for (int ks = 0; ks < 4; ks++) {
            uint32_t bf[4][2];
#pragma unroll
            for (int jb = 0; jb < 2; jb++) {
                int row = wn * 32 + jb * 16 + ((lane >> 4) << 3) + (lane & 7);
                int pb  = ks * 2 + ((lane >> 3) & 1);
                uint32_t ad = cB + row * 128 + ((pb ^ (row & 7)) << 4);
                uint32_t t4[4];
                ldmx4(t4, ad);
                bf[jb * 2][0] = t4[0]; bf[jb * 2][1] = t4[1];
                bf[jb * 2 + 1][0] = t4[2]; bf[jb * 2 + 1][1] = t4[3];
            }
#pragma unroll
            for (int i = 0; i < 4; i++) {
                int r0 = wm * 64 + i * 16;
                int row = r0 + (((lane >> 3) & 1) << 3) + (lane & 7);
                int pb  = ks * 2 + ((lane >> 4) & 1);
                uint32_t ad = cA + row * 128 + ((pb ^ (row & 7)) << 4);
                uint32_t af[4];
                ldmx4(af, ad);
#pragma unroll
                for (int j = 0; j < 4; j++)
                    mma16816(c[i][j], af, bf[j]);
            }
        }
    }

#pragma unroll
    for (int i = 0; i < 4; i++) {
        int r = bm + wm * 64 + i * 16 + (lane >> 2);
#pragma unroll
        for (int j = 0; j < 4; j++) {
            int col = bn + wn * 32 + j * 8 + (lane & 3) * 2;
            float b0 = bias[col], b1 = bias[col + 1];
            float2 v0 = make_float2(c[i][j][0] + b0, c[i][j][1] + b1);
            float2 v1 = make_float2(c[i][j][2] + b0, c[i][j][3] + b1);
            if (OUT_MODE == 0) {
                *(float2*)(C + (size_t)r * EE + col)       = v0;
                *(float2*)(C + (size_t)(r + 8) * EE + col) = v1;
            } else {
                int h_ = col >> 6, d0 = col & 63;
                int b_ = r >> 12, n_ = r & 4095;
                size_t base = ((size_t)(b_ * HH + h_) * NSEQ);
                *(float2*)(C + (base + n_)     * DD + d0) = v0;
                *(float2*)(C + (base + n_ + 8) * DD + d0) = v1;
            }
        }
    }
}

// ---------------- ctx_fused v2: dd on tensor cores (R11, unchanged) ----------------
#define CF_STRIDE 260
#define CTXF_SMEM_BYTES 90432

__global__ __launch_bounds__(256, 2) void ctx_fused(
    const float* __restrict__ K, const float* __restrict__ V,
    const float* __restrict__ proj)
{
    extern __shared__ __align__(128) char csm[];
    const uint32_t smem_base = smem_u32(csm);
    const uint32_t sPTh = smem_base;
    const uint32_t sPTl = smem_base + 32768;
    const uint32_t sXh  = smem_base + 65536;
    const uint32_t sXl  = smem_base + 67584;
    float* sKF   = (float*)(csm + 69632);
    float* sV    = (float*)(csm + 86272);
    float* sDiag = (float*)(csm + 90368);
    __shared__ float swm[8];

    const int tid = threadIdx.x;
    const int bh  = blockIdx.x;
    const int seg = blockIdx.y;
    const int lane = tid & 31;
    const int w    = tid >> 5;
    const int tx   = tid & 15;
    const int ty   = tid >> 4;

    {
        const float4* pr = (const float4*)(proj + tid * DD);
#pragma unroll
        for (int t = 0; t < 16; t++) {
            float4 v = pr[t];
            ushort h0 = bfu(v.x), h1 = bfu(v.y), h2 = bfu(v.z), h3 = bfu(v.w);
            ushort l0 = bfu(v.x - __bfloat162float(__ushort_as_bfloat16(h0)));
            ushort l1 = bfu(v.y - __bfloat162float(__ushort_as_bfloat16(h1)));
            ushort l2 = bfu(v.z - __bfloat162float(__ushort_as_bfloat16(h2)));
            ushort l3 = bfu(v.w - __bfloat162float(__ushort_as_bfloat16(h3)));
            uint2 hv, lv;
            hv.x = ((uint32_t)h1 << 16) | h0; hv.y = ((uint32_t)h3 << 16) | h2;
            lv.x = ((uint32_t)l1 << 16) | l0; lv.y = ((uint32_t)l3 << 16) | l2;
            uint32_t off = (uint32_t)(tid * 128 + (((t >> 1) ^ (tid & 7)) << 4) + (t & 1) * 8);
            *(uint2*)(csm + off)         = hv;
            *(uint2*)(csm + 32768 + off) = lv;
        }
    }

    unsigned long long cacc[16][2];
#pragma unroll
    for (int i = 0; i < 16; i++) { cacc[i][0] = 0ull; cacc[i][1] = 0ull; }
    float kacc = 0.f;
    float svacc = 0.f;
    float ddmax = -1e30f;

    for (int it = 0; it < 32; it++) {
        const int n0 = seg * 512 + it * 16;
        __syncthreads();

        {
            int row = tid >> 4;
            int t   = tid & 15;
            const float* kp = K + ((size_t)bh * NSEQ + n0 + row) * DD + t * 4;
            const float* vp = V + ((size_t)bh * NSEQ + n0 + row) * DD + t * 4;
            float4 kv = *(const float4*)kp;
            float4 vv = *(const float4*)vp;
            kv.x *= SCQ; kv.y *= SCQ; kv.z *= SCQ; kv.w *= SCQ;
            float ssq = kv.x * kv.x + kv.y * kv.y + kv.z * kv.z + kv.w * kv.w;
#pragma unroll
            for (int o = 8; o > 0; o >>= 1) ssq += __shfl_xor_sync(0xffffffffu, ssq, o);
            if (t == 0) sDiag[row] = 0.5f * ssq;

            ushort h0 = bfu(kv.x), h1 = bfu(kv.y), h2 = bfu(kv.z), h3 = bfu(kv.w);
            ushort l0 = bfu(kv.x - __bfloat162float(__ushort_as_bfloat16(h0)));
            ushort l1 = bfu(kv.y - __bfloat162float(__ushort_as_bfloat16(h1)));
            ushort l2 = bfu(kv.z - __bfloat162float(__ushort_as_bfloat16(h2)));
            ushort l3 = bfu(kv.w - __bfloat162float(__ushort_as_bfloat16(h3)));
            uint2 hv, lv;
            hv.x = ((uint32_t)h1 << 16) | h0; hv.y = ((uint32_t)h3 << 16) | h2;
            lv.x = ((uint32_t)l1 << 16) | l0; lv.y = ((uint32_t)l3 << 16) | l2;
            uint32_t off = (uint32_t)(row * 128 + (((t >> 1) ^ (row & 7)) << 4) + (t & 1) * 8);
            *(uint2*)(csm + 65536 + off) = hv;
            *(uint2*)(csm + 67584 + off) = lv;
            *(float4*)(sV + row * 64 + t * 4) = vv;
        }
        __syncthreads();

        {
            float c[4][4];
#pragma unroll
            for (int j = 0; j < 4; j++)
#pragma unroll
                for (int q = 0; q < 4; q++) c[j][q] = 0.f;

            const uint32_t pASrc[3] = {sXh, sXh, sXl};
            const uint32_t pBSrc[3] = {sPTh, sPTl, sPTh};
#pragma unroll
            for (int ph = 0; ph < 3; ph++) {
                const uint32_t cA = pASrc[ph];
                const uint32_t cB = pBSrc[ph];
#pragma unroll
                for (int ks = 0; ks < 4; ks++) {
                    int rowA = (((lane >> 3) & 1) << 3) + (lane & 7);
                    int pbA  = ks * 2 + ((lane >> 4) & 1);
                    uint32_t adA = cA + rowA * 128 + ((pbA ^ (rowA & 7)) << 4);
                    uint32_t af[4];
                    ldmx4(af, adA);
                    uint32_t bf[4][2];
#pragma unroll
                    for (int jb = 0; jb < 2; jb++) {
                        int rowB = w * 32 + jb * 16 + ((lane >> 4) << 3) + (lane & 7);
                        int pbB  = ks * 2 + ((lane >> 3) & 1);
                        uint32_t adB = cB + rowB * 128 + ((pbB ^ (rowB & 7)) << 4);
                        uint32_t t4[4];
                        ldmx4(t4, adB);
                        bf[jb * 2][0] = t4[0]; bf[jb * 2][1] = t4[1];
                        bf[jb * 2 + 1][0] = t4[2]; bf[jb * 2 + 1][1] = t4[3];
                    }
#pragma unroll
                    for (int j = 0; j < 4; j++)
                        mma16816(c[j], af, bf[j]);
                }
            }

            const int r0 = lane >> 2;
            const int mb = w * 32 + (lane & 3) * 2;
            const float dg0 = sDiag[r0];
            const float dg1 = sDiag[r0 + 8];
#pragma unroll
            for (int j = 0; j < 4; j++) {
                int m = mb + j * 8;
                float v0 = c[j][0], v1 = c[j][1], v2 = c[j][2], v3 = c[j][3];
                ddmax = fmaxf(ddmax, fmaxf(fmaxf(v0, v1), fmaxf(v2, v3)));
                *(float2*)&sKF[r0 * CF_STRIDE + m] =
                    make_float2(__expf(v0 - dg0), __expf(v1 - dg0));
                *(float2*)&sKF[(r0 + 8) * CF_STRIDE + m] =
                    make_float2(__expf(v2 - dg1), __expf(v3 - dg1));
            }
        }
        __syncthreads();

#pragma unroll
        for (int r = 0; r < 16; r++) kacc += sKF[r * CF_STRIDE + tid];

        if (tid < 64) {
#pragma unroll
            for (int r = 0; r < 16; r++) svacc += sV[r * 64 + tid];
        }

        const ulonglong2* sV2 = (const ulonglong2*)sV;
#pragma unroll 4
        for (int r = 0; r < 16; r++) {
            ulonglong2 bv = sV2[r * 16 + tx];
            const float4* kf4 = (const float4*)&sKF[r * CF_STRIDE + ty * 16];
            float4 kq[4];
            kq[0] = kf4[0]; kq[1] = kf4[1]; kq[2] = kf4[2]; kq[3] = kf4[3];
#pragma unroll
            for (int q = 0; q < 4; q++) {
#pragma unroll
                for (int j = 0; j < 4; j++) {
                    unsigned long long av = pack2(f4c(kq[q], j));
                    fma2(cacc[q * 4 + j][0], av, bv.x);
                    fma2(cacc[q * 4 + j][1], av, bv.y);
                }
            }
        }
    }

    g_ksump[((size_t)seg * BHn + bh) * MM + tid] = kacc;
    if (tid < 64) g_svp[((size_t)seg * BHn + bh) * DD + tid] = svacc;

    float* cp = g_ctxp + ((size_t)seg * BHn + bh) * MM * DD;
#pragma unroll
    for (int i = 0; i < 16; i++) {
        float2 f0 = unpack2(cacc[i][0]);
        float2 f1 = unpack2(cacc[i][1]);
        *(float4*)(cp + (ty * 16 + i) * DD + tx * 4) = make_float4(f0.x, f0.y, f1.x, f1.y);
    }

#pragma unroll
    for (int o = 16; o > 0; o >>= 1)
        ddmax = fmaxf(ddmax, __shfl_xor_sync(0xffffffffu, ddmax, o));
    if (lane == 0) swm[w] = ddmax;
    __syncthreads();
    if (tid == 0) {
        float m = swm[0];
#pragma unroll
        for (int i = 1; i < 8; i++) m = fmaxf(m, swm[i]);
        atomicMaxFloat(&g_kstab, m);
    }
}

// ---------------- assemble ctx + ksum from unstabilized partials ----------------
__global__ __launch_bounds__(256) void ctx_reduce_kernel() {
    const float escale = __expf(-g_kstab);
    int i = blockIdx.x * 256 + threadIdx.x;
    if (i < BHn * MM * DD) {
        int bh = i >> 14;
        int d  = i & 63;
        float U = 0.f, Sv = 0.f;
#pragma unroll
        for (int seg = 0; seg < NSEG; seg++) {
            U  += g_ctxp[(size_t)seg * BHn * MM * DD + i];
            Sv += g_svp[((size_t)seg * BHn + bh) * DD + d];
        }
        g_ctx[i] = RATIO * (escale * U + EPSK * Sv);
    }
    if (i < BHn * MM) {
        float T = 0.f;
#pragma unroll
        for (int seg = 0; seg < NSEG; seg++)
            T += g_ksump[(size_t)seg * BHn * MM + i];
        g_ksum[i] = RATIO * (escale * T + EPSK * (float)NSEQ);
    }
}

// ---------------- qf_kernel v2: dd on tensor cores ----------------
// grid (BHn, 16), block 256. Each block: 256 rows as 16 tiles of 16.
// Per-row max + dp via fixed-order cross-warp reductions (deterministic).
// smem: sPTh@0 32K, sPTl@32768 32K, sXh@65536 2K, sXl@67584 2K,
//       sKs@69632 1K, sDiag@70656 64B, sMaxP@70720 512B, sDpP@71232 512B
#define QF_SMEM_BYTES 71744

__global__ __launch_bounds__(256, 3) void qf_kernel(
    const float* __restrict__ Q, const float* __restrict__ proj,
    __nv_bfloat16* __restrict__ QFh, __nv_bfloat16* __restrict__ QFl,
    float* __restrict__ Dinv)
{
    extern __shared__ __align__(128) char qsm[];
    const uint32_t smem_base = smem_u32(qsm);
    const uint32_t sPTh = smem_base;
    const uint32_t sPTl = smem_base + 32768;
    const uint32_t sXh  = smem_base + 65536;
    const uint32_t sXl  = smem_base + 67584;
    float* sKs   = (float*)(qsm + 69632);
    float* sDiag = (float*)(qsm + 70656);
    float* sMaxP = (float*)(qsm + 70720);   // [8 warps][16 rows]
    float* sDpP  = (float*)(qsm + 71232);   // [8 warps][16 rows]

    const int tid = threadIdx.x;
    const int bh  = blockIdx.x;
    const int nblk = blockIdx.y * 256;
    const int lane = tid & 31;
    const int w    = tid >> 5;

    // convert proj -> resident bf16 hi/lo (same as ctx_fused); load ksum
    {
        const float4* pr = (const float4*)(proj + tid * DD);
#pragma unroll
        for (int t = 0; t < 16; t++) {
            float4 v = pr[t];
            ushort h0 = bfu(v.x), h1 = bfu(v.y), h2 = bfu(v.z), h3 = bfu(v.w);
            ushort l0 = bfu(v.x - __bfloat162float(__ushort_as_bfloat16(h0)));
            ushort l1 = bfu(v.y - __bfloat162float(__ushort_as_bfloat16(h1)));
            ushort l2 = bfu(v.z - __bfloat162float(__ushort_as_bfloat16(h2)));
            ushort l3 = bfu(v.w - __bfloat162float(__ushort_as_bfloat16(h3)));
            uint2 hv, lv;
            hv.x = ((uint32_t)h1 << 16) | h0; hv.y = ((uint32_t)h3 << 16) | h2;
            lv.x = ((uint32_t)l1 << 16) | l0; lv.y = ((uint32_t)l3 << 16) | l2;
            uint32_t off = (uint32_t)(tid * 128 + (((t >> 1) ^ (tid & 7)) << 4) + (t & 1) * 8);
            *(uint2*)(qsm + off)         = hv;
            *(uint2*)(qsm + 32768 + off) = lv;
        }
        sKs[tid] = g_ksum[bh * MM + tid];
    }

    for (int it = 0; it < 16; it++) {
        const int n0 = nblk + it * 16;
        __syncthreads();   // prior iter's sMaxP/sDpP/sDiag reads done (proj ready on it=0)

        // load 16 rows of Q (scaled); diag; bf16 hi/lo X tile
        {
            int row = tid >> 4;
            int t   = tid & 15;
            const float* qp = Q + ((size_t)bh * NSEQ + n0 + row) * DD + t * 4;
            float4 kv = *(const float4*)qp;
            kv.x *= SCQ; kv.y *= SCQ; kv.z *= SCQ; kv.w *= SCQ;
            float ssq = kv.x * kv.x + kv.y * kv.y + kv.z * kv.z + kv.w * kv.w;
#pragma unroll
            for (int o = 8; o > 0; o >>= 1) ssq += __shfl_xor_sync(0xffffffffu, ssq, o);
            if (t == 0) sDiag[row] = 0.5f * ssq;

            ushort h0 = bfu(kv.x), h1 = bfu(kv.y), h2 = bfu(kv.z), h3 = bfu(kv.w);
            ushort l0 = bfu(kv.x - __bfloat162float(__ushort_as_bfloat16(h0)));
            ushort l1 = bfu(kv.y - __bfloat162float(__ushort_as_bfloat16(h1)));
            ushort l2 = bfu(kv.z - __bfloat162float(__ushort_as_bfloat16(h2)));
            ushort l3 = bfu(kv.w - __bfloat162float(__ushort_as_bfloat16(h3)));
            uint2 hv, lv;
            hv.x = ((uint32_t)h1 << 16) | h0; hv.y = ((uint32_t)h3 << 16) | h2;
            lv.x = ((uint32_t)l1 << 16) | l0; lv.y = ((uint32_t)l3 << 16) | l2;
            uint32_t off = (uint32_t)(row * 128 + (((t >> 1) ^ (row & 7)) << 4) + (t & 1) * 8);
            *(uint2*)(qsm + 65536 + off) = hv;
            *(uint2*)(qsm + 67584 + off) = lv;
        }
        __syncthreads();

        // dd-mma: 3 passes, M=16 (rows), N=256 (m; warp slice 32), K=64
        float c[4][4];
#pragma unroll
        for (int j = 0; j < 4; j++)
#pragma unroll
            for (int q = 0; q < 4; q++) c[j][q] = 0.f;
        {
            const uint32_t pASrc[3] = {sXh, sXh, sXl};
            const uint32_t pBSrc[3] = {sPTh, sPTl, sPTh};
#pragma unroll
            for (int ph = 0; ph < 3; ph++) {
                const uint32_t cA = pASrc[ph];
                const uint32_t cB = pBSrc[ph];
#pragma unroll
                for (int ks = 0; ks < 4; ks++) {
                    int rowA = (((lane >> 3) & 1) << 3) + (lane & 7);
                    int pbA  = ks * 2 + ((lane >> 4) & 1);
                    uint32_t adA = cA + rowA * 128 + ((pbA ^ (rowA & 7)) << 4);
                    uint32_t af[4];
                    ldmx4(af, adA);
                    uint32_t bf[4][2];
#pragma unroll
                    for (int jb = 0; jb < 2; jb++) {
                        int rowB = w * 32 + jb * 16 + ((lane >> 4) << 3) + (lane & 7);
                        int pbB  = ks * 2 + ((lane >> 3) & 1);
                        uint32_t adB = cB + rowB * 128 + ((pbB ^ (rowB & 7)) << 4);
                        uint32_t t4[4];
                        ldmx4(t4, adB);
                        bf[jb * 2][0] = t4[0]; bf[jb * 2][1] = t4[1];
                        bf[jb * 2 + 1][0] = t4[2]; bf[jb * 2 + 1][1] = t4[3];
                    }
#pragma unroll
                    for (int j = 0; j < 4; j++)
                        mma16816(c[j], af, bf[j]);
                }
            }
        }

        const int r0 = lane >> 2;

        // per-row max: fragment max -> shfl over q bits -> per-warp partials
        {
            float mx0 = -1e30f, mx1 = -1e30f;
#pragma unroll
            for (int j = 0; j < 4; j++) {
                mx0 = fmaxf(mx0, fmaxf(c[j][0], c[j][1]));
                mx1 = fmaxf(mx1, fmaxf(c[j][2], c[j][3]));
            }
            mx0 = fmaxf(mx0, __shfl_xor_sync(0xffffffffu, mx0, 1));
            mx0 = fmaxf(mx0, __shfl_xor_sync(0xffffffffu, mx0, 2));
            mx1 = fmaxf(mx1, __shfl_xor_sync(0xffffffffu, mx1, 1));
            mx1 = fmaxf(mx1, __shfl_xor_sync(0xffffffffu, mx1, 2));
            if ((lane & 3) == 0) {
                sMaxP[w * 16 + r0]     = mx0;
                sMaxP[w * 16 + r0 + 8] = mx1;
            }
        }
        __syncthreads();

        // final row max (fixed-order scan of 8 warps), exp, pack, store, dp
        {
            float fmx0 = sMaxP[r0], fmx1 = sMaxP[r0 + 8];
#pragma unroll
            for (int ww = 1; ww < 8; ww++) {
                fmx0 = fmaxf(fmx0, sMaxP[ww * 16 + r0]);
                fmx1 = fmaxf(fmx1, sMaxP[ww * 16 + r0 + 8]);
            }
            const float sub0 = sDiag[r0] + fmx0;
            const float sub1 = sDiag[r0 + 8] + fmx1;
            const int mb = w * 32 + (lane & 3) * 2;
            const size_t baseA = ((size_t)bh * NSEQ + n0 + r0) * MM;
            const size_t baseB = baseA + 8 * MM;
            float dp0 = 0.f, dp1 = 0.f;
#pragma unroll
            for (int j = 0; j < 4; j++) {
                int m = mb + j * 8;
                float q0 = RATIO * (__expf(c[j][0] - sub0) + EPSK);
                float q1 = RATIO * (__expf(c[j][1] - sub0) + EPSK);
                float q2 = RATIO * (__expf(c[j][2] - sub1) + EPSK);
                float q3 = RATIO * (__expf(c[j][3] - sub1) + EPSK);
                dp0 += q0 * sKs[m] + q1 * sKs[m + 1];
                dp1 += q2 * sKs[m] + q3 * sKs[m + 1];
                ushort h0 = bfu(q0), h1 = bfu(q1), h2 = bfu(q2), h3 = bfu(q3);
                uint32_t hv0 = ((uint32_t)h1 << 16) | h0;
                uint32_t hv1 = ((uint32_t)h3 << 16) | h2;
                uint32_t lv0 = ((uint32_t)bfu(q1 - __bfloat162float(__ushort_as_bfloat16(h1))) << 16)
                             | bfu(q0 - __bfloat162float(__ushort_as_bfloat16(h0)));
                uint32_t lv1 = ((uint32_t)bfu(q3 - __bfloat162float(__ushort_as_bfloat16(h3))) << 16)
                             | bfu(q2 - __bfloat162float(__ushort_as_bfloat16(h2)));
                *(uint32_t*)(QFh + baseA + m) = hv0;
                *(uint32_t*)(QFl + baseA + m) = lv0;
                *(uint32_t*)(QFh + baseB + m) = hv1;
                *(uint32_t*)(QFl + baseB + m) = lv1;
            }
            dp0 += __shfl_xor_sync(0xffffffffu, dp0, 1);
            dp0 += __shfl_xor_sync(0xffffffffu, dp0, 2);
            dp1 += __shfl_xor_sync(0xffffffffu, dp1, 1);
            dp1 += __shfl_xor_sync(0xffffffffu, dp1, 2);
            if ((lane & 3) == 0) {
                sDpP[w * 16 + r0]     = dp0;
                sDpP[w * 16 + r0 + 8] = dp1;
            }
        }
        __syncthreads();

        if (tid < 16) {
            float s = sDpP[tid];
#pragma unroll
            for (int ww = 1; ww < 8; ww++) s += sDpP[ww * 16 + tid];
            Dinv[(size_t)bh * NSEQ + n0 + tid] = 1.f / s;
        }
    }
}

// ---------------- yv_gemm: per-head y = qf @ ctx^T, * dinv, bf16-split output (R9, unchanged) ----------------
#define YV_NCHUNK 12
#define YV_ASTG  16384

__global__ __launch_bounds__(256, 2) void yv_gemm(
    const __nv_bfloat16* __restrict__ QFh, const __nv_bfloat16* __restrict__ QFl,
    __nv_bfloat16* __restrict__ OutH, __nv_bfloat16* __restrict__ OutL)
{
    extern __shared__ __align__(128) char gsm[];
    const uint32_t smem_base = smem_u32(gsm);
    const uint32_t sBH = smem_base + 49152;
    const uint32_t sBL = smem_base + 81920;

    const int tid  = threadIdx.x;
    const int lane = tid & 31;
    const int wid  = tid >> 5;
    const int wm   = wid & 1;
    const int wn   = wid >> 1;
    const int bh   = blockIdx.y;
    const int bm   = blockIdx.x * 128;
    const int b_   = bh >> 4;
    const int h_   = bh & 15;

    {
        const float* cbase = g_ctx + (size_t)bh * MM * DD;
#pragma unroll
        for (int t = 0; t < 64; t++) {
            int e = t * 256 + tid;
            int m = e >> 6, d = e & 63;
            float val = cbase[e];
            __nv_bfloat16 h = __float2bfloat16(val);
            __nv_bfloat16 l = __float2bfloat16(val - __bfloat162float(h));
            int mc = m & 63;
            uint32_t off = (uint32_t)((m >> 6) * 8192 + d * 128 + (((mc >> 3) ^ (d & 7)) << 4) + (mc & 7) * 2);
            *(ushort*)((char*)gsm + 49152 + off) = __bfloat16_as_ushort(h);
            *(ushort*)((char*)gsm + 81920 + off) = __bfloat16_as_ushort(l);
        }
    }

    const __nv_bfloat16* pA[3] = {QFh, QFh, QFl};

    float c[4][2][4];
#pragma unroll
    for (int i = 0; i < 4; i++)
#pragma unroll
        for (int j = 0; j < 2; j++)
#pragma unroll
            for (int q = 0; q < 4; q++) c[i][j][q] = 0.f;

    auto prefetchA = [&](int s, int stage) {
        if (s < YV_NCHUNK) {
            const int ph = s >> 2;
            const int kk = (s & 3) << 6;
            const __nv_bfloat16* gA = pA[ph] + (size_t)bh * NSEQ * MM;
            const uint32_t aB = smem_base + stage * YV_ASTG;
#pragma unroll
            for (int it = 0; it < 4; it++) {
                int idx = it * 256 + tid;
                int row = idx >> 3;
                int pb  = idx & 7;
                uint32_t doff = row * 128 + ((pb ^ (row & 7)) << 4);
                const void* srcA = gA + (size_t)(bm + row) * MM + kk + pb * 8;
                asm volatile("cp.async.cg.shared.global [%0], [%1], 16;" :: "r"(aB + doff), "l"(srcA));
            }
        }
        asm volatile("cp.async.commit_group;" ::: "memory");
    };

    prefetchA(0, 0);
    prefetchA(1, 1);
    __syncthreads();

    for (int s = 0; s < YV_NCHUNK; s++) {
        const int stage = s % 3;
        asm volatile("cp.async.wait_group 1;" ::: "memory");
        __syncthreads();
        prefetchA(s + 2, (s + 2) % 3);

        const uint32_t cA = smem_base + stage * YV_ASTG;
        const int ph = s >> 2;
        const uint32_t cBbase = (ph == 1) ? sBL : sBH;
        const uint32_t cB = cBbase + (uint32_t)((s & 3) * 8192);

#pragma unroll
        for (int ks = 0; ks < 4; ks++) {
            uint32_t bf[2][2];
            {
                int row = wn * 16 + ((lane >> 4) << 3) + (lane & 7);
                int pb  = ks * 2 + ((lane >> 3) & 1);
                uint32_t ad = cB + row * 128 + ((pb ^ (row & 7)) << 4);
                uint32_t t4[4];
                ldmx4(t4, ad);
                bf[0][0] = t4[0]; bf[0][1] = t4[1];
                bf[1][0] = t4[2]; bf[1][1] = t4[3];
            }
#pragma unroll
            for (int i = 0; i < 4; i++) {
                int r0 = wm * 64 + i * 16;
                int row = r0 + (((lane >> 3) & 1) << 3) + (lane & 7);
                int pb  = ks * 2 + ((lane >> 4) & 1);
                uint32_t ad = cA + row * 128 + ((pb ^ (row & 7)) << 4);
                uint32_t af[4];
                ldmx4(af, ad);
#pragma unroll
                for (int j = 0; j < 2; j++)
                    mma16816(c[i][j], af, bf[j]);
            }
        }
        __syncthreads();
    }

#pragma unroll
    for (int i = 0; i < 4; i++) {
        int rl = wm * 64 + i * 16 + (lane >> 2);
        int nA = bm + rl;
        int nB = nA + 8;
        float dA = g_dinv[(size_t)bh * NSEQ + nA];
        float dB = g_dinv[(size_t)bh * NSEQ + nB];
#pragma unroll
        for (int j = 0; j < 2; j++) {
            int col = wn * 16 + j * 8 + (lane & 3) * 2;
            float vA0 = c[i][j][0] * dA, vA1 = c[i][j][1] * dA;
            float vB0 = c[i][j][2] * dB, vB1 = c[i][j][3] * dB;
            __nv_bfloat16 hA0 = __float2bfloat16(vA0), hA1 = __float2bfloat16(vA1);
            __nv_bfloat16 hB0 = __float2bfloat16(vB0), hB1 = __float2bfloat16(vB1);
            uint32_t hvA = ((uint32_t)__bfloat16_as_ushort(hA1) << 16) | __bfloat16_as_ushort(hA0);
            uint32_t lvA = ((uint32_t)__bfloat16_as_ushort(__float2bfloat16(vA1 - __bfloat162float(hA1))) << 16)
                         | __bfloat16_as_ushort(__float2bfloat16(vA0 - __bfloat162float(hA0)));
            uint32_t hvB = ((uint32_t)__bfloat16_as_ushort(hB1) << 16) | __bfloat16_as_ushort(hB0);
            uint32_t lvB = ((uint32_t)__bfloat16_as_ushort(__float2bfloat16(vB1 - __bfloat162float(hB1))) << 16)
                         | __bfloat16_as_ushort(__float2bfloat16(vB0 - __bfloat162float(hB0)));
            size_t idxA = ((size_t)(b_ * NSEQ + nA)) * EE + h_ * DD + col;
            size_t idxB = ((size_t)(b_ * NSEQ + nB)) * EE + h_ * DD + col;
            *(uint32_t*)(OutH + idxA) = hvA;
            *(uint32_t*)(OutL + idxA) = lvA;
            *(uint32_t*)(OutH + idxB) = hvB;
            *(uint32_t*)(OutL + idxB) = lvB;
        }
    }
}

// ---------------- launch ----------------
extern "C" void kernel_launch(void* const* d_in, const int* in_sizes, int n_in,
                              void* d_out, int out_size) {
    const float* x    = (const float*)d_in[0];
    const float* Wq   = (const float*)d_in[1];
    const float* bq   = (const float*)d_in[2];
    const float* Wk   = (const float*)d_in[3];
    const float* bk   = (const float*)d_in[4];
    const float* Wv   = (const float*)d_in[5];
    const float* bv   = (const float*)d_in[6];
    const float* Wo   = (const float*)d_in[7];
    const float* bo   = (const float*)d_in[8];
    const float* proj = (const float*)d_in[9];
    float* out = (float*)d_out;

    float *pq, *pk, *pv, *pdinv;
    __nv_bfloat16 *pah, *pal, *pwh, *pwl, *pqfh, *pqfl;
    cudaGetSymbolAddress((void**)&pq,   g_q);
    cudaGetSymbolAddress((void**)&pk,   g_k);
    cudaGetSymbolAddress((void**)&pv,   g_v);
    cudaGetSymbolAddress((void**)&pdinv, g_dinv);
    cudaGetSymbolAddress((void**)&pah,  g_ah);
    cudaGetSymbolAddress((void**)&pal,  g_al);
    cudaGetSymbolAddress((void**)&pwh,  g_wh);
    cudaGetSymbolAddress((void**)&pwl,  g_wl);
    cudaGetSymbolAddress((void**)&pqfh, g_qfh);
    cudaGetSymbolAddress((void**)&pqfl, g_qfl);

    const int GEMM_SMEM = 3 * STG_BYTES;                                      // 98304
    const int YV_SMEM   = 3 * YV_ASTG + 2 * 32768;                            // 114688
    cudaFuncSetAttribute(gemm_mma<0>, cudaFuncAttributeMaxDynamicSharedMemorySize, GEMM_SMEM);
    cudaFuncSetAttribute(gemm_mma<1>, cudaFuncAttributeMaxDynamicSharedMemorySize, GEMM_SMEM);
    cudaFuncSetAttribute(ctx_fused,  cudaFuncAttributeMaxDynamicSharedMemorySize, CTXF_SMEM_BYTES);
    cudaFuncSetAttribute(qf_kernel,  cudaFuncAttributeMaxDynamicSharedMemorySize, QF_SMEM_BYTES);
    cudaFuncSetAttribute(yv_gemm,    cudaFuncAttributeMaxDynamicSharedMemorySize, YV_SMEM);

    dim3 gg(EE / 128, TT / 128);

    init_kernel<<<1, 32>>>();

    split_kernel<<<2048, 256>>>(x, pah, pal, TT * EE / 4);

    split_kernel<<<512, 256>>>(Wq, pwh, pwl, EE * EE / 4);
    gemm_mma<1><<<gg, 256, GEMM_SMEM>>>(pah, pal, pwh, pwl, bq, pq);
    split_kernel<<<512, 256>>>(Wk, pwh, pwl, EE * EE / 4);
    gemm_mma<1><<<gg, 256, GEMM_SMEM>>>(pah, pal, pwh, pwl, bk, pk);
    split_kernel<<<512, 256>>>(Wv, pwh, pwl, EE * EE / 4);
    gemm_mma<1><<<gg, 256, GEMM_SMEM>>>(pah, pal, pwh, pwl, bv, pv);

    ctx_fused<<<dim3(BHn, NSEG), 256, CTXF_SMEM_BYTES>>>(pk, pv, proj);
    ctx_reduce_kernel<<<(BHn * MM * DD + 255) / 256, 256>>>();

    qf_kernel<<<dim3(BHn, 16), 256, QF_SMEM_BYTES>>>(pq, proj, pqfh, pqfl, pdinv);

    yv_gemm<<<dim3(NSEQ / 128, BHn), 256, YV_SMEM>>>(pqfh, pqfl, pah, pal);

    split_kernel<<<512, 256>>>(Wo, pwh, pwl, EE * EE / 4);
    gemm_mma<0><<<gg, 256, GEMM_SMEM>>>(pah, pal, pwh, pwl, bo, out);
}

// round 13
// speedup vs baseline: 1.2197x; 1.0469x over previous
#include <cuda_runtime.h>
#include <cuda_bf16.h>
#include <math.h>
#include <stdint.h>

// Problem constants
#define BB   4
#define NSEQ 4096
#define EE   1024
#define HH   16
#define DD   64
#define MM   256
#define TT   (BB*NSEQ)     // 16384
#define BHn  (BB*HH)       // 64
#define NSEG 8

#define RATIO 0.0625f
#define EPSK  1e-4f
#define SCQ   0.3535533905932738f   // 64^-0.25

// ---------------- device scratch ----------------
__device__ float g_q[(size_t)BHn*NSEQ*DD];
__device__ float g_k[(size_t)BHn*NSEQ*DD];
__device__ float g_v[(size_t)BHn*NSEQ*DD];
__device__ float g_ksum[BHn*MM];
__device__ float g_ksump[(size_t)NSEG*BHn*MM];
__device__ float g_svp[(size_t)NSEG*BHn*DD];
__device__ float g_ctxp[(size_t)NSEG*BHn*MM*DD];
__device__ float g_ctx[BHn*MM*DD];
__device__ float g_dinv[(size_t)BHn*NSEQ];
__device__ float g_kstab;
__device__ __nv_bfloat16 g_ah[(size_t)TT*EE];
__device__ __nv_bfloat16 g_al[(size_t)TT*EE];
__device__ __nv_bfloat16 g_wh[(size_t)EE*EE];
__device__ __nv_bfloat16 g_wl[(size_t)EE*EE];
__device__ __nv_bfloat16 g_qfh[(size_t)BHn*NSEQ*MM];
__device__ __nv_bfloat16 g_qfl[(size_t)BHn*NSEQ*MM];

// ---------------- helpers ----------------
__device__ __forceinline__ void atomicMaxFloat(float* addr, float v) {
    if (v >= 0.f) atomicMax((int*)addr, __float_as_int(v));
    else          atomicMin((unsigned int*)addr, __float_as_uint(v));
}

__global__ void init_kernel() {
    if (blockIdx.x == 0 && threadIdx.x == 0) g_kstab = -INFINITY;
}

__device__ __forceinline__ uint32_t smem_u32(const void* p) {
    uint32_t a;
    asm("{ .reg .u64 t; cvta.to.shared.u64 t, %1; cvt.u32.u64 %0, t; }" : "=r"(a) : "l"(p));
    return a;
}

__device__ __forceinline__ void mma16816(float* c, const uint32_t* a, const uint32_t* b) {
    asm volatile(
        "mma.sync.aligned.m16n8k16.row.col.f32.bf16.bf16.f32 "
        "{%0,%1,%2,%3},{%4,%5,%6,%7},{%8,%9},{%0,%1,%2,%3};"
        : "+f"(c[0]), "+f"(c[1]), "+f"(c[2]), "+f"(c[3])
        : "r"(a[0]), "r"(a[1]), "r"(a[2]), "r"(a[3]), "r"(b[0]), "r"(b[1]));
}

__device__ __forceinline__ void ldmx4(uint32_t* r, uint32_t addr) {
    asm volatile("ldmatrix.sync.aligned.m8n8.x4.shared.b16 {%0,%1,%2,%3}, [%4];"
        : "=r"(r[0]), "=r"(r[1]), "=r"(r[2]), "=r"(r[3]) : "r"(addr));
}
__device__ __forceinline__ void ldmx4t(uint32_t* r, uint32_t addr) {
    asm volatile("ldmatrix.sync.aligned.m8n8.x4.trans.shared.b16 {%0,%1,%2,%3}, [%4];"
        : "=r"(r[0]), "=r"(r[1]), "=r"(r[2]), "=r"(r[3]) : "r"(addr));
}

// packed fp32x2
__device__ __forceinline__ void fma2(unsigned long long& d, unsigned long long a, unsigned long long b) {
    asm("fma.rn.f32x2 %0, %1, %2, %0;" : "+l"(d) : "l"(a), "l"(b));
}
__device__ __forceinline__ unsigned long long pack2(float x) {
    unsigned long long r;
    asm("mov.b64 %0, {%1, %1};" : "=l"(r) : "f"(x));
    return r;
}
__device__ __forceinline__ float2 unpack2(unsigned long long v) {
    float2 f;
    asm("mov.b64 {%0, %1}, %2;" : "=f"(f.x), "=f"(f.y) : "l"(v));
    return f;
}
__device__ __forceinline__ float f4c(const float4& v, int j) {
    return j == 0 ? v.x : j == 1 ? v.y : j == 2 ? v.z : v.w;
}
__device__ __forceinline__ ushort bfu(float x) {
    return __bfloat16_as_ushort(__float2bfloat16(x));
}

// ---------------- fp32 -> bf16 hi/lo split ----------------
__global__ __launch_bounds__(256) void split_kernel(
    const float* __restrict__ src, __nv_bfloat16* __restrict__ hi,
    __nv_bfloat16* __restrict__ lo, int n4)
{
    const float4* s4 = (const float4*)src;
    uint2* h2 = (uint2*)hi;
    uint2* l2 = (uint2*)lo;
    for (int i = blockIdx.x * 256 + threadIdx.x; i < n4; i += gridDim.x * 256) {
        float4 v = s4[i];
        __nv_bfloat16 h0 = __float2bfloat16(v.x);
        __nv_bfloat16 h1 = __float2bfloat16(v.y);
        __nv_bfloat16 h2b = __float2bfloat16(v.z);
        __nv_bfloat16 h3 = __float2bfloat16(v.w);
        __nv_bfloat16 l0 = __float2bfloat16(v.x - __bfloat162float(h0));
        __nv_bfloat16 l1 = __float2bfloat16(v.y - __bfloat162float(h1));
        __nv_bfloat16 l2b = __float2bfloat16(v.z - __bfloat162float(h2b));
        __nv_bfloat16 l3 = __float2bfloat16(v.w - __bfloat162float(h3));
        uint2 hv, lv;
        hv.x = ((uint32_t)__bfloat16_as_ushort(h1) << 16) | __bfloat16_as_ushort(h0);
        hv.y = ((uint32_t)__bfloat16_as_ushort(h3) << 16) | __bfloat16_as_ushort(h2b);
        lv.x = ((uint32_t)__bfloat16_as_ushort(l1) << 16) | __bfloat16_as_ushort(l0);
        lv.y = ((uint32_t)__bfloat16_as_ushort(l3) << 16) | __bfloat16_as_ushort(l2b);
        h2[i] = hv;
        l2[i] = lv;
    }
}

// ---------------- bf16-split mma.sync GEMM: K-chunk 64, 3-stage, ldmatrix ----------------
#define NCHUNK 48
#define STG_BYTES 32768

template<int OUT_MODE>
__global__ __launch_bounds__(256) void gemm_mma(
    const __nv_bfloat16* __restrict__ Ah, const __nv_bfloat16* __restrict__ Al,
    const __nv_bfloat16* __restrict__ Wh, const __nv_bfloat16* __restrict__ Wl,
    const float* __restrict__ bias, float* __restrict__ C)
{
    extern __shared__ __align__(128) char gsm[];

    const int tid  = threadIdx.x;
    const int lane = tid & 31;
    const int wid  = tid >> 5;
    const int wm   = wid & 1;
    const int wn   = wid >> 1;
    const int bm   = blockIdx.y * 128;
    const int bn   = blockIdx.x * 128;

    const __nv_bfloat16* pA[3] = {Ah, Ah, Al};
    const __nv_bfloat16* pB[3] = {Wh, Wl, Wh};

    float c[4][4][4];
#pragma unroll
    for (int i = 0; i < 4; i++)
#pragma unroll
        for (int j = 0; j < 4; j++)
#pragma unroll
            for (int q = 0; q < 4; q++) c[i][j][q] = 0.f;

    const uint32_t smem_base = smem_u32(gsm);

    auto prefetch = [&](int s, int stage) {
        if (s < NCHUNK) {
            const int ph = s >> 4;
            const int kk = (s & 15) << 6;
            const __nv_bfloat16* gA = pA[ph];
            const __nv_bfloat16* gB = pB[ph];
            const uint32_t aB = smem_base + stage * STG_BYTES;
            const uint32_t bB = aB + 16384;
#pragma unroll
            for (int it = 0; it < 4; it++) {
                int idx = it * 256 + tid;
                int row = idx >> 3;
                int pb  = idx & 7;
                uint32_t doff = row * 128 + ((pb ^ (row & 7)) << 4);
                const void* srcA = gA + (size_t)(bm + row) * EE + kk + pb * 8;
                const void* srcB = gB + (size_t)(bn + row) * EE + kk + pb * 8;
                asm volatile("cp.async.cg.shared.global [%0], [%1], 16;" :: "r"(aB + doff), "l"(srcA));
                asm volatile("cp.async.cg.shared.global [%0], [%1], 16;" :: "r"(bB + doff), "l"(srcB));
            }
        }
        asm volatile("cp.async.commit_group;" ::: "memory");
    };

    prefetch(0, 0);
    prefetch(1, 1);

    for (int s = 0; s < NCHUNK; s++) {
        const int stage = s % 3;
        asm volatile("cp.async.wait_group 1;" ::: "memory");
        __syncthreads();
        prefetch(s + 2, (s + 2) % 3);

        const uint32_t cA = smem_base + stage * STG_BYTES;
        const uint32_t cB = cA + 16384;
#pragma unroll
        for (int ks = 0; ks < 4; ks++) {
            uint32_t bf[4][2];
#pragma unroll
            for (int jb = 0; jb < 2; jb++) {
                int row = wn * 32 + jb * 16 + ((lane >> 4) << 3) + (lane & 7);
                int pb  = ks * 2 + ((lane >> 3) & 1);
                uint32_t ad = cB + row * 128 + ((pb ^ (row & 7)) << 4);
                uint32_t t4[4];
                ldmx4(t4, ad);
                bf[jb * 2][0] = t4[0]; bf[jb * 2][1] = t4[1];
                bf[jb * 2 + 1][0] = t4[2]; bf[jb * 2 + 1][1] = t4[3];
            }
#pragma unroll
            for (int i = 0; i < 4; i++) {
                int r0 = wm * 64 + i * 16;
                int row = r0 + (((lane >> 3) & 1) << 3) + (lane & 7);
                int pb  = ks * 2 + ((lane >> 4) & 1);
                uint32_t ad = cA + row * 128 + ((pb ^ (row & 7)) << 4);
                uint32_t af[4];
                ldmx4(af, ad);
#pragma unroll
                for (int j = 0; j < 4; j++)
                    mma16816(c[i][j], af, bf[j]);
            }
        }
    }

#pragma unroll
    for (int i = 0; i < 4; i++) {
        int r = bm + wm * 64 + i * 16 + (lane >> 2);
#pragma unroll
        for (int j = 0; j < 4; j++) {
            int col = bn + wn * 32 + j * 8 + (lane & 3) * 2;
            float b0 = bias[col], b1 = bias[col + 1];
            float2 v0 = make_float2(c[i][j][0] + b0, c[i][j][1] + b1);
            float2 v1 = make_float2(c[i][j][2] + b0, c[i][j][3] + b1);
            if (OUT_MODE == 0) {
                *(float2*)(C + (size_t)r * EE + col)       = v0;
                *(float2*)(C + (size_t)(r + 8) * EE + col) = v1;
            } else {
                int h_ = col >> 6, d0 = col & 63;
                int b_ = r >> 12, n_ = r & 4095;
                size_t base = ((size_t)(b_ * HH + h_) * NSEQ);
                *(float2*)(C + (base + n_)     * DD + d0) = v0;
                *(float2*)(C + (base + n_ + 8) * DD + d0) = v1;
            }
        }
    }
}

// ---------------- ctx_fused v3: dd AND U on tensor cores ----------------
// grid (BHn, NSEG=8), block 256. Each block: 512 n-rows as 32 tiles of 16.
// dd[16,256]: 3-pass mma (proj resident). exp -> kf bf16 hi/lo in smem.
// U[256,64] += kf^T @ V: 3-pass mma via ldmatrix.trans; accum in C fragments.
// ksum via in-register shfl column sums; Sv scalar from fp32 V copy.
// smem: sPTh@0 32K, sPTl@32768 32K, sXh@65536 2K, sXl@67584 2K,
//       sKFh@69632 8K, sKFl@77824 8K, sVh@86016 2K, sVl@88064 2K,
//       sV32@90112 4K, sDiag@94208 64B
#define CTXF_SMEM_BYTES 94272

__global__ __launch_bounds__(256, 2) void ctx_fused(
    const float* __restrict__ K, const float* __restrict__ V,
    const float* __restrict__ proj)
{
    extern __shared__ __align__(128) char csm[];
    const uint32_t smem_base = smem_u32(csm);
    const uint32_t sPTh = smem_base;
    const uint32_t sPTl = smem_base + 32768;
    const uint32_t sXh  = smem_base + 65536;
    const uint32_t sXl  = smem_base + 67584;
    const uint32_t sKFh = smem_base + 69632;
    const uint32_t sKFl = smem_base + 77824;
    const uint32_t sVh  = smem_base + 86016;
    const uint32_t sVl  = smem_base + 88064;
    float* sV32  = (float*)(csm + 90112);
    float* sDiag = (float*)(csm + 94208);
    __shared__ float swm[8];

    const int tid = threadIdx.x;
    const int bh  = blockIdx.x;
    const int seg = blockIdx.y;
    const int lane = tid & 31;
    const int w    = tid >> 5;

    // convert proj -> resident bf16 hi/lo, K-major [m rows][64 d], swizzled
    {
        const float4* pr = (const float4*)(proj + tid * DD);
#pragma unroll
        for (int t = 0; t < 16; t++) {
            float4 v = pr[t];
            ushort h0 = bfu(v.x), h1 = bfu(v.y), h2 = bfu(v.z), h3 = bfu(v.w);
            ushort l0 = bfu(v.x - __bfloat162float(__ushort_as_bfloat16(h0)));
            ushort l1 = bfu(v.y - __bfloat162float(__ushort_as_bfloat16(h1)));
            ushort l2 = bfu(v.z - __bfloat162float(__ushort_as_bfloat16(h2)));
            ushort l3 = bfu(v.w - __bfloat162float(__ushort_as_bfloat16(h3)));
            uint2 hv, lv;
            hv.x = ((uint32_t)h1 << 16) | h0; hv.y = ((uint32_t)h3 << 16) | h2;
            lv.x = ((uint32_t)l1 << 16) | l0; lv.y = ((uint32_t)l3 << 16) | l2;
            uint32_t off = (uint32_t)(tid * 128 + (((t >> 1) ^ (tid & 7)) << 4) + (t & 1) * 8);
            *(uint2*)(csm + off)         = hv;
            *(uint2*)(csm + 32768 + off) = lv;
        }
    }

    float uacc[2][8][4];        // U fragments: [m-tile][d-tile][frag]
#pragma unroll
    for (int i = 0; i < 2; i++)
#pragma unroll
        for (int j = 0; j < 8; j++)
#pragma unroll
            for (int q = 0; q < 4; q++) uacc[i][j][q] = 0.f;
    float kaccv[8];
#pragma unroll
    for (int i = 0; i < 8; i++) kaccv[i] = 0.f;
    float svacc = 0.f;
    float ddmax = -1e30f;

    for (int it = 0; it < 32; it++) {
        const int n0 = seg * 512 + it * 16;
        __syncthreads();   // prior U-mma / Sv reads done (proj ready on it=0)

        // load 16 rows of K (scaled) and V; diag; bf16 hi/lo tiles
        {
            int row = tid >> 4;
            int t   = tid & 15;
            const float* kp = K + ((size_t)bh * NSEQ + n0 + row) * DD + t * 4;
            const float* vp = V + ((size_t)bh * NSEQ + n0 + row) * DD + t * 4;
            float4 kv = *(const float4*)kp;
            float4 vv = *(const float4*)vp;
            kv.x *= SCQ; kv.y *= SCQ; kv.z *= SCQ; kv.w *= SCQ;
            float ssq = kv.x * kv.x + kv.y * kv.y + kv.z * kv.z + kv.w * kv.w;
#pragma unroll
            for (int o = 8; o > 0; o >>= 1) ssq += __shfl_xor_sync(0xffffffffu, ssq, o);
            if (t == 0) sDiag[row] = 0.5f * ssq;

            uint32_t off = (uint32_t)(row * 128 + (((t >> 1) ^ (row & 7)) << 4) + (t & 1) * 8);
            {
                ushort h0 = bfu(kv.x), h1 = bfu(kv.y), h2 = bfu(kv.z), h3 = bfu(kv.w);
                ushort l0 = bfu(kv.x - __bfloat162float(__ushort_as_bfloat16(h0)));
                ushort l1 = bfu(kv.y - __bfloat162float(__ushort_as_bfloat16(h1)));
                ushort l2 = bfu(kv.z - __bfloat162float(__ushort_as_bfloat16(h2)));
                ushort l3 = bfu(kv.w - __bfloat162float(__ushort_as_bfloat16(h3)));
                uint2 hv, lv;
                hv.x = ((uint32_t)h1 << 16) | h0; hv.y = ((uint32_t)h3 << 16) | h2;
                lv.x = ((uint32_t)l1 << 16) | l0; lv.y = ((uint32_t)l3 << 16) | l2;
                *(uint2*)(csm + 65536 + off) = hv;
                *(uint2*)(csm + 67584 + off) = lv;
            }
            {
                ushort h0 = bfu(vv.x), h1 = bfu(vv.y), h2 = bfu(vv.z), h3 = bfu(vv.w);
                ushort l0 = bfu(vv.x - __bfloat162float(__ushort_as_bfloat16(h0)));
                ushort l1 = bfu(vv.y - __bfloat162float(__ushort_as_bfloat16(h1)));
                ushort l2 = bfu(vv.z - __bfloat162float(__ushort_as_bfloat16(h2)));
                ushort l3 = bfu(vv.w - __bfloat162float(__ushort_as_bfloat16(h3)));
                uint2 hv, lv;
                hv.x = ((uint32_t)h1 << 16) | h0; hv.y = ((uint32_t)h3 << 16) | h2;
                lv.x = ((uint32_t)l1 << 16) | l0; lv.y = ((uint32_t)l3 << 16) | l2;
                *(uint2*)(csm + 86016 + off) = hv;
                *(uint2*)(csm + 88064 + off) = lv;
                *(float4*)(sV32 + row * 64 + t * 4) = vv;
            }
        }
        __syncthreads();

        // dd-mma: 3 passes, M=16 (n), N=256 (m; warp slice 32), K=64
        {
            float c[4][4];
#pragma unroll
            for (int j = 0; j < 4; j++)
#pragma unroll
                for (int q = 0; q < 4; q++) c[j][q] = 0.f;

            const uint32_t pASrc[3] = {sXh, sXh, sXl};
            const uint32_t pBSrc[3] = {sPTh, sPTl, sPTh};
#pragma unroll
            for (int ph = 0; ph < 3; ph++) {
                const uint32_t cA = pASrc[ph];
                const uint32_t cB = pBSrc[ph];
#pragma unroll
                for (int ks = 0; ks < 4; ks++) {
                    int rowA = (((lane >> 3) & 1) << 3) + (lane & 7);
                    int pbA  = ks * 2 + ((lane >> 4) & 1);
                    uint32_t adA = cA + rowA * 128 + ((pbA ^ (rowA & 7)) << 4);
                    uint32_t af[4];
                    ldmx4(af, adA);
                    uint32_t bf[4][2];
#pragma unroll
                    for (int jb = 0; jb < 2; jb++) {
                        int rowB = w * 32 + jb * 16 + ((lane >> 4) << 3) + (lane & 7);
                        int pbB  = ks * 2 + ((lane >> 3) & 1);
                        uint32_t adB = cB + rowB * 128 + ((pbB ^ (rowB & 7)) << 4);
                        uint32_t t4[4];
                        ldmx4t_dummy: ;
                        ldmx4(t4, adB);
                        bf[jb * 2][0] = t4[0]; bf[jb * 2][1] = t4[1];
                        bf[jb * 2 + 1][0] = t4[2]; bf[jb * 2 + 1][1] = t4[3];
                    }
#pragma unroll
                    for (int j = 0; j < 4; j++)
                        mma16816(c[j], af, bf[j]);
                }
            }

            // exp -> kf bf16 hi/lo; ksum column partials via shfl; ddmax
            const int r0 = lane >> 2;
            const int mb = w * 32 + (lane & 3) * 2;
            const float dg0 = sDiag[r0];
            const float dg1 = sDiag[r0 + 8];
#pragma unroll
            for (int j = 0; j < 4; j++) {
                int m = mb + j * 8;
                float v0 = c[j][0], v1 = c[j][1], v2 = c[j][2], v3 = c[j][3];
                ddmax = fmaxf(ddmax, fmaxf(fmaxf(v0, v1), fmaxf(v2, v3)));
                float e0 = __expf(v0 - dg0), e1 = __expf(v1 - dg0);
                float e2 = __expf(v2 - dg1), e3 = __expf(v3 - dg1);

                uint32_t off0 = (uint32_t)(r0 * 512 + (((m >> 3) ^ (r0 & 7)) << 4) + (m & 7) * 2);
                uint32_t off1 = off0 + 8 * 512;   // (r0+8)&7 == r0&7, same swizzle
                ushort h0 = bfu(e0), h1 = bfu(e1), h2 = bfu(e2), h3 = bfu(e3);
                *(uint32_t*)(csm + 69632 + off0) = ((uint32_t)h1 << 16) | h0;
                *(uint32_t*)(csm + 69632 + off1) = ((uint32_t)h3 << 16) | h2;
                *(uint32_t*)(csm + 77824 + off0) =
                    ((uint32_t)bfu(e1 - __bfloat162float(__ushort_as_bfloat16(h1))) << 16)
                    | bfu(e0 - __bfloat162float(__ushort_as_bfloat16(h0)));
                *(uint32_t*)(csm + 77824 + off1) =
                    ((uint32_t)bfu(e3 - __bfloat162float(__ushort_as_bfloat16(h3))) << 16)
                    | bfu(e2 - __bfloat162float(__ushort_as_bfloat16(h2)));

                float s0 = e0 + e2, s1 = e1 + e3;
                s0 += __shfl_xor_sync(0xffffffffu, s0, 4);
                s0 += __shfl_xor_sync(0xffffffffu, s0, 8);
                s0 += __shfl_xor_sync(0xffffffffu, s0, 16);
                s1 += __shfl_xor_sync(0xffffffffu, s1, 4);
                s1 += __shfl_xor_sync(0xffffffffu, s1, 8);
                s1 += __shfl_xor_sync(0xffffffffu, s1, 16);
                kaccv[j * 2]     += s0;
                kaccv[j * 2 + 1] += s1;
            }
        }
        __syncthreads();

        // U-mma: 3 passes; A = kf^T (trans), B = V^T (trans); K=16
        {
            const uint32_t pASrc[3] = {sKFh, sKFh, sKFl};
            const uint32_t pBSrc[3] = {sVh, sVl, sVh};
#pragma unroll
            for (int ph = 0; ph < 3; ph++) {
                uint32_t af[2][4];
#pragma unroll
                for (int mt = 0; mt < 2; mt++) {
                    int krow = (((lane >> 4) & 1) << 3) + (lane & 7);
                    int moff = w * 32 + mt * 16 + (((lane >> 3) & 1) << 3);
                    uint32_t ad = pASrc[ph] + krow * 512 + ((((moff >> 3)) ^ (krow & 7)) << 4);
                    ldmx4t(af[mt], ad);
                }
                uint32_t bf[8][2];
#pragma unroll
                for (int g = 0; g < 4; g++) {
                    int krow = (((lane >> 3) & 1) << 3) + (lane & 7);
                    int dch  = g * 2 + ((lane >> 4) & 1);
                    uint32_t ad = pBSrc[ph] + krow * 128 + ((dch ^ (krow & 7)) << 4);
                    uint32_t t4[4];
                    ldmx4t(t4, ad);
                    bf[g * 2][0] = t4[0];     bf[g * 2][1] = t4[1];
                    bf[g * 2 + 1][0] = t4[2]; bf[g * 2 + 1][1] = t4[3];
                }
#pragma unroll
                for (int mt = 0; mt < 2; mt++)
#pragma unroll
                    for (int dt = 0; dt < 8; dt++)
                        mma16816(uacc[mt][dt], af[mt], bf[dt]);
            }
        }

        // Sv partial
        if (tid < 64) {
#pragma unroll
            for (int r = 0; r < 16; r++) svacc += sV32[r * 64 + tid];
        }
    }

    // write partials
    if (lane < 4) {
        float* kp = g_ksump + ((size_t)seg * BHn + bh) * MM;
#pragma unroll
        for (int j = 0; j < 4; j++) {
            int m = w * 32 + lane * 2 + j * 8;
            kp[m]     = kaccv[j * 2];
            kp[m + 1] = kaccv[j * 2 + 1];
        }
    }
    if (tid < 64) g_svp[((size_t)seg * BHn + bh) * DD + tid] = svacc;

    float* cp = g_ctxp + ((size_t)seg * BHn + bh) * MM * DD;
#pragma unroll
    for (int mt = 0; mt < 2; mt++) {
        int r = w * 32 + mt * 16 + (lane >> 2);
#pragma unroll
        for (int dt = 0; dt < 8; dt++) {
            int col = dt * 8 + (lane & 3) * 2;
            *(float2*)(cp + (size_t)r * DD + col) =
                make_float2(uacc[mt][dt][0], uacc[mt][dt][1]);
            *(float2*)(cp + (size_t)(r + 8) * DD + col) =
                make_float2(uacc[mt][dt][2], uacc[mt][dt][3]);
        }
    }

#pragma unroll
    for (int o = 16; o > 0; o >>= 1)
        ddmax = fmaxf(ddmax, __shfl_xor_sync(0xffffffffu, ddmax, o));
    if (lane == 0) swm[w] = ddmax;
    __syncthreads();
    if (tid == 0) {
        float m = swm[0];
#pragma unroll
        for (int i = 1; i < 8; i++) m = fmaxf(m, swm[i]);
        atomicMaxFloat(&g_kstab, m);
    }
}

// ---------------- assemble ctx + ksum from unstabilized partials ----------------
__global__ __launch_bounds__(256) void ctx_reduce_kernel() {
    const float escale = __expf(-g_kstab);
    int i = blockIdx.x * 256 + threadIdx.x;
    if (i < BHn * MM * DD) {
        int bh = i >> 14;
        int d  = i & 63;
        float U = 0.f, Sv = 0.f;
#pragma unroll
        for (int seg = 0; seg < NSEG; seg++) {
            U  += g_ctxp[(size_t)seg * BHn * MM * DD + i];
            Sv += g_svp[((size_t)seg * BHn + bh) * DD + d];
        }
        g_ctx[i] = RATIO * (escale * U + EPSK * Sv);
    }
    if (i < BHn * MM) {
        float T = 0.f;
#pragma unroll
        for (int seg = 0; seg < NSEG; seg++)
            T += g_ksump[(size_t)seg * BHn * MM + i];
        g_ksum[i] = RATIO * (escale * T + EPSK * (float)NSEQ);
    }
}

// ---------------- qf_kernel v2: dd on tensor cores (R12, unchanged) ----------------
#define QF_SMEM_BYTES 71744

__global__ __launch_bounds__(256, 3) void qf_kernel(
    const float* __restrict__ Q, const float* __restrict__ proj,
    __nv_bfloat16* __restrict__ QFh, __nv_bfloat16* __restrict__ QFl,
    float* __restrict__ Dinv)
{
    extern __shared__ __align__(128) char qsm[];
    const uint32_t smem_base = smem_u32(qsm);
    const uint32_t sPTh = smem_base;
    const uint32_t sPTl = smem_base + 32768;
    const uint32_t sXh  = smem_base + 65536;
    const uint32_t sXl  = smem_base + 67584;
    float* sKs   = (float*)(qsm + 69632);
    float* sDiag = (float*)(qsm + 70656);
    float* sMaxP = (float*)(qsm + 70720);
    float* sDpP  = (float*)(qsm + 71232);

    const int tid = threadIdx.x;
    const int bh  = blockIdx.x;
    const int nblk = blockIdx.y * 256;
    const int lane = tid & 31;
    const int w    = tid >> 5;

    {
        const float4* pr = (const float4*)(proj + tid * DD);
#pragma unroll
        for (int t = 0; t < 16; t++) {
            float4 v = pr[t];
            ushort h0 = bfu(v.x), h1 = bfu(v.y), h2 = bfu(v.z), h3 = bfu(v.w);
            ushort l0 = bfu(v.x - __bfloat162float(__ushort_as_bfloat16(h0)));
            ushort l1 = bfu(v.y - __bfloat162float(__ushort_as_bfloat16(h1)));
            ushort l2 = bfu(v.z - __bfloat162float(__ushort_as_bfloat16(h2)));
            ushort l3 = bfu(v.w - __bfloat162float(__ushort_as_bfloat16(h3)));
            uint2 hv, lv;
            hv.x = ((uint32_t)h1 << 16) | h0; hv.y = ((uint32_t)h3 << 16) | h2;
            lv.x = ((uint32_t)l1 << 16) | l0; lv.y = ((uint32_t)l3 << 16) | l2;
            uint32_t off = (uint32_t)(tid * 128 + (((t >> 1) ^ (tid & 7)) << 4) + (t & 1) * 8);
            *(uint2*)(qsm + off)         = hv;
            *(uint2*)(qsm + 32768 + off) = lv;
        }
        sKs[tid] = g_ksum[bh * MM + tid];
    }

    for (int it = 0; it < 16; it++) {
        const int n0 = nblk + it * 16;
        __syncthreads();

        {
            int row = tid >> 4;
            int t   = tid & 15;
            const float* qp = Q + ((size_t)bh * NSEQ + n0 + row) * DD + t * 4;
            float4 kv = *(const float4*)qp;
            kv.x *= SCQ; kv.y *= SCQ; kv.z *= SCQ; kv.w *= SCQ;
            float ssq = kv.x * kv.x + kv.y * kv.y + kv.z * kv.z + kv.w * kv.w;
#pragma unroll
            for (int o = 8; o > 0; o >>= 1) ssq += __shfl_xor_sync(0xffffffffu, ssq, o);
            if (t == 0) sDiag[row] = 0.5f * ssq;

            ushort h0 = bfu(kv.x), h1 = bfu(kv.y), h2 = bfu(kv.z), h3 = bfu(kv.w);
            ushort l0 = bfu(kv.x - __bfloat162float(__ushort_as_bfloat16(h0)));
            ushort l1 = bfu(kv.y - __bfloat162float(__ushort_as_bfloat16(h1)));
            ushort l2 = bfu(kv.z - __bfloat162float(__ushort_as_bfloat16(h2)));
            ushort l3 = bfu(kv.w - __bfloat162float(__ushort_as_bfloat16(h3)));
            uint2 hv, lv;
            hv.x = ((uint32_t)h1 << 16) | h0; hv.y = ((uint32_t)h3 << 16) | h2;
            lv.x = ((uint32_t)l1 << 16) | l0; lv.y = ((uint32_t)l3 << 16) | l2;
            uint32_t off = (uint32_t)(row * 128 + (((t >> 1) ^ (row & 7)) << 4) + (t & 1) * 8);
            *(uint2*)(qsm + 65536 + off) = hv;
            *(uint2*)(qsm + 67584 + off) = lv;
        }
        __syncthreads();

        float c[4][4];
#pragma unroll
        for (int j = 0; j < 4; j++)
#pragma unroll
            for (int q = 0; q < 4; q++) c[j][q] = 0.f;
        {
            const uint32_t pASrc[3] = {sXh, sXh, sXl};
            const uint32_t pBSrc[3] = {sPTh, sPTl, sPTh};
#pragma unroll
            for (int ph = 0; ph < 3; ph++) {
                const uint32_t cA = pASrc[ph];
                const uint32_t cB = pBSrc[ph];
#pragma unroll
                for (int ks = 0; ks < 4; ks++) {
                    int rowA = (((lane >> 3) & 1) << 3) + (lane & 7);
                    int pbA  = ks * 2 + ((lane >> 4) & 1);
                    uint32_t adA = cA + rowA * 128 + ((pbA ^ (rowA & 7)) << 4);
                    uint32_t af[4];
                    ldmx4(af, adA);
                    uint32_t bf[4][2];
#pragma unroll
                    for (int jb = 0; jb < 2; jb++) {
                        int rowB = w * 32 + jb * 16 + ((lane >> 4) << 3) + (lane & 7);
                        int pbB  = ks * 2 + ((lane >> 3) & 1);
                        uint32_t adB = cB + rowB * 128 + ((pbB ^ (rowB & 7)) << 4);
                        uint32_t t4[4];
                        ldmx4(t4, adB);
                        bf[jb * 2][0] = t4[0]; bf[jb * 2][1] = t4[1];
                        bf[jb * 2 + 1][0] = t4[2]; bf[jb * 2 + 1][1] = t4[3];
                    }
#pragma unroll
                    for (int j = 0; j < 4; j++)
                        mma16816(c[j], af, bf[j]);
                }
            }
        }

        const int r0 = lane >> 2;

        {
            float mx0 = -1e30f, mx1 = -1e30f;
#pragma unroll
            for (int j = 0; j < 4; j++) {
                mx0 = fmaxf(mx0, fmaxf(c[j][0], c[j][1]));
                mx1 = fmaxf(mx1, fmaxf(c[j][2], c[j][3]));
            }
            mx0 = fmaxf(mx0, __shfl_xor_sync(0xffffffffu, mx0, 1));
            mx0 = fmaxf(mx0, __shfl_xor_sync(0xffffffffu, mx0, 2));
            mx1 = fmaxf(mx1, __shfl_xor_sync(0xffffffffu, mx1, 1));
            mx1 = fmaxf(mx1, __shfl_xor_sync(0xffffffffu, mx1, 2));
            if ((lane & 3) == 0) {
                sMaxP[w * 16 + r0]     = mx0;
                sMaxP[w * 16 + r0 + 8] = mx1;
            }
        }
        __syncthreads();

        {
            float fmx0 = sMaxP[r0], fmx1 = sMaxP[r0 + 8];
#pragma unroll
            for (int ww = 1; ww < 8; ww++) {
                fmx0 = fmaxf(fmx0, sMaxP[ww * 16 + r0]);
                fmx1 = fmaxf(fmx1, sMaxP[ww * 16 + r0 + 8]);
            }
            const float sub0 = sDiag[r0] + fmx0;
            const float sub1 = sDiag[r0 + 8] + fmx1;
            const int mb = w * 32 + (lane & 3) * 2;
            const size_t baseA = ((size_t)bh * NSEQ + n0 + r0) * MM;
            const size_t baseB = baseA + 8 * MM;
            float dp0 = 0.f, dp1 = 0.f;
#pragma unroll
            for (int j = 0; j < 4; j++) {
                int m = mb + j * 8;
                float q0 = RATIO * (__expf(c[j][0] - sub0) + EPSK);
                float q1 = RATIO * (__expf(c[j][1] - sub0) + EPSK);
                float q2 = RATIO * (__expf(c[j][2] - sub1) + EPSK);
                float q3 = RATIO * (__expf(c[j][3] - sub1) + EPSK);
                dp0 += q0 * sKs[m] + q1 * sKs[m + 1];
                dp1 += q2 * sKs[m] + q3 * sKs[m + 1];
                ushort h0 = bfu(q0), h1 = bfu(q1), h2 = bfu(q2), h3 = bfu(q3);
                uint32_t hv0 = ((uint32_t)h1 << 16) | h0;
                uint32_t hv1 = ((uint32_t)h3 << 16) | h2;
                uint32_t lv0 = ((uint32_t)bfu(q1 - __bfloat162float(__ushort_as_bfloat16(h1))) << 16)
                             | bfu(q0 - __bfloat162float(__ushort_as_bfloat16(h0)));
                uint32_t lv1 = ((uint32_t)bfu(q3 - __bfloat162float(__ushort_as_bfloat16(h3))) << 16)
                             | bfu(q2 - __bfloat162float(__ushort_as_bfloat16(h2)));
                *(uint32_t*)(QFh + baseA + m) = hv0;
                *(uint32_t*)(QFl + baseA + m) = lv0;
                *(uint32_t*)(QFh + baseB + m) = hv1;
                *(uint32_t*)(QFl + baseB + m) = lv1;
            }
            dp0 += __shfl_xor_sync(0xffffffffu, dp0, 1);
            dp0 += __shfl_xor_sync(0xffffffffu, dp0, 2);
            dp1 += __shfl_xor_sync(0xffffffffu, dp1, 1);
            dp1 += __shfl_xor_sync(0xffffffffu, dp1, 2);
            if ((lane & 3) == 0) {
                sDpP[w * 16 + r0]     = dp0;
                sDpP[w * 16 + r0 + 8] = dp1;
            }
        }
        __syncthreads();

        if (tid < 16) {
            float s = sDpP[tid];
#pragma unroll
            for (int ww = 1; ww < 8; ww++) s += sDpP[ww * 16 + tid];
            Dinv[(size_t)bh * NSEQ + n0 + tid] = 1.f / s;
        }
    }
}

// ---------------- yv_gemm (R9, unchanged) ----------------
#define YV_NCHUNK 12
#define YV_ASTG  16384

__global__ __launch_bounds__(256, 2) void yv_gemm(
    const __nv_bfloat16* __restrict__ QFh, const __nv_bfloat16* __restrict__ QFl,
    __nv_bfloat16* __restrict__ OutH, __nv_bfloat16* __restrict__ OutL)
{
    extern __shared__ __align__(128) char gsm[];
    const uint32_t smem_base = smem_u32(gsm);
    const uint32_t sBH = smem_base + 49152;
    const uint32_t sBL = smem_base + 81920;

    const int tid  = threadIdx.x;
    const int lane = tid & 31;
    const int wid  = tid >> 5;
    const int wm   = wid & 1;
    const int wn   = wid >> 1;
    const int bh   = blockIdx.y;
    const int bm   = blockIdx.x * 128;
    const int b_   = bh >> 4;
    const int h_   = bh & 15;

    {
        const float* cbase = g_ctx + (size_t)bh * MM * DD;
#pragma unroll
        for (int t = 0; t < 64; t++) {
            int e = t * 256 + tid;
            int m = e >> 6, d = e & 63;
            float val = cbase[e];
            __nv_bfloat16 h = __float2bfloat16(val);
            __nv_bfloat16 l = __float2bfloat16(val - __bfloat162float(h));
            int mc = m & 63;
            uint32_t off = (uint32_t)((m >> 6) * 8192 + d * 128 + (((mc >> 3) ^ (d & 7)) << 4) + (mc & 7) * 2);
            *(ushort*)((char*)gsm + 49152 + off) = __bfloat16_as_ushort(h);
            *(ushort*)((char*)gsm + 81920 + off) = __bfloat16_as_ushort(l);
        }
    }

    const __nv_bfloat16* pA[3] = {QFh, QFh, QFl};

    float c[4][2][4];
#pragma unroll
    for (int i = 0; i < 4; i++)
#pragma unroll
        for (int j = 0; j < 2; j++)
#pragma unroll
            for (int q = 0; q < 4; q++) c[i][j][q] = 0.f;

    auto prefetchA = [&](int s, int stage) {
        if (s < YV_NCHUNK) {
            const int ph = s >> 2;
            const int kk = (s & 3) << 6;
            const __nv_bfloat16* gA = pA[ph] + (size_t)bh * NSEQ * MM;
            const uint32_t aB = smem_base + stage * YV_ASTG;
#pragma unroll
            for (int it = 0; it < 4; it++) {
                int idx = it * 256 + tid;
                int row = idx >> 3;
                int pb  = idx & 7;
                uint32_t doff = row * 128 + ((pb ^ (row & 7)) << 4);
                const void* srcA = gA + (size_t)(bm + row) * MM + kk + pb * 8;
                asm volatile("cp.async.cg.shared.global [%0], [%1], 16;" :: "r"(aB + doff), "l"(srcA));
            }
        }
        asm volatile("cp.async.commit_group;" ::: "memory");
    };

    prefetchA(0, 0);
    prefetchA(1, 1);
    __syncthreads();

    for (int s = 0; s < YV_NCHUNK; s++) {
        const int stage = s % 3;
        asm volatile("cp.async.wait_group 1;" ::: "memory");
        __syncthreads();
        prefetchA(s + 2, (s + 2) % 3);

        const uint32_t cA = smem_base + stage * YV_ASTG;
        const int ph = s >> 2;
        const uint32_t cBbase = (ph == 1) ? sBL : sBH;
        const uint32_t cB = cBbase + (uint32_t)((s & 3) * 8192);

#pragma unroll
        for (int ks = 0; ks < 4; ks++) {
            uint32_t bf[2][2];
            {
                int row = wn * 16 + ((lane >> 4) << 3) + (lane & 7);
                int pb  = ks * 2 + ((lane >> 3) & 1);
                uint32_t ad = cB + row * 128 + ((pb ^ (row & 7)) << 4);
                uint32_t t4[4];
                ldmx4(t4, ad);
                bf[0][0] = t4[0]; bf[0][1] = t4[1];
                bf[1][0] = t4[2]; bf[1][1] = t4[3];
            }
#pragma unroll
            for (int i = 0; i < 4; i++) {
                int r0 = wm * 64 + i * 16;
                int row = r0 + (((lane >> 3) & 1) << 3) + (lane & 7);
                int pb  = ks * 2 + ((lane >> 4) & 1);
                uint32_t ad = cA + row * 128 + ((pb ^ (row & 7)) << 4);
                uint32_t af[4];
                ldmx4(af, ad);
#pragma unroll
                for (int j = 0; j < 2; j++)
                    mma16816(c[i][j], af, bf[j]);
            }
        }
        __syncthreads();
    }

#pragma unroll
    for (int i = 0; i < 4; i++) {
        int rl = wm * 64 + i * 16 + (lane >> 2);
        int nA = bm + rl;
        int nB = nA + 8;
        float dA = g_dinv[(size_t)bh * NSEQ + nA];
        float dB = g_dinv[(size_t)bh * NSEQ + nB];
#pragma unroll
        for (int j = 0; j < 2; j++) {
            int col = wn * 16 + j * 8 + (lane & 3) * 2;
            float vA0 = c[i][j][0] * dA, vA1 = c[i][j][1] * dA;
            float vB0 = c[i][j][2] * dB, vB1 = c[i][j][3] * dB;
            __nv_bfloat16 hA0 = __float2bfloat16(vA0), hA1 = __float2bfloat16(vA1);
            __nv_bfloat16 hB0 = __float2bfloat16(vB0), hB1 = __float2bfloat16(vB1);
            uint32_t hvA = ((uint32_t)__bfloat16_as_ushort(hA1) << 16) | __bfloat16_as_ushort(hA0);
            uint32_t lvA = ((uint32_t)__bfloat16_as_ushort(__float2bfloat16(vA1 - __bfloat162float(hA1))) << 16)
                         | __bfloat16_as_ushort(__float2bfloat16(vA0 - __bfloat162float(hA0)));
            uint32_t hvB = ((uint32_t)__bfloat16_as_ushort(hB1) << 16) | __bfloat16_as_ushort(hB0);
            uint32_t lvB = ((uint32_t)__bfloat16_as_ushort(__float2bfloat16(vB1 - __bfloat162float(hB1))) << 16)
                         | __bfloat16_as_ushort(__float2bfloat16(vB0 - __bfloat162float(hB0)));
            size_t idxA = ((size_t)(b_ * NSEQ + nA)) * EE + h_ * DD + col;
            size_t idxB = ((size_t)(b_ * NSEQ + nB)) * EE + h_ * DD + col;
            *(uint32_t*)(OutH + idxA) = hvA;
            *(uint32_t*)(OutL + idxA) = lvA;
            *(uint32_t*)(OutH + idxB) = hvB;
            *(uint32_t*)(OutL + idxB) = lvB;
        }
    }
}

// ---------------- launch ----------------
extern "C" void kernel_launch(void* const* d_in, const int* in_sizes, int n_in,
                              void* d_out, int out_size) {
    const float* x    = (const float*)d_in[0];
    const float* Wq   = (const float*)d_in[1];
    const float* bq   = (const float*)d_in[2];
    const float* Wk   = (const float*)d_in[3];
    const float* bk   = (const float*)d_in[4];
    const float* Wv   = (const float*)d_in[5];
    const float* bv   = (const float*)d_in[6];
    const float* Wo   = (const float*)d_in[7];
    const float* bo   = (const float*)d_in[8];
    const float* proj = (const float*)d_in[9];
    float* out = (float*)d_out;

    float *pq, *pk, *pv, *pdinv;
    __nv_bfloat16 *pah, *pal, *pwh, *pwl, *pqfh, *pqfl;
    cudaGetSymbolAddress((void**)&pq,   g_q);
    cudaGetSymbolAddress((void**)&pk,   g_k);
    cudaGetSymbolAddress((void**)&pv,   g_v);
    cudaGetSymbolAddress((void**)&pdinv, g_dinv);
    cudaGetSymbolAddress((void**)&pah,  g_ah);
    cudaGetSymbolAddress((void**)&pal,  g_al);
    cudaGetSymbolAddress((void**)&pwh,  g_wh);
    cudaGetSymbolAddress((void**)&pwl,  g_wl);
    cudaGetSymbolAddress((void**)&pqfh, g_qfh);
    cudaGetSymbolAddress((void**)&pqfl, g_qfl);

    const int GEMM_SMEM = 3 * STG_BYTES;
    const int YV_SMEM   = 3 * YV_ASTG + 2 * 32768;
    cudaFuncSetAttribute(gemm_mma<0>, cudaFuncAttributeMaxDynamicSharedMemorySize, GEMM_SMEM);
    cudaFuncSetAttribute(gemm_mma<1>, cudaFuncAttributeMaxDynamicSharedMemorySize, GEMM_SMEM);
    cudaFuncSetAttribute(ctx_fused,  cudaFuncAttributeMaxDynamicSharedMemorySize, CTXF_SMEM_BYTES);
    cudaFuncSetAttribute(qf_kernel,  cudaFuncAttributeMaxDynamicSharedMemorySize, QF_SMEM_BYTES);
    cudaFuncSetAttribute(yv_gemm,    cudaFuncAttributeMaxDynamicSharedMemorySize, YV_SMEM);

    dim3 gg(EE / 128, TT / 128);

    init_kernel<<<1, 32>>>();

    split_kernel<<<2048, 256>>>(x, pah, pal, TT * EE / 4);

    split_kernel<<<512, 256>>>(Wq, pwh, pwl, EE * EE / 4);
    gemm_mma<1><<<gg, 256, GEMM_SMEM>>>(pah, pal, pwh, pwl, bq, pq);
    split_kernel<<<512, 256>>>(Wk, pwh, pwl, EE * EE / 4);
    gemm_mma<1><<<gg, 256, GEMM_SMEM>>>(pah, pal, pwh, pwl, bk, pk);
    split_kernel<<<512, 256>>>(Wv, pwh, pwl, EE * EE / 4);
    gemm_mma<1><<<gg, 256, GEMM_SMEM>>>(pah, pal, pwh, pwl, bv, pv);

    ctx_fused<<<dim3(BHn, NSEG), 256, CTXF_SMEM_BYTES>>>(pk, pv, proj);
    ctx_reduce_kernel<<<(BHn * MM * DD + 255) / 256, 256>>>();

    qf_kernel<<<dim3(BHn, 16), 256, QF_SMEM_BYTES>>>(pq, proj, pqfh, pqfl, pdinv);

    yv_gemm<<<dim3(NSEQ / 128, BHn), 256, YV_SMEM>>>(pqfh, pqfl, pah, pal);

    split_kernel<<<512, 256>>>(Wo, pwh, pwl, EE * EE / 4);
    gemm_mma<0><<<gg, 256, GEMM_SMEM>>>(pah, pal, pwh, pwl, bo, out);
}

// round 14
// speedup vs baseline: 1.2476x; 1.0229x over previous
#include <cuda_runtime.h>
#include <cuda_bf16.h>
#include <math.h>
#include <stdint.h>

// Problem constants
#define BB   4
#define NSEQ 4096
#define EE   1024
#define HH   16
#define DD   64
#define MM   256
#define TT   (BB*NSEQ)     // 16384
#define BHn  (BB*HH)       // 64
#define NSEG 8

#define RATIO 0.0625f
#define EPSK  1e-4f
#define SCQ   0.3535533905932738f   // 64^-0.25

// ---------------- device scratch ----------------
__device__ float g_q[(size_t)BHn*NSEQ*DD];
__device__ float g_k[(size_t)BHn*NSEQ*DD];
__device__ float g_v[(size_t)BHn*NSEQ*DD];
__device__ float g_ksum[BHn*MM];
__device__ float g_ksump[(size_t)NSEG*BHn*MM];
__device__ float g_svp[(size_t)NSEG*BHn*DD];
__device__ float g_ctxp[(size_t)NSEG*BHn*MM*DD];
__device__ float g_ctx[BHn*MM*DD];
__device__ float g_dinv[(size_t)BHn*NSEQ];
__device__ float g_kstab;
__device__ __nv_bfloat16 g_ah[(size_t)TT*EE];
__device__ __nv_bfloat16 g_al[(size_t)TT*EE];
__device__ __nv_bfloat16 g_wh[(size_t)EE*EE];
__device__ __nv_bfloat16 g_wl[(size_t)EE*EE];
__device__ __nv_bfloat16 g_qfh[(size_t)BHn*NSEQ*MM];
__device__ __nv_bfloat16 g_qfl[(size_t)BHn*NSEQ*MM];

// ---------------- helpers ----------------
__device__ __forceinline__ void atomicMaxFloat(float* addr, float v) {
    if (v >= 0.f) atomicMax((int*)addr, __float_as_int(v));
    else          atomicMin((unsigned int*)addr, __float_as_uint(v));
}

__global__ void init_kernel() {
    if (blockIdx.x == 0 && threadIdx.x == 0) g_kstab = -INFINITY;
}

__device__ __forceinline__ uint32_t smem_u32(const void* p) {
    uint32_t a;
    asm("{ .reg .u64 t; cvta.to.shared.u64 t, %1; cvt.u32.u64 %0, t; }" : "=r"(a) : "l"(p));
    return a;
}

__device__ __forceinline__ void mma16816(float* c, const uint32_t* a, const uint32_t* b) {
    asm volatile(
        "mma.sync.aligned.m16n8k16.row.col.f32.bf16.bf16.f32 "
        "{%0,%1,%2,%3},{%4,%5,%6,%7},{%8,%9},{%0,%1,%2,%3};"
        : "+f"(c[0]), "+f"(c[1]), "+f"(c[2]), "+f"(c[3])
        : "r"(a[0]), "r"(a[1]), "r"(a[2]), "r"(a[3]), "r"(b[0]), "r"(b[1]));
}

__device__ __forceinline__ void ldmx4(uint32_t* r, uint32_t addr) {
    asm volatile("ldmatrix.sync.aligned.m8n8.x4.shared.b16 {%0,%1,%2,%3}, [%4];"
        : "=r"(r[0]), "=r"(r[1]), "=r"(r[2]), "=r"(r[3]) : "r"(addr));
}
__device__ __forceinline__ void ldmx4t(uint32_t* r, uint32_t addr) {
    asm volatile("ldmatrix.sync.aligned.m8n8.x4.trans.shared.b16 {%0,%1,%2,%3}, [%4];"
        : "=r"(r[0]), "=r"(r[1]), "=r"(r[2]), "=r"(r[3]) : "r"(addr));
}

// packed fp32x2
__device__ __forceinline__ void fma2(unsigned long long& d, unsigned long long a, unsigned long long b) {
    asm("fma.rn.f32x2 %0, %1, %2, %0;" : "+l"(d) : "l"(a), "l"(b));
}
__device__ __forceinline__ unsigned long long pack2(float x) {
    unsigned long long r;
    asm("mov.b64 %0, {%1, %1};" : "=l"(r) : "f"(x));
    return r;
}
__device__ __forceinline__ float2 unpack2(unsigned long long v) {
    float2 f;
    asm("mov.b64 {%0, %1}, %2;" : "=f"(f.x), "=f"(f.y) : "l"(v));
    return f;
}
__device__ __forceinline__ float f4c(const float4& v, int j) {
    return j == 0 ? v.x : j == 1 ? v.y : j == 2 ? v.z : v.w;
}
__device__ __forceinline__ ushort bfu(float x) {
    return __bfloat16_as_ushort(__float2bfloat16(x));
}

// ---------------- fp32 -> bf16 hi/lo split ----------------
__global__ __launch_bounds__(256) void split_kernel(
    const float* __restrict__ src, __nv_bfloat16* __restrict__ hi,
    __nv_bfloat16* __restrict__ lo, int n4)
{
    const float4* s4 = (const float4*)src;
    uint2* h2 = (uint2*)hi;
    uint2* l2 = (uint2*)lo;
    for (int i = blockIdx.x * 256 + threadIdx.x; i < n4; i += gridDim.x * 256) {
        float4 v = s4[i];
        __nv_bfloat16 h0 = __float2bfloat16(v.x);
        __nv_bfloat16 h1 = __float2bfloat16(v.y);
        __nv_bfloat16 h2b = __float2bfloat16(v.z);
        __nv_bfloat16 h3 = __float2bfloat16(v.w);
        __nv_bfloat16 l0 = __float2bfloat16(v.x - __bfloat162float(h0));
        __nv_bfloat16 l1 = __float2bfloat16(v.y - __bfloat162float(h1));
        __nv_bfloat16 l2b = __float2bfloat16(v.z - __bfloat162float(h2b));
        __nv_bfloat16 l3 = __float2bfloat16(v.w - __bfloat162float(h3));
        uint2 hv, lv;
        hv.x = ((uint32_t)__bfloat16_as_ushort(h1) << 16) | __bfloat16_as_ushort(h0);
        hv.y = ((uint32_t)__bfloat16_as_ushort(h3) << 16) | __bfloat16_as_ushort(h2b);
        lv.x = ((uint32_t)__bfloat16_as_ushort(l1) << 16) | __bfloat16_as_ushort(l0);
        lv.y = ((uint32_t)__bfloat16_as_ushort(l3) << 16) | __bfloat16_as_ushort(l2b);
        h2[i] = hv;
        l2[i] = lv;
    }
}

// ---------------- bf16-split mma.sync GEMM: K-chunk 64, 3-stage, ldmatrix ----------------
// Change this round: __launch_bounds__(256, 2) -> ptxas reg budget 128 (was 98),
// enabling deeper LDSM/HMMA software pipelining. Occupancy unchanged (2 CTA/SM).
#define NCHUNK 48
#define STG_BYTES 32768

template<int OUT_MODE>
__global__ __launch_bounds__(256, 2) void gemm_mma(
    const __nv_bfloat16* __restrict__ Ah, const __nv_bfloat16* __restrict__ Al,
    const __nv_bfloat16* __restrict__ Wh, const __nv_bfloat16* __restrict__ Wl,
    const float* __restrict__ bias, float* __restrict__ C)
{
    extern __shared__ __align__(128) char gsm[];

    const int tid  = threadIdx.x;
    const int lane = tid & 31;
    const int wid  = tid >> 5;
    const int wm   = wid & 1;
    const int wn   = wid >> 1;
    const int bm   = blockIdx.y * 128;
    const int bn   = blockIdx.x * 128;

    const __nv_bfloat16* pA[3] = {Ah, Ah, Al};
    const __nv_bfloat16* pB[3] = {Wh, Wl, Wh};

    float c[4][4][4];
#pragma unroll
    for (int i = 0; i < 4; i++)
#pragma unroll
        for (int j = 0; j < 4; j++)
#pragma unroll
            for (int q = 0; q < 4; q++) c[i][j][q] = 0.f;

    const uint32_t smem_base = smem_u32(gsm);

    auto prefetch = [&](int s, int stage) {
        if (s < NCHUNK) {
            const int ph = s >> 4;
            const int kk = (s & 15) << 6;
            const __nv_bfloat16* gA = pA[ph];
            const __nv_bfloat16* gB = pB[ph];
            const uint32_t aB = smem_base + stage * STG_BYTES;
            const uint32_t bB = aB + 16384;
#pragma unroll
            for (int it = 0; it < 4; it++) {
                int idx = it * 256 + tid;
                int row = idx >> 3;
                int pb  = idx & 7;
                uint32_t doff = row * 128 + ((pb ^ (row & 7)) << 4);
                const void* srcA = gA + (size_t)(bm + row) * EE + kk + pb * 8;
                const void* srcB = gB + (size_t)(bn + row) * EE + kk + pb * 8;
                asm volatile("cp.async.cg.shared.global [%0], [%1], 16;" :: "r"(aB + doff), "l"(srcA));
                asm volatile("cp.async.cg.shared.global [%0], [%1], 16;" :: "r"(bB + doff), "l"(srcB));
            }
        }
        asm volatile("cp.async.commit_group;" ::: "memory");
    };

    prefetch(0, 0);
    prefetch(1, 1);

    for (int s = 0; s < NCHUNK; s++) {
        const int stage = s % 3;
        asm volatile("cp.async.wait_group 1;" ::: "memory");
        __syncthreads();
        prefetch(s + 2, (s + 2) % 3);

        const uint32_t cA = smem_base + stage * STG_BYTES;
        const uint32_t cB = cA + 16384;
#pragma unroll
        for (int ks = 0; ks < 4; ks++) {
            uint32_t bf[4][2];
#pragma unroll
            for (int jb = 0; jb < 2; jb++) {
                int row = wn * 32 + jb * 16 + ((lane >> 4) << 3) + (lane & 7);
                int pb  = ks * 2 + ((lane >> 3) & 1);
                uint32_t ad = cB + row * 128 + ((pb ^ (row & 7)) << 4);
                uint32_t t4[4];
                ldmx4(t4, ad);
                bf[jb * 2][0] = t4[0]; bf[jb * 2][1] = t4[1];
                bf[jb * 2 + 1][0] = t4[2]; bf[jb * 2 + 1][1] = t4[3];
            }
#pragma unroll
            for (int i = 0; i < 4; i++) {
                int r0 = wm * 64 + i * 16;
                int row = r0 + (((lane >> 3) & 1) << 3) + (lane & 7);
                int pb  = ks * 2 + ((lane >> 4) & 1);
                uint32_t ad = cA + row * 128 + ((pb ^ (row & 7)) << 4);
                uint32_t af[4];
                ldmx4(af, ad);
#pragma unroll
                for (int j = 0; j < 4; j++)
                    mma16816(c[i][j], af, bf[j]);
            }
        }
    }

#pragma unroll
    for (int i = 0; i < 4; i++) {
        int r = bm + wm * 64 + i * 16 + (lane >> 2);
#pragma unroll
        for (int j = 0; j < 4; j++) {
            int col = bn + wn * 32 + j * 8 + (lane & 3) * 2;
            float b0 = bias[col], b1 = bias[col + 1];
            float2 v0 = make_float2(c[i][j][0] + b0, c[i][j][1] + b1);
            float2 v1 = make_float2(c[i][j][2] + b0, c[i][j][3] + b1);
            if (OUT_MODE == 0) {
                *(float2*)(C + (size_t)r * EE + col)       = v0;
                *(float2*)(C + (size_t)(r + 8) * EE + col) = v1;
            } else {
                int h_ = col >> 6, d0 = col & 63;
                int b_ = r >> 12, n_ = r & 4095;
                size_t base = ((size_t)(b_ * HH + h_) * NSEQ);
                *(float2*)(C + (base + n_)     * DD + d0) = v0;
                *(float2*)(C + (base + n_ + 8) * DD + d0) = v1;
            }
        }
    }
}

// ---------------- ctx_fused v3: dd AND U on tensor cores (R13, unchanged) ----------------
#define CTXF_SMEM_BYTES 94272

__global__ __launch_bounds__(256, 2) void ctx_fused(
    const float* __restrict__ K, const float* __restrict__ V,
    const float* __restrict__ proj)
{
    extern __shared__ __align__(128) char csm[];
    const uint32_t smem_base = smem_u32(csm);
    const uint32_t sPTh = smem_base;
    const uint32_t sPTl = smem_base + 32768;
    const uint32_t sXh  = smem_base + 65536;
    const uint32_t sXl  = smem_base + 67584;
    const uint32_t sKFh = smem_base + 69632;
    const uint32_t sKFl = smem_base + 77824;
    const uint32_t sVh  = smem_base + 86016;
    const uint32_t sVl  = smem_base + 88064;
    float* sV32  = (float*)(csm + 90112);
    float* sDiag = (float*)(csm + 94208);
    __shared__ float swm[8];

    const int tid = threadIdx.x;
    const int bh  = blockIdx.x;
    const int seg = blockIdx.y;
    const int lane = tid & 31;
    const int w    = tid >> 5;

    {
        const float4* pr = (const float4*)(proj + tid * DD);
#pragma unroll
        for (int t = 0; t < 16; t++) {
            float4 v = pr[t];
            ushort h0 = bfu(v.x), h1 = bfu(v.y), h2 = bfu(v.z), h3 = bfu(v.w);
            ushort l0 = bfu(v.x - __bfloat162float(__ushort_as_bfloat16(h0)));
            ushort l1 = bfu(v.y - __bfloat162float(__ushort_as_bfloat16(h1)));
            ushort l2 = bfu(v.z - __bfloat162float(__ushort_as_bfloat16(h2)));
            ushort l3 = bfu(v.w - __bfloat162float(__ushort_as_bfloat16(h3)));
            uint2 hv, lv;
            hv.x = ((uint32_t)h1 << 16) | h0; hv.y = ((uint32_t)h3 << 16) | h2;
            lv.x = ((uint32_t)l1 << 16) | l0; lv.y = ((uint32_t)l3 << 16) | l2;
            uint32_t off = (uint32_t)(tid * 128 + (((t >> 1) ^ (tid & 7)) << 4) + (t & 1) * 8);
            *(uint2*)(csm + off)         = hv;
            *(uint2*)(csm + 32768 + off) = lv;
        }
    }

    float uacc[2][8][4];
#pragma unroll
    for (int i = 0; i < 2; i++)
#pragma unroll
        for (int j = 0; j < 8; j++)
#pragma unroll
            for (int q = 0; q < 4; q++) uacc[i][j][q] = 0.f;
    float kaccv[8];
#pragma unroll
    for (int i = 0; i < 8; i++) kaccv[i] = 0.f;
    float svacc = 0.f;
    float ddmax = -1e30f;

    for (int it = 0; it < 32; it++) {
        const int n0 = seg * 512 + it * 16;
        __syncthreads();

        {
            int row = tid >> 4;
            int t   = tid & 15;
            const float* kp = K + ((size_t)bh * NSEQ + n0 + row) * DD + t * 4;
            const float* vp = V + ((size_t)bh * NSEQ + n0 + row) * DD + t * 4;
            float4 kv = *(const float4*)kp;
            float4 vv = *(const float4*)vp;
            kv.x *= SCQ; kv.y *= SCQ; kv.z *= SCQ; kv.w *= SCQ;
            float ssq = kv.x * kv.x + kv.y * kv.y + kv.z * kv.z + kv.w * kv.w;
#pragma unroll
            for (int o = 8; o > 0; o >>= 1) ssq += __shfl_xor_sync(0xffffffffu, ssq, o);
            if (t == 0) sDiag[row] = 0.5f * ssq;

            uint32_t off = (uint32_t)(row * 128 + (((t >> 1) ^ (row & 7)) << 4) + (t & 1) * 8);
            {
                ushort h0 = bfu(kv.x), h1 = bfu(kv.y), h2 = bfu(kv.z), h3 = bfu(kv.w);
                ushort l0 = bfu(kv.x - __bfloat162float(__ushort_as_bfloat16(h0)));
                ushort l1 = bfu(kv.y - __bfloat162float(__ushort_as_bfloat16(h1)));
                ushort l2 = bfu(kv.z - __bfloat162float(__ushort_as_bfloat16(h2)));
                ushort l3 = bfu(kv.w - __bfloat162float(__ushort_as_bfloat16(h3)));
                uint2 hv, lv;
                hv.x = ((uint32_t)h1 << 16) | h0; hv.y = ((uint32_t)h3 << 16) | h2;
                lv.x = ((uint32_t)l1 << 16) | l0; lv.y = ((uint32_t)l3 << 16) | l2;
                *(uint2*)(csm + 65536 + off) = hv;
                *(uint2*)(csm + 67584 + off) = lv;
            }
            {
                ushort h0 = bfu(vv.x), h1 = bfu(vv.y), h2 = bfu(vv.z), h3 = bfu(vv.w);
                ushort l0 = bfu(vv.x - __bfloat162float(__ushort_as_bfloat16(h0)));
                ushort l1 = bfu(vv.y - __bfloat162float(__ushort_as_bfloat16(h1)));
                ushort l2 = bfu(vv.z - __bfloat162float(__ushort_as_bfloat16(h2)));
                ushort l3 = bfu(vv.w - __bfloat162float(__ushort_as_bfloat16(h3)));
                uint2 hv, lv;
                hv.x = ((uint32_t)h1 << 16) | h0; hv.y = ((uint32_t)h3 << 16) | h2;
                lv.x = ((uint32_t)l1 << 16) | l0; lv.y = ((uint32_t)l3 << 16) | l2;
                *(uint2*)(csm + 86016 + off) = hv;
                *(uint2*)(csm + 88064 + off) = lv;
                *(float4*)(sV32 + row * 64 + t * 4) = vv;
            }
        }
        __syncthreads();

        {
            float c[4][4];
#pragma unroll
            for (int j = 0; j < 4; j++)
#pragma unroll
                for (int q = 0; q < 4; q++) c[j][q] = 0.f;

            const uint32_t pASrc[3] = {sXh, sXh, sXl};
            const uint32_t pBSrc[3] = {sPTh, sPTl, sPTh};
#pragma unroll
            for (int ph = 0; ph < 3; ph++) {
                const uint32_t cA = pASrc[ph];
                const uint32_t cB = pBSrc[ph];
#pragma unroll
                for (int ks = 0; ks < 4; ks++) {
                    int rowA = (((lane >> 3) & 1) << 3) + (lane & 7);
                    int pbA  = ks * 2 + ((lane >> 4) & 1);
                    uint32_t adA = cA + rowA * 128 + ((pbA ^ (rowA & 7)) << 4);
                    uint32_t af[4];
                    ldmx4(af, adA);
                    uint32_t bf[4][2];
#pragma unroll
                    for (int jb = 0; jb < 2; jb++) {
                        int rowB = w * 32 + jb * 16 + ((lane >> 4) << 3) + (lane & 7);
                        int pbB  = ks * 2 + ((lane >> 3) & 1);
                        uint32_t adB = cB + rowB * 128 + ((pbB ^ (rowB & 7)) << 4);
                        uint32_t t4[4];
                        ldmx4(t4, adB);
                        bf[jb * 2][0] = t4[0]; bf[jb * 2][1] = t4[1];
                        bf[jb * 2 + 1][0] = t4[2]; bf[jb * 2 + 1][1] = t4[3];
                    }
#pragma unroll
                    for (int j = 0; j < 4; j++)
                        mma16816(c[j], af, bf[j]);
                }
            }

            const int r0 = lane >> 2;
            const int mb = w * 32 + (lane & 3) * 2;
            const float dg0 = sDiag[r0];
            const float dg1 = sDiag[r0 + 8];
#pragma unroll
            for (int j = 0; j < 4; j++) {
                int m = mb + j * 8;
                float v0 = c[j][0], v1 = c[j][1], v2 = c[j][2], v3 = c[j][3];
                ddmax = fmaxf(ddmax, fmaxf(fmaxf(v0, v1), fmaxf(v2, v3)));
                float e0 = __expf(v0 - dg0), e1 = __expf(v1 - dg0);
                float e2 = __expf(v2 - dg1), e3 = __expf(v3 - dg1);

                uint32_t off0 = (uint32_t)(r0 * 512 + (((m >> 3) ^ (r0 & 7)) << 4) + (m & 7) * 2);
                uint32_t off1 = off0 + 8 * 512;
                ushort h0 = bfu(e0), h1 = bfu(e1), h2 = bfu(e2), h3 = bfu(e3);
                *(uint32_t*)(csm + 69632 + off0) = ((uint32_t)h1 << 16) | h0;
                *(uint32_t*)(csm + 69632 + off1) = ((uint32_t)h3 << 16) | h2;
                *(uint32_t*)(csm + 77824 + off0) =
                    ((uint32_t)bfu(e1 - __bfloat162float(__ushort_as_bfloat16(h1))) << 16)
                    | bfu(e0 - __bfloat162float(__ushort_as_bfloat16(h0)));
                *(uint32_t*)(csm + 77824 + off1) =
                    ((uint32_t)bfu(e3 - __bfloat162float(__ushort_as_bfloat16(h3))) << 16)
                    | bfu(e2 - __bfloat162float(__ushort_as_bfloat16(h2)));

                float s0 = e0 + e2, s1 = e1 + e3;
                s0 += __shfl_xor_sync(0xffffffffu, s0, 4);
                s0 += __shfl_xor_sync(0xffffffffu, s0, 8);
                s0 += __shfl_xor_sync(0xffffffffu, s0, 16);
                s1 += __shfl_xor_sync(0xffffffffu, s1, 4);
                s1 += __shfl_xor_sync(0xffffffffu, s1, 8);
                s1 += __shfl_xor_sync(0xffffffffu, s1, 16);
                kaccv[j * 2]     += s0;
                kaccv[j * 2 + 1] += s1;
            }
        }
        __syncthreads();

        {
            const uint32_t pASrc[3] = {sKFh, sKFh, sKFl};
            const uint32_t pBSrc[3] = {sVh, sVl, sVh};
#pragma unroll
            for (int ph = 0; ph < 3; ph++) {
                uint32_t af[2][4];
#pragma unroll
                for (int mt = 0; mt < 2; mt++) {
                    int krow = (((lane >> 4) & 1) << 3) + (lane & 7);
                    int moff = w * 32 + mt * 16 + (((lane >> 3) & 1) << 3);
                    uint32_t ad = pASrc[ph] + krow * 512 + ((((moff >> 3)) ^ (krow & 7)) << 4);
                    ldmx4t(af[mt], ad);
                }
                uint32_t bf[8][2];
#pragma unroll
                for (int g = 0; g < 4; g++) {
                    int krow = (((lane >> 3) & 1) << 3) + (lane & 7);
                    int dch  = g * 2 + ((lane >> 4) & 1);
                    uint32_t ad = pBSrc[ph] + krow * 128 + ((dch ^ (krow & 7)) << 4);
                    uint32_t t4[4];
                    ldmx4t(t4, ad);
                    bf[g * 2][0] = t4[0];     bf[g * 2][1] = t4[1];
                    bf[g * 2 + 1][0] = t4[2]; bf[g * 2 + 1][1] = t4[3];
                }
#pragma unroll
                for (int mt = 0; mt < 2; mt++)
#pragma unroll
                    for (int dt = 0; dt < 8; dt++)
                        mma16816(uacc[mt][dt], af[mt], bf[dt]);
            }
        }

        if (tid < 64) {
#pragma unroll
            for (int r = 0; r < 16; r++) svacc += sV32[r * 64 + tid];
        }
    }

    if (lane < 4) {
        float* kp = g_ksump + ((size_t)seg * BHn + bh) * MM;
#pragma unroll
        for (int j = 0; j < 4; j++) {
            int m = w * 32 + lane * 2 + j * 8;
            kp[m]     = kaccv[j * 2];
            kp[m + 1] = kaccv[j * 2 + 1];
        }
    }
    if (tid < 64) g_svp[((size_t)seg * BHn + bh) * DD + tid] = svacc;

    float* cp = g_ctxp + ((size_t)seg * BHn + bh) * MM * DD;
#pragma unroll
    for (int mt = 0; mt < 2; mt++) {
        int r = w * 32 + mt * 16 + (lane >> 2);
#pragma unroll
        for (int dt = 0; dt < 8; dt++) {
            int col = dt * 8 + (lane & 3) * 2;
            *(float2*)(cp + (size_t)r * DD + col) =
                make_float2(uacc[mt][dt][0], uacc[mt][dt][1]);
            *(float2*)(cp + (size_t)(r + 8) * DD + col) =
                make_float2(uacc[mt][dt][2], uacc[mt][dt][3]);
        }
    }

#pragma unroll
    for (int o = 16; o > 0; o >>= 1)
        ddmax = fmaxf(ddmax, __shfl_xor_sync(0xffffffffu, ddmax, o));
    if (lane == 0) swm[w] = ddmax;
    __syncthreads();
    if (tid == 0) {
        float m = swm[0];
#pragma unroll
        for (int i = 1; i < 8; i++) m = fmaxf(m, swm[i]);
        atomicMaxFloat(&g_kstab, m);
    }
}

// ---------------- assemble ctx + ksum from unstabilized partials ----------------
__global__ __launch_bounds__(256) void ctx_reduce_kernel() {
    const float escale = __expf(-g_kstab);
    int i = blockIdx.x * 256 + threadIdx.x;
    if (i < BHn * MM * DD) {
        int bh = i >> 14;
        int d  = i & 63;
        float U = 0.f, Sv = 0.f;
#pragma unroll
        for (int seg = 0; seg < NSEG; seg++) {
            U  += g_ctxp[(size_t)seg * BHn * MM * DD + i];
            Sv += g_svp[((size_t)seg * BHn + bh) * DD + d];
        }
        g_ctx[i] = RATIO * (escale * U + EPSK * Sv);
    }
    if (i < BHn * MM) {
        float T = 0.f;
#pragma unroll
        for (int seg = 0; seg < NSEG; seg++)
            T += g_ksump[(size_t)seg * BHn * MM + i];
        g_ksum[i] = RATIO * (escale * T + EPSK * (float)NSEQ);
    }
}

// ---------------- qf_kernel v2: dd on tensor cores (R12, unchanged) ----------------
#define QF_SMEM_BYTES 71744

__global__ __launch_bounds__(256, 3) void qf_kernel(
    const float* __restrict__ Q, const float* __restrict__ proj,
    __nv_bfloat16* __restrict__ QFh, __nv_bfloat16* __restrict__ QFl,
    float* __restrict__ Dinv)
{
    extern __shared__ __align__(128) char qsm[];
    const uint32_t smem_base = smem_u32(qsm);
    const uint32_t sPTh = smem_base;
    const uint32_t sPTl = smem_base + 32768;
    const uint32_t sXh  = smem_base + 65536;
    const uint32_t sXl  = smem_base + 67584;
    float* sKs   = (float*)(qsm + 69632);
    float* sDiag = (float*)(qsm + 70656);
    float* sMaxP = (float*)(qsm + 70720);
    float* sDpP  = (float*)(qsm + 71232);

    const int tid = threadIdx.x;
    const int bh  = blockIdx.x;
    const int nblk = blockIdx.y * 256;
    const int lane = tid & 31;
    const int w    = tid >> 5;

    {
        const float4* pr = (const float4*)(proj + tid * DD);
#pragma unroll
        for (int t = 0; t < 16; t++) {
            float4 v = pr[t];
            ushort h0 = bfu(v.x), h1 = bfu(v.y), h2 = bfu(v.z), h3 = bfu(v.w);
            ushort l0 = bfu(v.x - __bfloat162float(__ushort_as_bfloat16(h0)));
            ushort l1 = bfu(v.y - __bfloat162float(__ushort_as_bfloat16(h1)));
            ushort l2 = bfu(v.z - __bfloat162float(__ushort_as_bfloat16(h2)));
            ushort l3 = bfu(v.w - __bfloat162float(__ushort_as_bfloat16(h3)));
            uint2 hv, lv;
            hv.x = ((uint32_t)h1 << 16) | h0; hv.y = ((uint32_t)h3 << 16) | h2;
            lv.x = ((uint32_t)l1 << 16) | l0; lv.y = ((uint32_t)l3 << 16) | l2;
            uint32_t off = (uint32_t)(tid * 128 + (((t >> 1) ^ (tid & 7)) << 4) + (t & 1) * 8);
            *(uint2*)(qsm + off)         = hv;
            *(uint2*)(qsm + 32768 + off) = lv;
        }
        sKs[tid] = g_ksum[bh * MM + tid];
    }

    for (int it = 0; it < 16; it++) {
        const int n0 = nblk + it * 16;
        __syncthreads();

        {
            int row = tid >> 4;
            int t   = tid & 15;
            const float* qp = Q + ((size_t)bh * NSEQ + n0 + row) * DD + t * 4;
            float4 kv = *(const float4*)qp;
            kv.x *= SCQ; kv.y *= SCQ; kv.z *= SCQ; kv.w *= SCQ;
            float ssq = kv.x * kv.x + kv.y * kv.y + kv.z * kv.z + kv.w * kv.w;
#pragma unroll
            for (int o = 8; o > 0; o >>= 1) ssq += __shfl_xor_sync(0xffffffffu, ssq, o);
            if (t == 0) sDiag[row] = 0.5f * ssq;

            ushort h0 = bfu(kv.x), h1 = bfu(kv.y), h2 = bfu(kv.z), h3 = bfu(kv.w);
            ushort l0 = bfu(kv.x - __bfloat162float(__ushort_as_bfloat16(h0)));
            ushort l1 = bfu(kv.y - __bfloat162float(__ushort_as_bfloat16(h1)));
            ushort l2 = bfu(kv.z - __bfloat162float(__ushort_as_bfloat16(h2)));
            ushort l3 = bfu(kv.w - __bfloat162float(__ushort_as_bfloat16(h3)));
            uint2 hv, lv;
            hv.x = ((uint32_t)h1 << 16) | h0; hv.y = ((uint32_t)h3 << 16) | h2;
            lv.x = ((uint32_t)l1 << 16) | l0; lv.y = ((uint32_t)l3 << 16) | l2;
            uint32_t off = (uint32_t)(row * 128 + (((t >> 1) ^ (row & 7)) << 4) + (t & 1) * 8);
            *(uint2*)(qsm + 65536 + off) = hv;
            *(uint2*)(qsm + 67584 + off) = lv;
        }
        __syncthreads();

        float c[4][4];
#pragma unroll
        for (int j = 0; j < 4; j++)
#pragma unroll
            for (int q = 0; q < 4; q++) c[j][q] = 0.f;
        {
            const uint32_t pASrc[3] = {sXh, sXh, sXl};
            const uint32_t pBSrc[3] = {sPTh, sPTl, sPTh};
#pragma unroll
            for (int ph = 0; ph < 3; ph++) {
                const uint32_t cA = pASrc[ph];
                const uint32_t cB = pBSrc[ph];
#pragma unroll
                for (int ks = 0; ks < 4; ks++) {
                    int rowA = (((lane >> 3) & 1) << 3) + (lane & 7);
                    int pbA  = ks * 2 + ((lane >> 4) & 1);
                    uint32_t adA = cA + rowA * 128 + ((pbA ^ (rowA & 7)) << 4);
                    uint32_t af[4];
                    ldmx4(af, adA);
                    uint32_t bf[4][2];
#pragma unroll
                    for (int jb = 0; jb < 2; jb++) {
                        int rowB = w * 32 + jb * 16 + ((lane >> 4) << 3) + (lane & 7);
                        int pbB  = ks * 2 + ((lane >> 3) & 1);
                        uint32_t adB = cB + rowB * 128 + ((pbB ^ (rowB & 7)) << 4);
                        uint32_t t4[4];
                        ldmx4(t4, adB);
                        bf[jb * 2][0] = t4[0]; bf[jb * 2][1] = t4[1];
                        bf[jb * 2 + 1][0] = t4[2]; bf[jb * 2 + 1][1] = t4[3];
                    }
#pragma unroll
                    for (int j = 0; j < 4; j++)
                        mma16816(c[j], af, bf[j]);
                }
            }
        }

        const int r0 = lane >> 2;

        {
            float mx0 = -1e30f, mx1 = -1e30f;
#pragma unroll
            for (int j = 0; j < 4; j++) {
                mx0 = fmaxf(mx0, fmaxf(c[j][0], c[j][1]));
                mx1 = fmaxf(mx1, fmaxf(c[j][2], c[j][3]));
            }
            mx0 = fmaxf(mx0, __shfl_xor_sync(0xffffffffu, mx0, 1));
            mx0 = fmaxf(mx0, __shfl_xor_sync(0xffffffffu, mx0, 2));
            mx1 = fmaxf(mx1, __shfl_xor_sync(0xffffffffu, mx1, 1));
            mx1 = fmaxf(mx1, __shfl_xor_sync(0xffffffffu, mx1, 2));
            if ((lane & 3) == 0) {
                sMaxP[w * 16 + r0]     = mx0;
                sMaxP[w * 16 + r0 + 8] = mx1;
            }
        }
        __syncthreads();

        {
            float fmx0 = sMaxP[r0], fmx1 = sMaxP[r0 + 8];
#pragma unroll
            for (int ww = 1; ww < 8; ww++) {
                fmx0 = fmaxf(fmx0, sMaxP[ww * 16 + r0]);
                fmx1 = fmaxf(fmx1, sMaxP[ww * 16 + r0 + 8]);
            }
            const float sub0 = sDiag[r0] + fmx0;
            const float sub1 = sDiag[r0 + 8] + fmx1;
            const int mb = w * 32 + (lane & 3) * 2;
            const size_t baseA = ((size_t)bh * NSEQ + n0 + r0) * MM;
            const size_t baseB = baseA + 8 * MM;
            float dp0 = 0.f, dp1 = 0.f;
#pragma unroll
            for (int j = 0; j < 4; j++) {
                int m = mb + j * 8;
                float q0 = RATIO * (__expf(c[j][0] - sub0) + EPSK);
                float q1 = RATIO * (__expf(c[j][1] - sub0) + EPSK);
                float q2 = RATIO * (__expf(c[j][2] - sub1) + EPSK);
                float q3 = RATIO * (__expf(c[j][3] - sub1) + EPSK);
                dp0 += q0 * sKs[m] + q1 * sKs[m + 1];
                dp1 += q2 * sKs[m] + q3 * sKs[m + 1];
                ushort h0 = bfu(q0), h1 = bfu(q1), h2 = bfu(q2), h3 = bfu(q3);
                uint32_t hv0 = ((uint32_t)h1 << 16) | h0;
                uint32_t hv1 = ((uint32_t)h3 << 16) | h2;
                uint32_t lv0 = ((uint32_t)bfu(q1 - __bfloat162float(__ushort_as_bfloat16(h1))) << 16)
                             | bfu(q0 - __bfloat162float(__ushort_as_bfloat16(h0)));
                uint32_t lv1 = ((uint32_t)bfu(q3 - __bfloat162float(__ushort_as_bfloat16(h3))) << 16)
                             | bfu(q2 - __bfloat162float(__ushort_as_bfloat16(h2)));
                *(uint32_t*)(QFh + baseA + m) = hv0;
                *(uint32_t*)(QFl + baseA + m) = lv0;
                *(uint32_t*)(QFh + baseB + m) = hv1;
                *(uint32_t*)(QFl + baseB + m) = lv1;
            }
            dp0 += __shfl_xor_sync(0xffffffffu, dp0, 1);
            dp0 += __shfl_xor_sync(0xffffffffu, dp0, 2);
            dp1 += __shfl_xor_sync(0xffffffffu, dp1, 1);
            dp1 += __shfl_xor_sync(0xffffffffu, dp1, 2);
            if ((lane & 3) == 0) {
                sDpP[w * 16 + r0]     = dp0;
                sDpP[w * 16 + r0 + 8] = dp1;
            }
        }
        __syncthreads();

        if (tid < 16) {
            float s = sDpP[tid];
#pragma unroll
            for (int ww = 1; ww < 8; ww++) s += sDpP[ww * 16 + tid];
            Dinv[(size_t)bh * NSEQ + n0 + tid] = 1.f / s;
        }
    }
}

// ---------------- yv_gemm (R9, unchanged) ----------------
#define YV_NCHUNK 12
#define YV_ASTG  16384

__global__ __launch_bounds__(256, 2) void yv_gemm(
    const __nv_bfloat16* __restrict__ QFh, const __nv_bfloat16* __restrict__ QFl,
    __nv_bfloat16* __restrict__ OutH, __nv_bfloat16* __restrict__ OutL)
{
    extern __shared__ __align__(128) char gsm[];
    const uint32_t smem_base = smem_u32(gsm);
    const uint32_t sBH = smem_base + 49152;
    const uint32_t sBL = smem_base + 81920;

    const int tid  = threadIdx.x;
    const int lane = tid & 31;
    const int wid  = tid >> 5;
    const int wm   = wid & 1;
    const int wn   = wid >> 1;
    const int bh   = blockIdx.y;
    const int bm   = blockIdx.x * 128;
    const int b_   = bh >> 4;
    const int h_   = bh & 15;

    {
        const float* cbase = g_ctx + (size_t)bh * MM * DD;
#pragma unroll
        for (int t = 0; t < 64; t++) {
            int e = t * 256 + tid;
            int m = e >> 6, d = e & 63;
            float val = cbase[e];
            __nv_bfloat16 h = __float2bfloat16(val);
            __nv_bfloat16 l = __float2bfloat16(val - __bfloat162float(h));
            int mc = m & 63;
            uint32_t off = (uint32_t)((m >> 6) * 8192 + d * 128 + (((mc >> 3) ^ (d & 7)) << 4) + (mc & 7) * 2);
            *(ushort*)((char*)gsm + 49152 + off) = __bfloat16_as_ushort(h);
            *(ushort*)((char*)gsm + 81920 + off) = __bfloat16_as_ushort(l);
        }
    }

    const __nv_bfloat16* pA[3] = {QFh, QFh, QFl};

    float c[4][2][4];
#pragma unroll
    for (int i = 0; i < 4; i++)
#pragma unroll
        for (int j = 0; j < 2; j++)
#pragma unroll
            for (int q = 0; q < 4; q++) c[i][j][q] = 0.f;

    auto prefetchA = [&](int s, int stage) {
        if (s < YV_NCHUNK) {
            const int ph = s >> 2;
            const int kk = (s & 3) << 6;
            const __nv_bfloat16* gA = pA[ph] + (size_t)bh * NSEQ * MM;
            const uint32_t aB = smem_base + stage * YV_ASTG;
#pragma unroll
            for (int it = 0; it < 4; it++) {
                int idx = it * 256 + tid;
                int row = idx >> 3;
                int pb  = idx & 7;
                uint32_t doff = row * 128 + ((pb ^ (row & 7)) << 4);
                const void* srcA = gA + (size_t)(bm + row) * MM + kk + pb * 8;
                asm volatile("cp.async.cg.shared.global [%0], [%1], 16;" :: "r"(aB + doff), "l"(srcA));
            }
        }
        asm volatile("cp.async.commit_group;" ::: "memory");
    };

    prefetchA(0, 0);
    prefetchA(1, 1);
    __syncthreads();

    for (int s = 0; s < YV_NCHUNK; s++) {
        const int stage = s % 3;
        asm volatile("cp.async.wait_group 1;" ::: "memory");
        __syncthreads();
        prefetchA(s + 2, (s + 2) % 3);

        const uint32_t cA = smem_base + stage * YV_ASTG;
        const int ph = s >> 2;
        const uint32_t cBbase = (ph == 1) ? sBL : sBH;
        const uint32_t cB = cBbase + (uint32_t)((s & 3) * 8192);

#pragma unroll
        for (int ks = 0; ks < 4; ks++) {
            uint32_t bf[2][2];
            {
                int row = wn * 16 + ((lane >> 4) << 3) + (lane & 7);
                int pb  = ks * 2 + ((lane >> 3) & 1);
                uint32_t ad = cB + row * 128 + ((pb ^ (row & 7)) << 4);
                uint32_t t4[4];
                ldmx4(t4, ad);
                bf[0][0] = t4[0]; bf[0][1] = t4[1];
                bf[1][0] = t4[2]; bf[1][1] = t4[3];
            }
#pragma unroll
            for (int i = 0; i < 4; i++) {
                int r0 = wm * 64 + i * 16;
                int row = r0 + (((lane >> 3) & 1) << 3) + (lane & 7);
                int pb  = ks * 2 + ((lane >> 4) & 1);
                uint32_t ad = cA + row * 128 + ((pb ^ (row & 7)) << 4);
                uint32_t af[4];
                ldmx4(af, ad);
#pragma unroll
                for (int j = 0; j < 2; j++)
                    mma16816(c[i][j], af, bf[j]);
            }
        }
        __syncthreads();
    }

#pragma unroll
    for (int i = 0; i < 4; i++) {
        int rl = wm * 64 + i * 16 + (lane >> 2);
        int nA = bm + rl;
        int nB = nA + 8;
        float dA = g_dinv[(size_t)bh * NSEQ + nA];
        float dB = g_dinv[(size_t)bh * NSEQ + nB];
#pragma unroll
        for (int j = 0; j < 2; j++) {
            int col = wn * 16 + j * 8 + (lane & 3) * 2;
            float vA0 = c[i][j][0] * dA, vA1 = c[i][j][1] * dA;
            float vB0 = c[i][j][2] * dB, vB1 = c[i][j][3] * dB;
            __nv_bfloat16 hA0 = __float2bfloat16(vA0), hA1 = __float2bfloat16(vA1);
            __nv_bfloat16 hB0 = __float2bfloat16(vB0), hB1 = __float2bfloat16(vB1);
            uint32_t hvA = ((uint32_t)__bfloat16_as_ushort(hA1) << 16) | __bfloat16_as_ushort(hA0);
            uint32_t lvA = ((uint32_t)__bfloat16_as_ushort(__float2bfloat16(vA1 - __bfloat162float(hA1))) << 16)
                         | __bfloat16_as_ushort(__float2bfloat16(vA0 - __bfloat162float(hA0)));
            uint32_t hvB = ((uint32_t)__bfloat16_as_ushort(hB1) << 16) | __bfloat16_as_ushort(hB0);
            uint32_t lvB = ((uint32_t)__bfloat16_as_ushort(__float2bfloat16(vB1 - __bfloat162float(hB1))) << 16)
                         | __bfloat16_as_ushort(__float2bfloat16(vB0 - __bfloat162float(hB0)));
            size_t idxA = ((size_t)(b_ * NSEQ + nA)) * EE + h_ * DD + col;
            size_t idxB = ((size_t)(b_ * NSEQ + nB)) * EE + h_ * DD + col;
            *(uint32_t*)(OutH + idxA) = hvA;
            *(uint32_t*)(OutL + idxA) = lvA;
            *(uint32_t*)(OutH + idxB) = hvB;
            *(uint32_t*)(OutL + idxB) = lvB;
        }
    }
}

// ---------------- launch ----------------
extern "C" void kernel_launch(void* const* d_in, const int* in_sizes, int n_in,
                              void* d_out, int out_size) {
    const float* x    = (const float*)d_in[0];
    const float* Wq   = (const float*)d_in[1];
    const float* bq   = (const float*)d_in[2];
    const float* Wk   = (const float*)d_in[3];
    const float* bk   = (const float*)d_in[4];
    const float* Wv   = (const float*)d_in[5];
    const float* bv   = (const float*)d_in[6];
    const float* Wo   = (const float*)d_in[7];
    const float* bo   = (const float*)d_in[8];
    const float* proj = (const float*)d_in[9];
    float* out = (float*)d_out;

    float *pq, *pk, *pv, *pdinv;
    __nv_bfloat16 *pah, *pal, *pwh, *pwl, *pqfh, *pqfl;
    cudaGetSymbolAddress((void**)&pq,   g_q);
    cudaGetSymbolAddress((void**)&pk,   g_k);
    cudaGetSymbolAddress((void**)&pv,   g_v);
    cudaGetSymbolAddress((void**)&pdinv, g_dinv);
    cudaGetSymbolAddress((void**)&pah,  g_ah);
    cudaGetSymbolAddress((void**)&pal,  g_al);
    cudaGetSymbolAddress((void**)&pwh,  g_wh);
    cudaGetSymbolAddress((void**)&pwl,  g_wl);
    cudaGetSymbolAddress((void**)&pqfh, g_qfh);
    cudaGetSymbolAddress((void**)&pqfl, g_qfl);

    const int GEMM_SMEM = 3 * STG_BYTES;
    const int YV_SMEM   = 3 * YV_ASTG + 2 * 32768;
    cudaFuncSetAttribute(gemm_mma<0>, cudaFuncAttributeMaxDynamicSharedMemorySize, GEMM_SMEM);
    cudaFuncSetAttribute(gemm_mma<1>, cudaFuncAttributeMaxDynamicSharedMemorySize, GEMM_SMEM);
    cudaFuncSetAttribute(ctx_fused,  cudaFuncAttributeMaxDynamicSharedMemorySize, CTXF_SMEM_BYTES);
    cudaFuncSetAttribute(qf_kernel,  cudaFuncAttributeMaxDynamicSharedMemorySize, QF_SMEM_BYTES);
    cudaFuncSetAttribute(yv_gemm,    cudaFuncAttributeMaxDynamicSharedMemorySize, YV_SMEM);

    dim3 gg(EE / 128, TT / 128);

    init_kernel<<<1, 32>>>();

    split_kernel<<<2048, 256>>>(x, pah, pal, TT * EE / 4);

    split_kernel<<<512, 256>>>(Wq, pwh, pwl, EE * EE / 4);
    gemm_mma<1><<<gg, 256, GEMM_SMEM>>>(pah, pal, pwh, pwl, bq, pq);
    split_kernel<<<512, 256>>>(Wk, pwh, pwl, EE * EE / 4);
    gemm_mma<1><<<gg, 256, GEMM_SMEM>>>(pah, pal, pwh, pwl, bk, pk);
    split_kernel<<<512, 256>>>(Wv, pwh, pwl, EE * EE / 4);
    gemm_mma<1><<<gg, 256, GEMM_SMEM>>>(pah, pal, pwh, pwl, bv, pv);

    ctx_fused<<<dim3(BHn, NSEG), 256, CTXF_SMEM_BYTES>>>(pk, pv, proj);
    ctx_reduce_kernel<<<(BHn * MM * DD + 255) / 256, 256>>>();

    qf_kernel<<<dim3(BHn, 16), 256, QF_SMEM_BYTES>>>(pq, proj, pqfh, pqfl, pdinv);

    yv_gemm<<<dim3(NSEQ / 128, BHn), 256, YV_SMEM>>>(pqfh, pqfl, pah, pal);

    split_kernel<<<512, 256>>>(Wo, pwh, pwl, EE * EE / 4);
    gemm_mma<0><<<gg, 256, GEMM_SMEM>>>(pah, pal, pwh, pwl, bo, out);
}

// round 15
// speedup vs baseline: 1.2778x; 1.0243x over previous
#include <cuda_runtime.h>
#include <cuda_bf16.h>
#include <math.h>
#include <stdint.h>

// Problem constants
#define BB   4
#define NSEQ 4096
#define EE   1024
#define HH   16
#define DD   64
#define MM   256
#define TT   (BB*NSEQ)     // 16384
#define BHn  (BB*HH)       // 64
#define NSEG 8

#define RATIO 0.0625f
#define EPSK  1e-4f
#define SCQ   0.3535533905932738f   // 64^-0.25

// ---------------- device scratch ----------------
__device__ float g_q[(size_t)BHn*NSEQ*DD];
__device__ float g_k[(size_t)BHn*NSEQ*DD];
__device__ float g_v[(size_t)BHn*NSEQ*DD];
__device__ float g_ksum[BHn*MM];
__device__ float g_ksump[(size_t)NSEG*BHn*MM];
__device__ float g_svp[(size_t)NSEG*BHn*DD];
__device__ float g_ctxp[(size_t)NSEG*BHn*MM*DD];
__device__ float g_ctx[BHn*MM*DD];
__device__ float g_dinv[(size_t)BHn*NSEQ];
__device__ float g_kstab;
__device__ __nv_bfloat16 g_ah[(size_t)TT*EE];
__device__ __nv_bfloat16 g_al[(size_t)TT*EE];
__device__ __nv_bfloat16 g_wh[(size_t)EE*EE];
__device__ __nv_bfloat16 g_wl[(size_t)EE*EE];
__device__ __nv_bfloat16 g_qfh[(size_t)BHn*NSEQ*MM];
__device__ __nv_bfloat16 g_qfl[(size_t)BHn*NSEQ*MM];

// ---------------- helpers ----------------
__device__ __forceinline__ void atomicMaxFloat(float* addr, float v) {
    if (v >= 0.f) atomicMax((int*)addr, __float_as_int(v));
    else          atomicMin((unsigned int*)addr, __float_as_uint(v));
}

__global__ void init_kernel() {
    if (blockIdx.x == 0 && threadIdx.x == 0) g_kstab = -INFINITY;
}

__device__ __forceinline__ uint32_t smem_u32(const void* p) {
    uint32_t a;
    asm("{ .reg .u64 t; cvta.to.shared.u64 t, %1; cvt.u32.u64 %0, t; }" : "=r"(a) : "l"(p));
    return a;
}

__device__ __forceinline__ void mma16816(float* c, const uint32_t* a, const uint32_t* b) {
    asm volatile(
        "mma.sync.aligned.m16n8k16.row.col.f32.bf16.bf16.f32 "
        "{%0,%1,%2,%3},{%4,%5,%6,%7},{%8,%9},{%0,%1,%2,%3};"
        : "+f"(c[0]), "+f"(c[1]), "+f"(c[2]), "+f"(c[3])
        : "r"(a[0]), "r"(a[1]), "r"(a[2]), "r"(a[3]), "r"(b[0]), "r"(b[1]));
}

__device__ __forceinline__ void ldmx4(uint32_t* r, uint32_t addr) {
    asm volatile("ldmatrix.sync.aligned.m8n8.x4.shared.b16 {%0,%1,%2,%3}, [%4];"
        : "=r"(r[0]), "=r"(r[1]), "=r"(r[2]), "=r"(r[3]) : "r"(addr));
}
__device__ __forceinline__ void ldmx4t(uint32_t* r, uint32_t addr) {
    asm volatile("ldmatrix.sync.aligned.m8n8.x4.trans.shared.b16 {%0,%1,%2,%3}, [%4];"
        : "=r"(r[0]), "=r"(r[1]), "=r"(r[2]), "=r"(r[3]) : "r"(addr));
}

// packed fp32x2
__device__ __forceinline__ void fma2(unsigned long long& d, unsigned long long a, unsigned long long b) {
    asm("fma.rn.f32x2 %0, %1, %2, %0;" : "+l"(d) : "l"(a), "l"(b));
}
__device__ __forceinline__ unsigned long long pack2(float x) {
    unsigned long long r;
    asm("mov.b64 %0, {%1, %1};" : "=l"(r) : "f"(x));
    return r;
}
__device__ __forceinline__ float2 unpack2(unsigned long long v) {
    float2 f;
    asm("mov.b64 {%0, %1}, %2;" : "=f"(f.x), "=f"(f.y) : "l"(v));
    return f;
}
__device__ __forceinline__ float f4c(const float4& v, int j) {
    return j == 0 ? v.x : j == 1 ? v.y : j == 2 ? v.z : v.w;
}
__device__ __forceinline__ ushort bfu(float x) {
    return __bfloat16_as_ushort(__float2bfloat16(x));
}

// ---------------- fp32 -> bf16 hi/lo split ----------------
__global__ __launch_bounds__(256) void split_kernel(
    const float* __restrict__ src, __nv_bfloat16* __restrict__ hi,
    __nv_bfloat16* __restrict__ lo, int n4)
{
    const float4* s4 = (const float4*)src;
    uint2* h2 = (uint2*)hi;
    uint2* l2 = (uint2*)lo;
    for (int i = blockIdx.x * 256 + threadIdx.x; i < n4; i += gridDim.x * 256) {
        float4 v = s4[i];
        __nv_bfloat16 h0 = __float2bfloat16(v.x);
        __nv_bfloat16 h1 = __float2bfloat16(v.y);
        __nv_bfloat16 h2b = __float2bfloat16(v.z);
        __nv_bfloat16 h3 = __float2bfloat16(v.w);
        __nv_bfloat16 l0 = __float2bfloat16(v.x - __bfloat162float(h0));
        __nv_bfloat16 l1 = __float2bfloat16(v.y - __bfloat162float(h1));
        __nv_bfloat16 l2b = __float2bfloat16(v.z - __bfloat162float(h2b));
        __nv_bfloat16 l3 = __float2bfloat16(v.w - __bfloat162float(h3));
        uint2 hv, lv;
        hv.x = ((uint32_t)__bfloat16_as_ushort(h1) << 16) | __bfloat16_as_ushort(h0);
        hv.y = ((uint32_t)__bfloat16_as_ushort(h3) << 16) | __bfloat16_as_ushort(h2b);
        lv.x = ((uint32_t)__bfloat16_as_ushort(l1) << 16) | __bfloat16_as_ushort(l0);
        lv.y = ((uint32_t)__bfloat16_as_ushort(l3) << 16) | __bfloat16_as_ushort(l2b);
        h2[i] = hv;
        l2[i] = lv;
    }
}

// ---------------- bf16-split mma.sync GEMM v3: fused 3-term per K-chunk ----------------
// K-chunk 32; stage holds Ah/Al/Wh/Wl tiles (4 x 8KB = 32KB); 3-stage ring (96KB).
// Per fragment-pair: Ah*Wh + Ah*Wl + Al*Wh -> 12 LDSM per 48 HMMA (was 24/64).
// 64B-row swizzle: (pb ^ ((row>>1)&3)) << 4  (R3/R4 proven layout).
#define NCHUNK 32
#define STG_BYTES 32768

template<int OUT_MODE>
__global__ __launch_bounds__(256, 2) void gemm_mma(
    const __nv_bfloat16* __restrict__ Ah, const __nv_bfloat16* __restrict__ Al,
    const __nv_bfloat16* __restrict__ Wh, const __nv_bfloat16* __restrict__ Wl,
    const float* __restrict__ bias, float* __restrict__ C)
{
    extern __shared__ __align__(128) char gsm[];

    const int tid  = threadIdx.x;
    const int lane = tid & 31;
    const int wid  = tid >> 5;
    const int wm   = wid & 1;
    const int wn   = wid >> 1;
    const int bm   = blockIdx.y * 128;
    const int bn   = blockIdx.x * 128;

    float c[4][4][4];
#pragma unroll
    for (int i = 0; i < 4; i++)
#pragma unroll
        for (int j = 0; j < 4; j++)
#pragma unroll
            for (int q = 0; q < 4; q++) c[i][j][q] = 0.f;

    const uint32_t smem_base = smem_u32(gsm);

    auto prefetch = [&](int s, int stage) {
        if (s < NCHUNK) {
            const int kk = s << 5;
            const uint32_t st = smem_base + stage * STG_BYTES;
#pragma unroll
            for (int it = 0; it < 2; it++) {
                int idx = it * 256 + tid;        // 0..511
                int row = idx >> 2;              // 0..127
                int pb  = idx & 3;
                uint32_t doff = row * 64 + ((pb ^ ((row >> 1) & 3)) << 4);
                const void* sAh = Ah + (size_t)(bm + row) * EE + kk + pb * 8;
                const void* sAl = Al + (size_t)(bm + row) * EE + kk + pb * 8;
                const void* sBh = Wh + (size_t)(bn + row) * EE + kk + pb * 8;
                const void* sBl = Wl + (size_t)(bn + row) * EE + kk + pb * 8;
                asm volatile("cp.async.cg.shared.global [%0], [%1], 16;" :: "r"(st + doff),         "l"(sAh));
                asm volatile("cp.async.cg.shared.global [%0], [%1], 16;" :: "r"(st + 8192 + doff),  "l"(sAl));
                asm volatile("cp.async.cg.shared.global [%0], [%1], 16;" :: "r"(st + 16384 + doff), "l"(sBh));
                asm volatile("cp.async.cg.shared.global [%0], [%1], 16;" :: "r"(st + 24576 + doff), "l"(sBl));
            }
        }
        asm volatile("cp.async.commit_group;" ::: "memory");
    };

    prefetch(0, 0);
    prefetch(1, 1);

    for (int s = 0; s < NCHUNK; s++) {
        const int stage = s % 3;
        asm volatile("cp.async.wait_group 1;" ::: "memory");
        __syncthreads();
        prefetch(s + 2, (s + 2) % 3);

        const uint32_t cAh = smem_base + stage * STG_BYTES;
        const uint32_t cAl = cAh + 8192;
        const uint32_t cBh = cAh + 16384;
        const uint32_t cBl = cAh + 24576;
#pragma unroll
        for (int ks = 0; ks < 2; ks++) {
            uint32_t bfh[4][2], bfl[4][2];
#pragma unroll
            for (int jb = 0; jb < 2; jb++) {
                int row = wn * 32 + jb * 16 + ((lane >> 4) << 3) + (lane & 7);
                int pb  = ks * 2 + ((lane >> 3) & 1);
                uint32_t doff = row * 64 + ((pb ^ ((row >> 1) & 3)) << 4);
                uint32_t t4[4];
                ldmx4(t4, cBh + doff);
                bfh[jb * 2][0] = t4[0]; bfh[jb * 2][1] = t4[1];
                bfh[jb * 2 + 1][0] = t4[2]; bfh[jb * 2 + 1][1] = t4[3];
                ldmx4(t4, cBl + doff);
                bfl[jb * 2][0] = t4[0]; bfl[jb * 2][1] = t4[1];
                bfl[jb * 2 + 1][0] = t4[2]; bfl[jb * 2 + 1][1] = t4[3];
            }
#pragma unroll
            for (int i = 0; i < 4; i++) {
                int row = wm * 64 + i * 16 + (((lane >> 3) & 1) << 3) + (lane & 7);
                int pb  = ks * 2 + ((lane >> 4) & 1);
                uint32_t doff = row * 64 + ((pb ^ ((row >> 1) & 3)) << 4);
                uint32_t afh[4], afl[4];
                ldmx4(afh, cAh + doff);
                ldmx4(afl, cAl + doff);
#pragma unroll
                for (int j = 0; j < 4; j++) {
                    mma16816(c[i][j], afh, bfh[j]);
                    mma16816(c[i][j], afh, bfl[j]);
                    mma16816(c[i][j], afl, bfh[j]);
                }
            }
        }
    }

#pragma unroll
    for (int i = 0; i < 4; i++) {
        int r = bm + wm * 64 + i * 16 + (lane >> 2);
#pragma unroll
        for (int j = 0; j < 4; j++) {
            int col = bn + wn * 32 + j * 8 + (lane & 3) * 2;
            float b0 = bias[col], b1 = bias[col + 1];
            float2 v0 = make_float2(c[i][j][0] + b0, c[i][j][1] + b1);
            float2 v1 = make_float2(c[i][j][2] + b0, c[i][j][3] + b1);
            if (OUT_MODE == 0) {
                *(float2*)(C + (size_t)r * EE + col)       = v0;
                *(float2*)(C + (size_t)(r + 8) * EE + col) = v1;
            } else {
                int h_ = col >> 6, d0 = col & 63;
                int b_ = r >> 12, n_ = r & 4095;
                size_t base = ((size_t)(b_ * HH + h_) * NSEQ);
                *(float2*)(C + (base + n_)     * DD + d0) = v0;
                *(float2*)(C + (base + n_ + 8) * DD + d0) = v1;
            }
        }
    }
}

// ---------------- ctx_fused v3: dd AND U on tensor cores (R13, unchanged) ----------------
#define CTXF_SMEM_BYTES 94272

__global__ __launch_bounds__(256, 2) void ctx_fused(
    const float* __restrict__ K, const float* __restrict__ V,
    const float* __restrict__ proj)
{
    extern __shared__ __align__(128) char csm[];
    const uint32_t smem_base = smem_u32(csm);
    const uint32_t sPTh = smem_base;
    const uint32_t sPTl = smem_base + 32768;
    const uint32_t sXh  = smem_base + 65536;
    const uint32_t sXl  = smem_base + 67584;
    const uint32_t sKFh = smem_base + 69632;
    const uint32_t sKFl = smem_base + 77824;
    const uint32_t sVh  = smem_base + 86016;
    const uint32_t sVl  = smem_base + 88064;
    float* sV32  = (float*)(csm + 90112);
    float* sDiag = (float*)(csm + 94208);
    __shared__ float swm[8];

    const int tid = threadIdx.x;
    const int bh  = blockIdx.x;
    const int seg = blockIdx.y;
    const int lane = tid & 31;
    const int w    = tid >> 5;

    {
        const float4* pr = (const float4*)(proj + tid * DD);
#pragma unroll
        for (int t = 0; t < 16; t++) {
            float4 v = pr[t];
            ushort h0 = bfu(v.x), h1 = bfu(v.y), h2 = bfu(v.z), h3 = bfu(v.w);
            ushort l0 = bfu(v.x - __bfloat162float(__ushort_as_bfloat16(h0)));
            ushort l1 = bfu(v.y - __bfloat162float(__ushort_as_bfloat16(h1)));
            ushort l2 = bfu(v.z - __bfloat162float(__ushort_as_bfloat16(h2)));
            ushort l3 = bfu(v.w - __bfloat162float(__ushort_as_bfloat16(h3)));
            uint2 hv, lv;
            hv.x = ((uint32_t)h1 << 16) | h0; hv.y = ((uint32_t)h3 << 16) | h2;
            lv.x = ((uint32_t)l1 << 16) | l0; lv.y = ((uint32_t)l3 << 16) | l2;
            uint32_t off = (uint32_t)(tid * 128 + (((t >> 1) ^ (tid & 7)) << 4) + (t & 1) * 8);
            *(uint2*)(csm + off)         = hv;
            *(uint2*)(csm + 32768 + off) = lv;
        }
    }

    float uacc[2][8][4];
#pragma unroll
    for (int i = 0; i < 2; i++)
#pragma unroll
        for (int j = 0; j < 8; j++)
#pragma unroll
            for (int q = 0; q < 4; q++) uacc[i][j][q] = 0.f;
    float kaccv[8];
#pragma unroll
    for (int i = 0; i < 8; i++) kaccv[i] = 0.f;
    float svacc = 0.f;
    float ddmax = -1e30f;

    for (int it = 0; it < 32; it++) {
        const int n0 = seg * 512 + it * 16;
        __syncthreads();

        {
            int row = tid >> 4;
            int t   = tid & 15;
            const float* kp = K + ((size_t)bh * NSEQ + n0 + row) * DD + t * 4;
            const float* vp = V + ((size_t)bh * NSEQ + n0 + row) * DD + t * 4;
            float4 kv = *(const float4*)kp;
            float4 vv = *(const float4*)vp;
            kv.x *= SCQ; kv.y *= SCQ; kv.z *= SCQ; kv.w *= SCQ;
            float ssq = kv.x * kv.x + kv.y * kv.y + kv.z * kv.z + kv.w * kv.w;
#pragma unroll
            for (int o = 8; o > 0; o >>= 1) ssq += __shfl_xor_sync(0xffffffffu, ssq, o);
            if (t == 0) sDiag[row] = 0.5f * ssq;

            uint32_t off = (uint32_t)(row * 128 + (((t >> 1) ^ (row & 7)) << 4) + (t & 1) * 8);
            {
                ushort h0 = bfu(kv.x), h1 = bfu(kv.y), h2 = bfu(kv.z), h3 = bfu(kv.w);
                ushort l0 = bfu(kv.x - __bfloat162float(__ushort_as_bfloat16(h0)));
                ushort l1 = bfu(kv.y - __bfloat162float(__ushort_as_bfloat16(h1)));
                ushort l2 = bfu(kv.z - __bfloat162float(__ushort_as_bfloat16(h2)));
                ushort l3 = bfu(kv.w - __bfloat162float(__ushort_as_bfloat16(h3)));
                uint2 hv, lv;
                hv.x = ((uint32_t)h1 << 16) | h0; hv.y = ((uint32_t)h3 << 16) | h2;
                lv.x = ((uint32_t)l1 << 16) | l0; lv.y = ((uint32_t)l3 << 16) | l2;
                *(uint2*)(csm + 65536 + off) = hv;
                *(uint2*)(csm + 67584 + off) = lv;
            }
            {
                ushort h0 = bfu(vv.x), h1 = bfu(vv.y), h2 = bfu(vv.z), h3 = bfu(vv.w);
                ushort l0 = bfu(vv.x - __bfloat162float(__ushort_as_bfloat16(h0)));
                ushort l1 = bfu(vv.y - __bfloat162float(__ushort_as_bfloat16(h1)));
                ushort l2 = bfu(vv.z - __bfloat162float(__ushort_as_bfloat16(h2)));
                ushort l3 = bfu(vv.w - __bfloat162float(__ushort_as_bfloat16(h3)));
                uint2 hv, lv;
                hv.x = ((uint32_t)h1 << 16) | h0; hv.y = ((uint32_t)h3 << 16) | h2;
                lv.x = ((uint32_t)l1 << 16) | l0; lv.y = ((uint32_t)l3 << 16) | l2;
                *(uint2*)(csm + 86016 + off) = hv;
                *(uint2*)(csm + 88064 + off) = lv;
                *(float4*)(sV32 + row * 64 + t * 4) = vv;
            }
        }
        __syncthreads();

        {
            float c[4][4];
#pragma unroll
            for (int j = 0; j < 4; j++)
#pragma unroll
                for (int q = 0; q < 4; q++) c[j][q] = 0.f;

            const uint32_t pASrc[3] = {sXh, sXh, sXl};
            const uint32_t pBSrc[3] = {sPTh, sPTl, sPTh};
#pragma unroll
            for (int ph = 0; ph < 3; ph++) {
                const uint32_t cA = pASrc[ph];
                const uint32_t cB = pBSrc[ph];
#pragma unroll
                for (int ks = 0; ks < 4; ks++) {
                    int rowA = (((lane >> 3) & 1) << 3) + (lane & 7);
                    int pbA  = ks * 2 + ((lane >> 4) & 1);
                    uint32_t adA = cA + rowA * 128 + ((pbA ^ (rowA & 7)) << 4);
                    uint32_t af[4];
                    ldmx4(af, adA);
                    uint32_t bf[4][2];
#pragma unroll
                    for (int jb = 0; jb < 2; jb++) {
                        int rowB = w * 32 + jb * 16 + ((lane >> 4) << 3) + (lane & 7);
                        int pbB  = ks * 2 + ((lane >> 3) & 1);
                        uint32_t adB = cB + rowB * 128 + ((pbB ^ (rowB & 7)) << 4);
                        uint32_t t4[4];
                        ldmx4(t4, adB);
                        bf[jb * 2][0] = t4[0]; bf[jb * 2][1] = t4[1];
                        bf[jb * 2 + 1][0] = t4[2]; bf[jb * 2 + 1][1] = t4[3];
                    }
#pragma unroll
                    for (int j = 0; j < 4; j++)
                        mma16816(c[j], af, bf[j]);
                }
            }

            const int r0 = lane >> 2;
            const int mb = w * 32 + (lane & 3) * 2;
            const float dg0 = sDiag[r0];
            const float dg1 = sDiag[r0 + 8];
#pragma unroll
            for (int j = 0; j < 4; j++) {
                int m = mb + j * 8;
                float v0 = c[j][0], v1 = c[j][1], v2 = c[j][2], v3 = c[j][3];
                ddmax = fmaxf(ddmax, fmaxf(fmaxf(v0, v1), fmaxf(v2, v3)));
                float e0 = __expf(v0 - dg0), e1 = __expf(v1 - dg0);
                float e2 = __expf(v2 - dg1), e3 = __expf(v3 - dg1);

                uint32_t off0 = (uint32_t)(r0 * 512 + (((m >> 3) ^ (r0 & 7)) << 4) + (m & 7) * 2);
                uint32_t off1 = off0 + 8 * 512;
                ushort h0 = bfu(e0), h1 = bfu(e1), h2 = bfu(e2), h3 = bfu(e3);
                *(uint32_t*)(csm + 69632 + off0) = ((uint32_t)h1 << 16) | h0;
                *(uint32_t*)(csm + 69632 + off1) = ((uint32_t)h3 << 16) | h2;
                *(uint32_t*)(csm + 77824 + off0) =
                    ((uint32_t)bfu(e1 - __bfloat162float(__ushort_as_bfloat16(h1))) << 16)
                    | bfu(e0 - __bfloat162float(__ushort_as_bfloat16(h0)));
                *(uint32_t*)(csm + 77824 + off1) =
                    ((uint32_t)bfu(e3 - __bfloat162float(__ushort_as_bfloat16(h3))) << 16)
                    | bfu(e2 - __bfloat162float(__ushort_as_bfloat16(h2)));

                float s0 = e0 + e2, s1 = e1 + e3;
                s0 += __shfl_xor_sync(0xffffffffu, s0, 4);
                s0 += __shfl_xor_sync(0xffffffffu, s0, 8);
                s0 += __shfl_xor_sync(0xffffffffu, s0, 16);
                s1 += __shfl_xor_sync(0xffffffffu, s1, 4);
                s1 += __shfl_xor_sync(0xffffffffu, s1, 8);
                s1 += __shfl_xor_sync(0xffffffffu, s1, 16);
                kaccv[j * 2]     += s0;
                kaccv[j * 2 + 1] += s1;
            }
        }
        __syncthreads();

        {
            const uint32_t pASrc[3] = {sKFh, sKFh, sKFl};
            const uint32_t pBSrc[3] = {sVh, sVl, sVh};
#pragma unroll
            for (int ph = 0; ph < 3; ph++) {
                uint32_t af[2][4];
#pragma unroll
                for (int mt = 0; mt < 2; mt++) {
                    int krow = (((lane >> 4) & 1) << 3) + (lane & 7);
                    int moff = w * 32 + mt * 16 + (((lane >> 3) & 1) << 3);
                    uint32_t ad = pASrc[ph] + krow * 512 + ((((moff >> 3)) ^ (krow & 7)) << 4);
                    ldmx4t(af[mt], ad);
                }
                uint32_t bf[8][2];
#pragma unroll
                for (int g = 0; g < 4; g++) {
                    int krow = (((lane >> 3) & 1) << 3) + (lane & 7);
                    int dch  = g * 2 + ((lane >> 4) & 1);
                    uint32_t ad = pBSrc[ph] + krow * 128 + ((dch ^ (krow & 7)) << 4);
                    uint32_t t4[4];
                    ldmx4t(t4, ad);
                    bf[g * 2][0] = t4[0];     bf[g * 2][1] = t4[1];
                    bf[g * 2 + 1][0] = t4[2]; bf[g * 2 + 1][1] = t4[3];
                }
#pragma unroll
                for (int mt = 0; mt < 2; mt++)
#pragma unroll
                    for (int dt = 0; dt < 8; dt++)
                        mma16816(uacc[mt][dt], af[mt], bf[dt]);
            }
        }

        if (tid < 64) {
#pragma unroll
            for (int r = 0; r < 16; r++) svacc += sV32[r * 64 + tid];
        }
    }

    if (lane < 4) {
        float* kp = g_ksump + ((size_t)seg * BHn + bh) * MM;
#pragma unroll
        for (int j = 0; j < 4; j++) {
            int m = w * 32 + lane * 2 + j * 8;
            kp[m]     = kaccv[j * 2];
            kp[m + 1] = kaccv[j * 2 + 1];
        }
    }
    if (tid < 64) g_svp[((size_t)seg * BHn + bh) * DD + tid] = svacc;

    float* cp = g_ctxp + ((size_t)seg * BHn + bh) * MM * DD;
#pragma unroll
    for (int mt = 0; mt < 2; mt++) {
        int r = w * 32 + mt * 16 + (lane >> 2);
#pragma unroll
        for (int dt = 0; dt < 8; dt++) {
            int col = dt * 8 + (lane & 3) * 2;
            *(float2*)(cp + (size_t)r * DD + col) =
                make_float2(uacc[mt][dt][0], uacc[mt][dt][1]);
            *(float2*)(cp + (size_t)(r + 8) * DD + col) =
                make_float2(uacc[mt][dt][2], uacc[mt][dt][3]);
        }
    }

#pragma unroll
    for (int o = 16; o > 0; o >>= 1)
        ddmax = fmaxf(ddmax, __shfl_xor_sync(0xffffffffu, ddmax, o));
    if (lane == 0) swm[w] = ddmax;
    __syncthreads();
    if (tid == 0) {
        float m = swm[0];
#pragma unroll
        for (int i = 1; i < 8; i++) m = fmaxf(m, swm[i]);
        atomicMaxFloat(&g_kstab, m);
    }
}

// ---------------- assemble ctx + ksum from unstabilized partials ----------------
__global__ __launch_bounds__(256) void ctx_reduce_kernel() {
    const float escale = __expf(-g_kstab);
    int i = blockIdx.x * 256 + threadIdx.x;
    if (i < BHn * MM * DD) {
        int bh = i >> 14;
        int d  = i & 63;
        float U = 0.f, Sv = 0.f;
#pragma unroll
        for (int seg = 0; seg < NSEG; seg++) {
            U  += g_ctxp[(size_t)seg * BHn * MM * DD + i];
            Sv += g_svp[((size_t)seg * BHn + bh) * DD + d];
        }
        g_ctx[i] = RATIO * (escale * U + EPSK * Sv);
    }
    if (i < BHn * MM) {
        float T = 0.f;
#pragma unroll
        for (int seg = 0; seg < NSEG; seg++)
            T += g_ksump[(size_t)seg * BHn * MM + i];
        g_ksum[i] = RATIO * (escale * T + EPSK * (float)NSEQ);
    }
}

// ---------------- qf_kernel v2: dd on tensor cores (R12, unchanged) ----------------
#define QF_SMEM_BYTES 71744

__global__ __launch_bounds__(256, 3) void qf_kernel(
    const float* __restrict__ Q, const float* __restrict__ proj,
    __nv_bfloat16* __restrict__ QFh, __nv_bfloat16* __restrict__ QFl,
    float* __restrict__ Dinv)
{
    extern __shared__ __align__(128) char qsm[];
    const uint32_t smem_base = smem_u32(qsm);
    const uint32_t sPTh = smem_base;
    const uint32_t sPTl = smem_base + 32768;
    const uint32_t sXh  = smem_base + 65536;
    const uint32_t sXl  = smem_base + 67584;
    float* sKs   = (float*)(qsm + 69632);
    float* sDiag = (float*)(qsm + 70656);
    float* sMaxP = (float*)(qsm + 70720);
    float* sDpP  = (float*)(qsm + 71232);

    const int tid = threadIdx.x;
    const int bh  = blockIdx.x;
    const int nblk = blockIdx.y * 256;
    const int lane = tid & 31;
    const int w    = tid >> 5;

    {
        const float4* pr = (const float4*)(proj + tid * DD);
#pragma unroll
        for (int t = 0; t < 16; t++) {
            float4 v = pr[t];
            ushort h0 = bfu(v.x), h1 = bfu(v.y), h2 = bfu(v.z), h3 = bfu(v.w);
            ushort l0 = bfu(v.x - __bfloat162float(__ushort_as_bfloat16(h0)));
            ushort l1 = bfu(v.y - __bfloat162float(__ushort_as_bfloat16(h1)));
            ushort l2 = bfu(v.z - __bfloat162float(__ushort_as_bfloat16(h2)));
            ushort l3 = bfu(v.w - __bfloat162float(__ushort_as_bfloat16(h3)));
            uint2 hv, lv;
            hv.x = ((uint32_t)h1 << 16) | h0; hv.y = ((uint32_t)h3 << 16) | h2;
            lv.x = ((uint32_t)l1 << 16) | l0; lv.y = ((uint32_t)l3 << 16) | l2;
            uint32_t off = (uint32_t)(tid * 128 + (((t >> 1) ^ (tid & 7)) << 4) + (t & 1) * 8);
            *(uint2*)(qsm + off)         = hv;
            *(uint2*)(qsm + 32768 + off) = lv;
        }
        sKs[tid] = g_ksum[bh * MM + tid];
    }

    for (int it = 0; it < 16; it++) {
        const int n0 = nblk + it * 16;
        __syncthreads();

        {
            int row = tid >> 4;
            int t   = tid & 15;
            const float* qp = Q + ((size_t)bh * NSEQ + n0 + row) * DD + t * 4;
            float4 kv = *(const float4*)qp;
            kv.x *= SCQ; kv.y *= SCQ; kv.z *= SCQ; kv.w *= SCQ;
            float ssq = kv.x * kv.x + kv.y * kv.y + kv.z * kv.z + kv.w * kv.w;
#pragma unroll
            for (int o = 8; o > 0; o >>= 1) ssq += __shfl_xor_sync(0xffffffffu, ssq, o);
            if (t == 0) sDiag[row] = 0.5f * ssq;

            ushort h0 = bfu(kv.x), h1 = bfu(kv.y), h2 = bfu(kv.z), h3 = bfu(kv.w);
            ushort l0 = bfu(kv.x - __bfloat162float(__ushort_as_bfloat16(h0)));
            ushort l1 = bfu(kv.y - __bfloat162float(__ushort_as_bfloat16(h1)));
            ushort l2 = bfu(kv.z - __bfloat162float(__ushort_as_bfloat16(h2)));
            ushort l3 = bfu(kv.w - __bfloat162float(__ushort_as_bfloat16(h3)));
            uint2 hv, lv;
            hv.x = ((uint32_t)h1 << 16) | h0; hv.y = ((uint32_t)h3 << 16) | h2;
            lv.x = ((uint32_t)l1 << 16) | l0; lv.y = ((uint32_t)l3 << 16) | l2;
            uint32_t off = (uint32_t)(row * 128 + (((t >> 1) ^ (row & 7)) << 4) + (t & 1) * 8);
            *(uint2*)(qsm + 65536 + off) = hv;
            *(uint2*)(qsm + 67584 + off) = lv;
        }
        __syncthreads();

        float c[4][4];
#pragma unroll
        for (int j = 0; j < 4; j++)
#pragma unroll
            for (int q = 0; q < 4; q++) c[j][q] = 0.f;
        {
            const uint32_t pASrc[3] = {sXh, sXh, sXl};
            const uint32_t pBSrc[3] = {sPTh, sPTl, sPTh};
#pragma unroll
            for (int ph = 0; ph < 3; ph++) {
                const uint32_t cA = pASrc[ph];
                const uint32_t cB = pBSrc[ph];
#pragma unroll
                for (int ks = 0; ks < 4; ks++) {
                    int rowA = (((lane >> 3) & 1) << 3) + (lane & 7);
                    int pbA  = ks * 2 + ((lane >> 4) & 1);
                    uint32_t adA = cA + rowA * 128 + ((pbA ^ (rowA & 7)) << 4);
                    uint32_t af[4];
                    ldmx4(af, adA);
                    uint32_t bf[4][2];
#pragma unroll
                    for (int jb = 0; jb < 2; jb++) {
                        int rowB = w * 32 + jb * 16 + ((lane >> 4) << 3) + (lane & 7);
                        int pbB  = ks * 2 + ((lane >> 3) & 1);
                        uint32_t adB = cB + rowB * 128 + ((pbB ^ (rowB & 7)) << 4);
                        uint32_t t4[4];
                        ldmx4(t4, adB);
                        bf[jb * 2][0] = t4[0]; bf[jb * 2][1] = t4[1];
                        bf[jb * 2 + 1][0] = t4[2]; bf[jb * 2 + 1][1] = t4[3];
                    }
#pragma unroll
                    for (int j = 0; j < 4; j++)
                        mma16816(c[j], af, bf[j]);
                }
            }
        }

        const int r0 = lane >> 2;

        {
            float mx0 = -1e30f, mx1 = -1e30f;
#pragma unroll
            for (int j = 0; j < 4; j++) {
                mx0 = fmaxf(mx0, fmaxf(c[j][0], c[j][1]));
                mx1 = fmaxf(mx1, fmaxf(c[j][2], c[j][3]));
            }
            mx0 = fmaxf(mx0, __shfl_xor_sync(0xffffffffu, mx0, 1));
            mx0 = fmaxf(mx0, __shfl_xor_sync(0xffffffffu, mx0, 2));
            mx1 = fmaxf(mx1, __shfl_xor_sync(0xffffffffu, mx1, 1));
            mx1 = fmaxf(mx1, __shfl_xor_sync(0xffffffffu, mx1, 2));
            if ((lane & 3) == 0) {
                sMaxP[w * 16 + r0]     = mx0;
                sMaxP[w * 16 + r0 + 8] = mx1;
            }
        }
        __syncthreads();

        {
            float fmx0 = sMaxP[r0], fmx1 = sMaxP[r0 + 8];
#pragma unroll
            for (int ww = 1; ww < 8; ww++) {
                fmx0 = fmaxf(fmx0, sMaxP[ww * 16 + r0]);
                fmx1 = fmaxf(fmx1, sMaxP[ww * 16 + r0 + 8]);
            }
            const float sub0 = sDiag[r0] + fmx0;
            const float sub1 = sDiag[r0 + 8] + fmx1;
            const int mb = w * 32 + (lane & 3) * 2;
            const size_t baseA = ((size_t)bh * NSEQ + n0 + r0) * MM;
            const size_t baseB = baseA + 8 * MM;
            float dp0 = 0.f, dp1 = 0.f;
#pragma unroll
            for (int j = 0; j < 4; j++) {
                int m = mb + j * 8;
                float q0 = RATIO * (__expf(c[j][0] - sub0) + EPSK);
                float q1 = RATIO * (__expf(c[j][1] - sub0) + EPSK);
                float q2 = RATIO * (__expf(c[j][2] - sub1) + EPSK);
                float q3 = RATIO * (__expf(c[j][3] - sub1) + EPSK);
                dp0 += q0 * sKs[m] + q1 * sKs[m + 1];
                dp1 += q2 * sKs[m] + q3 * sKs[m + 1];
                ushort h0 = bfu(q0), h1 = bfu(q1), h2 = bfu(q2), h3 = bfu(q3);
                uint32_t hv0 = ((uint32_t)h1 << 16) | h0;
                uint32_t hv1 = ((uint32_t)h3 << 16) | h2;
                uint32_t lv0 = ((uint32_t)bfu(q1 - __bfloat162float(__ushort_as_bfloat16(h1))) << 16)
                             | bfu(q0 - __bfloat162float(__ushort_as_bfloat16(h0)));
                uint32_t lv1 = ((uint32_t)bfu(q3 - __bfloat162float(__ushort_as_bfloat16(h3))) << 16)
                             | bfu(q2 - __bfloat162float(__ushort_as_bfloat16(h2)));
                *(uint32_t*)(QFh + baseA + m) = hv0;
                *(uint32_t*)(QFl + baseA + m) = lv0;
                *(uint32_t*)(QFh + baseB + m) = hv1;
                *(uint32_t*)(QFl + baseB + m) = lv1;
            }
            dp0 += __shfl_xor_sync(0xffffffffu, dp0, 1);
            dp0 += __shfl_xor_sync(0xffffffffu, dp0, 2);
            dp1 += __shfl_xor_sync(0xffffffffu, dp1, 1);
            dp1 += __shfl_xor_sync(0xffffffffu, dp1, 2);
            if ((lane & 3) == 0) {
                sDpP[w * 16 + r0]     = dp0;
                sDpP[w * 16 + r0 + 8] = dp1;
            }
        }
        __syncthreads();

        if (tid < 16) {
            float s = sDpP[tid];
#pragma unroll
            for (int ww = 1; ww < 8; ww++) s += sDpP[ww * 16 + tid];
            Dinv[(size_t)bh * NSEQ + n0 + tid] = 1.f / s;
        }
    }
}

// ---------------- yv_gemm (R9, unchanged) ----------------
#define YV_NCHUNK 12
#define YV_ASTG  16384

__global__ __launch_bounds__(256, 2) void yv_gemm(
    const __nv_bfloat16* __restrict__ QFh, const __nv_bfloat16* __restrict__ QFl,
    __nv_bfloat16* __restrict__ OutH, __nv_bfloat16* __restrict__ OutL)
{
    extern __shared__ __align__(128) char gsm[];
    const uint32_t smem_base = smem_u32(gsm);
    const uint32_t sBH = smem_base + 49152;
    const uint32_t sBL = smem_base + 81920;

    const int tid  = threadIdx.x;
    const int lane = tid & 31;
    const int wid  = tid >> 5;
    const int wm   = wid & 1;
    const int wn   = wid >> 1;
    const int bh   = blockIdx.y;
    const int bm   = blockIdx.x * 128;
    const int b_   = bh >> 4;
    const int h_   = bh & 15;

    {
        const float* cbase = g_ctx + (size_t)bh * MM * DD;
#pragma unroll
        for (int t = 0; t < 64; t++) {
            int e = t * 256 + tid;
            int m = e >> 6, d = e & 63;
            float val = cbase[e];
            __nv_bfloat16 h = __float2bfloat16(val);
            __nv_bfloat16 l = __float2bfloat16(val - __bfloat162float(h));
            int mc = m & 63;
            uint32_t off = (uint32_t)((m >> 6) * 8192 + d * 128 + (((mc >> 3) ^ (d & 7)) << 4) + (mc & 7) * 2);
            *(ushort*)((char*)gsm + 49152 + off) = __bfloat16_as_ushort(h);
            *(ushort*)((char*)gsm + 81920 + off) = __bfloat16_as_ushort(l);
        }
    }

    const __nv_bfloat16* pA[3] = {QFh, QFh, QFl};

    float c[4][2][4];
#pragma unroll
    for (int i = 0; i < 4; i++)
#pragma unroll
        for (int j = 0; j < 2; j++)
#pragma unroll
            for (int q = 0; q < 4; q++) c[i][j][q] = 0.f;

    auto prefetchA = [&](int s, int stage) {
        if (s < YV_NCHUNK) {
            const int ph = s >> 2;
            const int kk = (s & 3) << 6;
            const __nv_bfloat16* gA = pA[ph] + (size_t)bh * NSEQ * MM;
            const uint32_t aB = smem_base + stage * YV_ASTG;
#pragma unroll
            for (int it = 0; it < 4; it++) {
                int idx = it * 256 + tid;
                int row = idx >> 3;
                int pb  = idx & 7;
                uint32_t doff = row * 128 + ((pb ^ (row & 7)) << 4);
                const void* srcA = gA + (size_t)(bm + row) * MM + kk + pb * 8;
                asm volatile("cp.async.cg.shared.global [%0], [%1], 16;" :: "r"(aB + doff), "l"(srcA));
            }
        }
        asm volatile("cp.async.commit_group;" ::: "memory");
    };

    prefetchA(0, 0);
    prefetchA(1, 1);
    __syncthreads();

    for (int s = 0; s < YV_NCHUNK; s++) {
        const int stage = s % 3;
        asm volatile("cp.async.wait_group 1;" ::: "memory");
        __syncthreads();
        prefetchA(s + 2, (s + 2) % 3);

        const uint32_t cA = smem_base + stage * YV_ASTG;
        const int ph = s >> 2;
        const uint32_t cBbase = (ph == 1) ? sBL : sBH;
        const uint32_t cB = cBbase + (uint32_t)((s & 3) * 8192);

#pragma unroll
        for (int ks = 0; ks < 4; ks++) {
            uint32_t bf[2][2];
            {
                int row = wn * 16 + ((lane >> 4) << 3) + (lane & 7);
                int pb  = ks * 2 + ((lane >> 3) & 1);
                uint32_t ad = cB + row * 128 + ((pb ^ (row & 7)) << 4);
                uint32_t t4[4];
                ldmx4(t4, ad);
                bf[0][0] = t4[0]; bf[0][1] = t4[1];
                bf[1][0] = t4[2]; bf[1][1] = t4[3];
            }
#pragma unroll
            for (int i = 0; i < 4; i++) {
                int r0 = wm * 64 + i * 16;
                int row = r0 + (((lane >> 3) & 1) << 3) + (lane & 7);
                int pb  = ks * 2 + ((lane >> 4) & 1);
                uint32_t ad = cA + row * 128 + ((pb ^ (row & 7)) << 4);
                uint32_t af[4];
                ldmx4(af, ad);
#pragma unroll
                for (int j = 0; j < 2; j++)
                    mma16816(c[i][j], af, bf[j]);
            }
        }
        __syncthreads();
    }

#pragma unroll
    for (int i = 0; i < 4; i++) {
        int rl = wm * 64 + i * 16 + (lane >> 2);
        int nA = bm + rl;
        int nB = nA + 8;
        float dA = g_dinv[(size_t)bh * NSEQ + nA];
        float dB = g_dinv[(size_t)bh * NSEQ + nB];
#pragma unroll
        for (int j = 0; j < 2; j++) {
            int col = wn * 16 + j * 8 + (lane & 3) * 2;
            float vA0 = c[i][j][0] * dA, vA1 = c[i][j][1] * dA;
            float vB0 = c[i][j][2] * dB, vB1 = c[i][j][3] * dB;
            __nv_bfloat16 hA0 = __float2bfloat16(vA0), hA1 = __float2bfloat16(vA1);
            __nv_bfloat16 hB0 = __float2bfloat16(vB0), hB1 = __float2bfloat16(vB1);
            uint32_t hvA = ((uint32_t)__bfloat16_as_ushort(hA1) << 16) | __bfloat16_as_ushort(hA0);
            uint32_t lvA = ((uint32_t)__bfloat16_as_ushort(__float2bfloat16(vA1 - __bfloat162float(hA1))) << 16)
                         | __bfloat16_as_ushort(__float2bfloat16(vA0 - __bfloat162float(hA0)));
            uint32_t hvB = ((uint32_t)__bfloat16_as_ushort(hB1) << 16) | __bfloat16_as_ushort(hB0);
            uint32_t lvB = ((uint32_t)__bfloat16_as_ushort(__float2bfloat16(vB1 - __bfloat162float(hB1))) << 16)
                         | __bfloat16_as_ushort(__float2bfloat16(vB0 - __bfloat162float(hB0)));
            size_t idxA = ((size_t)(b_ * NSEQ + nA)) * EE + h_ * DD + col;
            size_t idxB = ((size_t)(b_ * NSEQ + nB)) * EE + h_ * DD + col;
            *(uint32_t*)(OutH + idxA) = hvA;
            *(uint32_t*)(OutL + idxA) = lvA;
            *(uint32_t*)(OutH + idxB) = hvB;
            *(uint32_t*)(OutL + idxB) = lvB;
        }
    }
}

// ---------------- launch ----------------
extern "C" void kernel_launch(void* const* d_in, const int* in_sizes, int n_in,
                              void* d_out, int out_size) {
    const float* x    = (const float*)d_in[0];
    const float* Wq   = (const float*)d_in[1];
    const float* bq   = (const float*)d_in[2];
    const float* Wk   = (const float*)d_in[3];
    const float* bk   = (const float*)d_in[4];
    const float* Wv   = (const float*)d_in[5];
    const float* bv   = (const float*)d_in[6];
    const float* Wo   = (const float*)d_in[7];
    const float* bo   = (const float*)d_in[8];
    const float* proj = (const float*)d_in[9];
    float* out = (float*)d_out;

    float *pq, *pk, *pv, *pdinv;
    __nv_bfloat16 *pah, *pal, *pwh, *pwl, *pqfh, *pqfl;
    cudaGetSymbolAddress((void**)&pq,   g_q);
    cudaGetSymbolAddress((void**)&pk,   g_k);
    cudaGetSymbolAddress((void**)&pv,   g_v);
    cudaGetSymbolAddress((void**)&pdinv, g_dinv);
    cudaGetSymbolAddress((void**)&pah,  g_ah);
    cudaGetSymbolAddress((void**)&pal,  g_al);
    cudaGetSymbolAddress((void**)&pwh,  g_wh);
    cudaGetSymbolAddress((void**)&pwl,  g_wl);
    cudaGetSymbolAddress((void**)&pqfh, g_qfh);
    cudaGetSymbolAddress((void**)&pqfl, g_qfl);

    const int GEMM_SMEM = 3 * STG_BYTES;
    const int YV_SMEM   = 3 * YV_ASTG + 2 * 32768;
    cudaFuncSetAttribute(gemm_mma<0>, cudaFuncAttributeMaxDynamicSharedMemorySize, GEMM_SMEM);
    cudaFuncSetAttribute(gemm_mma<1>, cudaFuncAttributeMaxDynamicSharedMemorySize, GEMM_SMEM);
    cudaFuncSetAttribute(ctx_fused,  cudaFuncAttributeMaxDynamicSharedMemorySize, CTXF_SMEM_BYTES);
    cudaFuncSetAttribute(qf_kernel,  cudaFuncAttributeMaxDynamicSharedMemorySize, QF_SMEM_BYTES);
    cudaFuncSetAttribute(yv_gemm,    cudaFuncAttributeMaxDynamicSharedMemorySize, YV_SMEM);

    dim3 gg(EE / 128, TT / 128);

    init_kernel<<<1, 32>>>();

    split_kernel<<<2048, 256>>>(x, pah, pal, TT * EE / 4);

    split_kernel<<<512, 256>>>(Wq, pwh, pwl, EE * EE / 4);
    gemm_mma<1><<<gg, 256, GEMM_SMEM>>>(pah, pal, pwh, pwl, bq, pq);
    split_kernel<<<512, 256>>>(Wk, pwh, pwl, EE * EE / 4);
    gemm_mma<1><<<gg, 256, GEMM_SMEM>>>(pah, pal, pwh, pwl, bk, pk);
    split_kernel<<<512, 256>>>(Wv, pwh, pwl, EE * EE / 4);
    gemm_mma<1><<<gg, 256, GEMM_SMEM>>>(pah, pal, pwh, pwl, bv, pv);

    ctx_fused<<<dim3(BHn, NSEG), 256, CTXF_SMEM_BYTES>>>(pk, pv, proj);
    ctx_reduce_kernel<<<(BHn * MM * DD + 255) / 256, 256>>>();

    qf_kernel<<<dim3(BHn, 16), 256, QF_SMEM_BYTES>>>(pq, proj, pqfh, pqfl, pdinv);

    yv_gemm<<<dim3(NSEQ / 128, BHn), 256, YV_SMEM>>>(pqfh, pqfl, pah, pal);

    split_kernel<<<512, 256>>>(Wo, pwh, pwl, EE * EE / 4);
    gemm_mma<0><<<gg, 256, GEMM_SMEM>>>(pah, pal, pwh, pwl, bo, out);
}

// round 16
// speedup vs baseline: 1.2890x; 1.0087x over previous
#include <cuda_runtime.h>
#include <cuda_bf16.h>
#include <math.h>
#include <stdint.h>

// Problem constants
#define BB   4
#define NSEQ 4096
#define EE   1024
#define HH   16
#define DD   64
#define MM   256
#define TT   (BB*NSEQ)     // 16384
#define BHn  (BB*HH)       // 64
#define NSEG 8

#define RATIO 0.0625f
#define EPSK  1e-4f
#define SCQ   0.3535533905932738f   // 64^-0.25

// ---------------- device scratch ----------------
__device__ float g_q[(size_t)BHn*NSEQ*DD];
__device__ float g_k[(size_t)BHn*NSEQ*DD];
__device__ float g_v[(size_t)BHn*NSEQ*DD];
__device__ float g_ksum[BHn*MM];
__device__ float g_ksump[(size_t)NSEG*BHn*MM];
__device__ float g_svp[(size_t)NSEG*BHn*DD];
__device__ float g_ctxp[(size_t)NSEG*BHn*MM*DD];
__device__ float g_ctx[BHn*MM*DD];
__device__ float g_dinv[(size_t)BHn*NSEQ];
__device__ float g_kstab;
__device__ __nv_bfloat16 g_ah[(size_t)TT*EE];
__device__ __nv_bfloat16 g_al[(size_t)TT*EE];
__device__ __nv_bfloat16 g_wh[(size_t)3*EE*EE];   // 3 weight slots (Q/K/V; slot0 reused for Wo)
__device__ __nv_bfloat16 g_wl[(size_t)3*EE*EE];
__device__ __nv_bfloat16 g_qfh[(size_t)BHn*NSEQ*MM];
__device__ __nv_bfloat16 g_qfl[(size_t)BHn*NSEQ*MM];

// ---------------- helpers ----------------
__device__ __forceinline__ void atomicMaxFloat(float* addr, float v) {
    if (v >= 0.f) atomicMax((int*)addr, __float_as_int(v));
    else          atomicMin((unsigned int*)addr, __float_as_uint(v));
}

__global__ void init_kernel() {
    if (blockIdx.x == 0 && threadIdx.x == 0) g_kstab = -INFINITY;
}

__device__ __forceinline__ uint32_t smem_u32(const void* p) {
    uint32_t a;
    asm("{ .reg .u64 t; cvta.to.shared.u64 t, %1; cvt.u32.u64 %0, t; }" : "=r"(a) : "l"(p));
    return a;
}

__device__ __forceinline__ void mma16816(float* c, const uint32_t* a, const uint32_t* b) {
    asm volatile(
        "mma.sync.aligned.m16n8k16.row.col.f32.bf16.bf16.f32 "
        "{%0,%1,%2,%3},{%4,%5,%6,%7},{%8,%9},{%0,%1,%2,%3};"
        : "+f"(c[0]), "+f"(c[1]), "+f"(c[2]), "+f"(c[3])
        : "r"(a[0]), "r"(a[1]), "r"(a[2]), "r"(a[3]), "r"(b[0]), "r"(b[1]));
}

__device__ __forceinline__ void ldmx4(uint32_t* r, uint32_t addr) {
    asm volatile("ldmatrix.sync.aligned.m8n8.x4.shared.b16 {%0,%1,%2,%3}, [%4];"
        : "=r"(r[0]), "=r"(r[1]), "=r"(r[2]), "=r"(r[3]) : "r"(addr));
}
__device__ __forceinline__ void ldmx4t(uint32_t* r, uint32_t addr) {
    asm volatile("ldmatrix.sync.aligned.m8n8.x4.trans.shared.b16 {%0,%1,%2,%3}, [%4];"
        : "=r"(r[0]), "=r"(r[1]), "=r"(r[2]), "=r"(r[3]) : "r"(addr));
}

__device__ __forceinline__ ushort bfu(float x) {
    return __bfloat16_as_ushort(__float2bfloat16(x));
}

// ---------------- fp32 -> bf16 hi/lo split ----------------
__device__ __forceinline__ void split_body(const float* __restrict__ src,
    __nv_bfloat16* __restrict__ hi, __nv_bfloat16* __restrict__ lo,
    int n4, int start, int stride)
{
    const float4* s4 = (const float4*)src;
    uint2* h2 = (uint2*)hi;
    uint2* l2 = (uint2*)lo;
    for (int i = start; i < n4; i += stride) {
        float4 v = s4[i];
        __nv_bfloat16 h0 = __float2bfloat16(v.x);
        __nv_bfloat16 h1 = __float2bfloat16(v.y);
        __nv_bfloat16 h2b = __float2bfloat16(v.z);
        __nv_bfloat16 h3 = __float2bfloat16(v.w);
        __nv_bfloat16 l0 = __float2bfloat16(v.x - __bfloat162float(h0));
        __nv_bfloat16 l1 = __float2bfloat16(v.y - __bfloat162float(h1));
        __nv_bfloat16 l2b = __float2bfloat16(v.z - __bfloat162float(h2b));
        __nv_bfloat16 l3 = __float2bfloat16(v.w - __bfloat162float(h3));
        uint2 hv, lv;
        hv.x = ((uint32_t)__bfloat16_as_ushort(h1) << 16) | __bfloat16_as_ushort(h0);
        hv.y = ((uint32_t)__bfloat16_as_ushort(h3) << 16) | __bfloat16_as_ushort(h2b);
        lv.x = ((uint32_t)__bfloat16_as_ushort(l1) << 16) | __bfloat16_as_ushort(l0);
        lv.y = ((uint32_t)__bfloat16_as_ushort(l3) << 16) | __bfloat16_as_ushort(l2b);
        h2[i] = hv;
        l2[i] = lv;
    }
}

__global__ __launch_bounds__(256) void split_kernel(
    const float* __restrict__ src, __nv_bfloat16* __restrict__ hi,
    __nv_bfloat16* __restrict__ lo, int n4)
{
    split_body(src, hi, lo, n4, blockIdx.x * 256 + threadIdx.x, gridDim.x * 256);
}

// three weight matrices in one launch: group g = blockIdx.x/512 -> slot g
__global__ __launch_bounds__(256) void split3_kernel(
    const float* __restrict__ s0, const float* __restrict__ s1, const float* __restrict__ s2,
    __nv_bfloat16* __restrict__ hB, __nv_bfloat16* __restrict__ lB, int n4)
{
    int g   = blockIdx.x >> 9;           // 0..2
    int bid = blockIdx.x & 511;
    const float* src = (g == 0) ? s0 : (g == 1) ? s1 : s2;
    split_body(src, hB + (size_t)g * EE * EE, lB + (size_t)g * EE * EE,
               n4, bid * 256 + threadIdx.x, 512 * 256);
}

// ---------------- bf16-split mma.sync GEMM v3: fused 3-term per K-chunk ----------------
// QKV=1: grid (24, 128); blockIdx.x>>3 selects weight slot / bias / output (head-split).
// QKV=0: grid (8, 128); slot 0; row-major output.
#define NCHUNK 32
#define STG_BYTES 32768

template<int QKV>
__global__ __launch_bounds__(256, 2) void gemm_mma(
    const __nv_bfloat16* __restrict__ Ah, const __nv_bfloat16* __restrict__ Al,
    const __nv_bfloat16* __restrict__ WhB, const __nv_bfloat16* __restrict__ WlB,
    const float* __restrict__ bias0, const float* __restrict__ bias1, const float* __restrict__ bias2,
    float* __restrict__ C0, float* __restrict__ C1, float* __restrict__ C2)
{
    extern __shared__ __align__(128) char gsm[];

    const int tid  = threadIdx.x;
    const int lane = tid & 31;
    const int wid  = tid >> 5;
    const int wm   = wid & 1;
    const int wn   = wid >> 1;
    const int bm   = blockIdx.y * 128;
    const int wsel = QKV ? (blockIdx.x >> 3) : 0;
    const int bn   = (blockIdx.x & 7) * 128;

    const __nv_bfloat16* Wh = WhB + (size_t)wsel * EE * EE;
    const __nv_bfloat16* Wl = WlB + (size_t)wsel * EE * EE;
    const float* bias = (wsel == 0) ? bias0 : (wsel == 1) ? bias1 : bias2;
    float* C = (wsel == 0) ? C0 : (wsel == 1) ? C1 : C2;

    float c[4][4][4];
#pragma unroll
    for (int i = 0; i < 4; i++)
#pragma unroll
        for (int j = 0; j < 4; j++)
#pragma unroll
            for (int q = 0; q < 4; q++) c[i][j][q] = 0.f;

    const uint32_t smem_base = smem_u32(gsm);

    auto prefetch = [&](int s, int stage) {
        if (s < NCHUNK) {
            const int kk = s << 5;
            const uint32_t st = smem_base + stage * STG_BYTES;
#pragma unroll
            for (int it = 0; it < 2; it++) {
                int idx = it * 256 + tid;
                int row = idx >> 2;
                int pb  = idx & 3;
                uint32_t doff = row * 64 + ((pb ^ ((row >> 1) & 3)) << 4);
                const void* sAh = Ah + (size_t)(bm + row) * EE + kk + pb * 8;
                const void* sAl = Al + (size_t)(bm + row) * EE + kk + pb * 8;
                const void* sBh = Wh + (size_t)(bn + row) * EE + kk + pb * 8;
                const void* sBl = Wl + (size_t)(bn + row) * EE + kk + pb * 8;
                asm volatile("cp.async.cg.shared.global [%0], [%1], 16;" :: "r"(st + doff),         "l"(sAh));
                asm volatile("cp.async.cg.shared.global [%0], [%1], 16;" :: "r"(st + 8192 + doff),  "l"(sAl));
                asm volatile("cp.async.cg.shared.global [%0], [%1], 16;" :: "r"(st + 16384 + doff), "l"(sBh));
                asm volatile("cp.async.cg.shared.global [%0], [%1], 16;" :: "r"(st + 24576 + doff), "l"(sBl));
            }
        }
        asm volatile("cp.async.commit_group;" ::: "memory");
    };

    prefetch(0, 0);
    prefetch(1, 1);

    for (int s = 0; s < NCHUNK; s++) {
        const int stage = s % 3;
        asm volatile("cp.async.wait_group 1;" ::: "memory");
        __syncthreads();
        prefetch(s + 2, (s + 2) % 3);

        const uint32_t cAh = smem_base + stage * STG_BYTES;
        const uint32_t cAl = cAh + 8192;
        const uint32_t cBh = cAh + 16384;
        const uint32_t cBl = cAh + 24576;
#pragma unroll
        for (int ks = 0; ks < 2; ks++) {
            uint32_t bfh[4][2], bfl[4][2];
#pragma unroll
            for (int jb = 0; jb < 2; jb++) {
                int row = wn * 32 + jb * 16 + ((lane >> 4) << 3) + (lane & 7);
                int pb  = ks * 2 + ((lane >> 3) & 1);
                uint32_t doff = row * 64 + ((pb ^ ((row >> 1) & 3)) << 4);
                uint32_t t4[4];
                ldmx4(t4, cBh + doff);
                bfh[jb * 2][0] = t4[0]; bfh[jb * 2][1] = t4[1];
                bfh[jb * 2 + 1][0] = t4[2]; bfh[jb * 2 + 1][1] = t4[3];
                ldmx4(t4, cBl + doff);
                bfl[jb * 2][0] = t4[0]; bfl[jb * 2][1] = t4[1];
                bfl[jb * 2 + 1][0] = t4[2]; bfl[jb * 2 + 1][1] = t4[3];
            }
#pragma unroll
            for (int i = 0; i < 4; i++) {
                int row = wm * 64 + i * 16 + (((lane >> 3) & 1) << 3) + (lane & 7);
                int pb  = ks * 2 + ((lane >> 4) & 1);
                uint32_t doff = row * 64 + ((pb ^ ((row >> 1) & 3)) << 4);
                uint32_t afh[4], afl[4];
                ldmx4(afh, cAh + doff);
                ldmx4(afl, cAl + doff);
#pragma unroll
                for (int j = 0; j < 4; j++) {
                    mma16816(c[i][j], afh, bfh[j]);
                    mma16816(c[i][j], afh, bfl[j]);
                    mma16816(c[i][j], afl, bfh[j]);
                }
            }
        }
    }

#pragma unroll
    for (int i = 0; i < 4; i++) {
        int r = bm + wm * 64 + i * 16 + (lane >> 2);
#pragma unroll
        for (int j = 0; j < 4; j++) {
            int col = bn + wn * 32 + j * 8 + (lane & 3) * 2;
            float b0 = bias[col], b1 = bias[col + 1];
            float2 v0 = make_float2(c[i][j][0] + b0, c[i][j][1] + b1);
            float2 v1 = make_float2(c[i][j][2] + b0, c[i][j][3] + b1);
            if (QKV == 0) {
                *(float2*)(C + (size_t)r * EE + col)       = v0;
                *(float2*)(C + (size_t)(r + 8) * EE + col) = v1;
            } else {
                int h_ = col >> 6, d0 = col & 63;
                int b_ = r >> 12, n_ = r & 4095;
                size_t base = ((size_t)(b_ * HH + h_) * NSEQ);
                *(float2*)(C + (base + n_)     * DD + d0) = v0;
                *(float2*)(C + (base + n_ + 8) * DD + d0) = v1;
            }
        }
    }
}

// ---------------- ctx_fused v3: dd AND U on tensor cores (R13, unchanged) ----------------
#define CTXF_SMEM_BYTES 94272

__global__ __launch_bounds__(256, 2) void ctx_fused(
    const float* __restrict__ K, const float* __restrict__ V,
    const float* __restrict__ proj)
{
    extern __shared__ __align__(128) char csm[];
    const uint32_t smem_base = smem_u32(csm);
    const uint32_t sPTh = smem_base;
    const uint32_t sPTl = smem_base + 32768;
    const uint32_t sXh  = smem_base + 65536;
    const uint32_t sXl  = smem_base + 67584;
    const uint32_t sKFh = smem_base + 69632;
    const uint32_t sKFl = smem_base + 77824;
    const uint32_t sVh  = smem_base + 86016;
    const uint32_t sVl  = smem_base + 88064;
    float* sV32  = (float*)(csm + 90112);
    float* sDiag = (float*)(csm + 94208);
    __shared__ float swm[8];

    const int tid = threadIdx.x;
    const int bh  = blockIdx.x;
    const int seg = blockIdx.y;
    const int lane = tid & 31;
    const int w    = tid >> 5;

    {
        const float4* pr = (const float4*)(proj + tid * DD);
#pragma unroll
        for (int t = 0; t < 16; t++) {
            float4 v = pr[t];
            ushort h0 = bfu(v.x), h1 = bfu(v.y), h2 = bfu(v.z), h3 = bfu(v.w);
            ushort l0 = bfu(v.x - __bfloat162float(__ushort_as_bfloat16(h0)));
            ushort l1 = bfu(v.y - __bfloat162float(__ushort_as_bfloat16(h1)));
            ushort l2 = bfu(v.z - __bfloat162float(__ushort_as_bfloat16(h2)));
            ushort l3 = bfu(v.w - __bfloat162float(__ushort_as_bfloat16(h3)));
            uint2 hv, lv;
            hv.x = ((uint32_t)h1 << 16) | h0; hv.y = ((uint32_t)h3 << 16) | h2;
            lv.x = ((uint32_t)l1 << 16) | l0; lv.y = ((uint32_t)l3 << 16) | l2;
            uint32_t off = (uint32_t)(tid * 128 + (((t >> 1) ^ (tid & 7)) << 4) + (t & 1) * 8);
            *(uint2*)(csm + off)         = hv;
            *(uint2*)(csm + 32768 + off) = lv;
        }
    }

    float uacc[2][8][4];
#pragma unroll
    for (int i = 0; i < 2; i++)
#pragma unroll
        for (int j = 0; j < 8; j++)
#pragma unroll
            for (int q = 0; q < 4; q++) uacc[i][j][q] = 0.f;
    float kaccv[8];
#pragma unroll
    for (int i = 0; i < 8; i++) kaccv[i] = 0.f;
    float svacc = 0.f;
    float ddmax = -1e30f;

    for (int it = 0; it < 32; it++) {
        const int n0 = seg * 512 + it * 16;
        __syncthreads();

        {
            int row = tid >> 4;
            int t   = tid & 15;
            const float* kp = K + ((size_t)bh * NSEQ + n0 + row) * DD + t * 4;
            const float* vp = V + ((size_t)bh * NSEQ + n0 + row) * DD + t * 4;
            float4 kv = *(const float4*)kp;
            float4 vv = *(const float4*)vp;
            kv.x *= SCQ; kv.y *= SCQ; kv.z *= SCQ; kv.w *= SCQ;
            float ssq = kv.x * kv.x + kv.y * kv.y + kv.z * kv.z + kv.w * kv.w;
#pragma unroll
            for (int o = 8; o > 0; o >>= 1) ssq += __shfl_xor_sync(0xffffffffu, ssq, o);
            if (t == 0) sDiag[row] = 0.5f * ssq;

            uint32_t off = (uint32_t)(row * 128 + (((t >> 1) ^ (row & 7)) << 4) + (t & 1) * 8);
            {
                ushort h0 = bfu(kv.x), h1 = bfu(kv.y), h2 = bfu(kv.z), h3 = bfu(kv.w);
                ushort l0 = bfu(kv.x - __bfloat162float(__ushort_as_bfloat16(h0)));
                ushort l1 = bfu(kv.y - __bfloat162float(__ushort_as_bfloat16(h1)));
                ushort l2 = bfu(kv.z - __bfloat162float(__ushort_as_bfloat16(h2)));
                ushort l3 = bfu(kv.w - __bfloat162float(__ushort_as_bfloat16(h3)));
                uint2 hv, lv;
                hv.x = ((uint32_t)h1 << 16) | h0; hv.y = ((uint32_t)h3 << 16) | h2;
                lv.x = ((uint32_t)l1 << 16) | l0; lv.y = ((uint32_t)l3 << 16) | l2;
                *(uint2*)(csm + 65536 + off) = hv;
                *(uint2*)(csm + 67584 + off) = lv;
            }
            {
                ushort h0 = bfu(vv.x), h1 = bfu(vv.y), h2 = bfu(vv.z), h3 = bfu(vv.w);
                ushort l0 = bfu(vv.x - __bfloat162float(__ushort_as_bfloat16(h0)));
                ushort l1 = bfu(vv.y - __bfloat162float(__ushort_as_bfloat16(h1)));
                ushort l2 = bfu(vv.z - __bfloat162float(__ushort_as_bfloat16(h2)));
                ushort l3 = bfu(vv.w - __bfloat162float(__ushort_as_bfloat16(h3)));
                uint2 hv, lv;
                hv.x = ((uint32_t)h1 << 16) | h0; hv.y = ((uint32_t)h3 << 16) | h2;
                lv.x = ((uint32_t)l1 << 16) | l0; lv.y = ((uint32_t)l3 << 16) | l2;
                *(uint2*)(csm + 86016 + off) = hv;
                *(uint2*)(csm + 88064 + off) = lv;
                *(float4*)(sV32 + row * 64 + t * 4) = vv;
            }
        }
        __syncthreads();

        {
            float c[4][4];
#pragma unroll
            for (int j = 0; j < 4; j++)
#pragma unroll
                for (int q = 0; q < 4; q++) c[j][q] = 0.f;

            const uint32_t pASrc[3] = {sXh, sXh, sXl};
            const uint32_t pBSrc[3] = {sPTh, sPTl, sPTh};
#pragma unroll
            for (int ph = 0; ph < 3; ph++) {
                const uint32_t cA = pASrc[ph];
                const uint32_t cB = pBSrc[ph];
#pragma unroll
                for (int ks = 0; ks < 4; ks++) {
                    int rowA = (((lane >> 3) & 1) << 3) + (lane & 7);
                    int pbA  = ks * 2 + ((lane >> 4) & 1);
                    uint32_t adA = cA + rowA * 128 + ((pbA ^ (rowA & 7)) << 4);
                    uint32_t af[4];
                    ldmx4(af, adA);
                    uint32_t bf[4][2];
#pragma unroll
                    for (int jb = 0; jb < 2; jb++) {
                        int rowB = w * 32 + jb * 16 + ((lane >> 4) << 3) + (lane & 7);
                        int pbB  = ks * 2 + ((lane >> 3) & 1);
                        uint32_t adB = cB + rowB * 128 + ((pbB ^ (rowB & 7)) << 4);
                        uint32_t t4[4];
                        ldmx4(t4, adB);
                        bf[jb * 2][0] = t4[0]; bf[jb * 2][1] = t4[1];
                        bf[jb * 2 + 1][0] = t4[2]; bf[jb * 2 + 1][1] = t4[3];
                    }
#pragma unroll
                    for (int j = 0; j < 4; j++)
                        mma16816(c[j], af, bf[j]);
                }
            }

            const int r0 = lane >> 2;
            const int mb = w * 32 + (lane & 3) * 2;
            const float dg0 = sDiag[r0];
            const float dg1 = sDiag[r0 + 8];
#pragma unroll
            for (int j = 0; j < 4; j++) {
                int m = mb + j * 8;
                float v0 = c[j][0], v1 = c[j][1], v2 = c[j][2], v3 = c[j][3];
                ddmax = fmaxf(ddmax, fmaxf(fmaxf(v0, v1), fmaxf(v2, v3)));
                float e0 = __expf(v0 - dg0), e1 = __expf(v1 - dg0);
                float e2 = __expf(v2 - dg1), e3 = __expf(v3 - dg1);

                uint32_t off0 = (uint32_t)(r0 * 512 + (((m >> 3) ^ (r0 & 7)) << 4) + (m & 7) * 2);
                uint32_t off1 = off0 + 8 * 512;
                ushort h0 = bfu(e0), h1 = bfu(e1), h2 = bfu(e2), h3 = bfu(e3);
                *(uint32_t*)(csm + 69632 + off0) = ((uint32_t)h1 << 16) | h0;
                *(uint32_t*)(csm + 69632 + off1) = ((uint32_t)h3 << 16) | h2;
                *(uint32_t*)(csm + 77824 + off0) =
                    ((uint32_t)bfu(e1 - __bfloat162float(__ushort_as_bfloat16(h1))) << 16)
                    | bfu(e0 - __bfloat162float(__ushort_as_bfloat16(h0)));
                *(uint32_t*)(csm + 77824 + off1) =
                    ((uint32_t)bfu(e3 - __bfloat162float(__ushort_as_bfloat16(h3))) << 16)
                    | bfu(e2 - __bfloat162float(__ushort_as_bfloat16(h2)));

                float s0 = e0 + e2, s1 = e1 + e3;
                s0 += __shfl_xor_sync(0xffffffffu, s0, 4);
                s0 += __shfl_xor_sync(0xffffffffu, s0, 8);
                s0 += __shfl_xor_sync(0xffffffffu, s0, 16);
                s1 += __shfl_xor_sync(0xffffffffu, s1, 4);
                s1 += __shfl_xor_sync(0xffffffffu, s1, 8);
                s1 += __shfl_xor_sync(0xffffffffu, s1, 16);
                kaccv[j * 2]     += s0;
                kaccv[j * 2 + 1] += s1;
            }
        }
        __syncthreads();

        {
            const uint32_t pASrc[3] = {sKFh, sKFh, sKFl};
            const uint32_t pBSrc[3] = {sVh, sVl, sVh};
#pragma unroll
            for (int ph = 0; ph < 3; ph++) {
                uint32_t af[2][4];
#pragma unroll
                for (int mt = 0; mt < 2; mt++) {
                    int krow = (((lane >> 4) & 1) << 3) + (lane & 7);
                    int moff = w * 32 + mt * 16 + (((lane >> 3) & 1) << 3);
                    uint32_t ad = pASrc[ph] + krow * 512 + ((((moff >> 3)) ^ (krow & 7)) << 4);
                    ldmx4t(af[mt], ad);
                }
                uint32_t bf[8][2];
#pragma unroll
                for (int g = 0; g < 4; g++) {
                    int krow = (((lane >> 3) & 1) << 3) + (lane & 7);
                    int dch  = g * 2 + ((lane >> 4) & 1);
                    uint32_t ad = pBSrc[ph] + krow * 128 + ((dch ^ (krow & 7)) << 4);
                    uint32_t t4[4];
                    ldmx4t(t4, ad);
                    bf[g * 2][0] = t4[0];     bf[g * 2][1] = t4[1];
                    bf[g * 2 + 1][0] = t4[2]; bf[g * 2 + 1][1] = t4[3];
                }
#pragma unroll
                for (int mt = 0; mt < 2; mt++)
#pragma unroll
                    for (int dt = 0; dt < 8; dt++)
                        mma16816(uacc[mt][dt], af[mt], bf[dt]);
            }
        }

        if (tid < 64) {
#pragma unroll
            for (int r = 0; r < 16; r++) svacc += sV32[r * 64 + tid];
        }
    }

    if (lane < 4) {
        float* kp = g_ksump + ((size_t)seg * BHn + bh) * MM;
#pragma unroll
        for (int j = 0; j < 4; j++) {
            int m = w * 32 + lane * 2 + j * 8;
            kp[m]     = kaccv[j * 2];
            kp[m + 1] = kaccv[j * 2 + 1];
        }
    }
    if (tid < 64) g_svp[((size_t)seg * BHn + bh) * DD + tid] = svacc;

    float* cp = g_ctxp + ((size_t)seg * BHn + bh) * MM * DD;
#pragma unroll
    for (int mt = 0; mt < 2; mt++) {
        int r = w * 32 + mt * 16 + (lane >> 2);
#pragma unroll
        for (int dt = 0; dt < 8; dt++) {
            int col = dt * 8 + (lane & 3) * 2;
            *(float2*)(cp + (size_t)r * DD + col) =
                make_float2(uacc[mt][dt][0], uacc[mt][dt][1]);
            *(float2*)(cp + (size_t)(r + 8) * DD + col) =
                make_float2(uacc[mt][dt][2], uacc[mt][dt][3]);
        }
    }

#pragma unroll
    for (int o = 16; o > 0; o >>= 1)
        ddmax = fmaxf(ddmax, __shfl_xor_sync(0xffffffffu, ddmax, o));
    if (lane == 0) swm[w] = ddmax;
    __syncthreads();
    if (tid == 0) {
        float m = swm[0];
#pragma unroll
        for (int i = 1; i < 8; i++) m = fmaxf(m, swm[i]);
        atomicMaxFloat(&g_kstab, m);
    }
}

// ---------------- assemble ctx + ksum from unstabilized partials ----------------
__global__ __launch_bounds__(256) void ctx_reduce_kernel() {
    const float escale = __expf(-g_kstab);
    int i = blockIdx.x * 256 + threadIdx.x;
    if (i < BHn * MM * DD) {
        int bh = i >> 14;
        int d  = i & 63;
        float U = 0.f, Sv = 0.f;
#pragma unroll
        for (int seg = 0; seg < NSEG; seg++) {
            U  += g_ctxp[(size_t)seg * BHn * MM * DD + i];
            Sv += g_svp[((size_t)seg * BHn + bh) * DD + d];
        }
        g_ctx[i] = RATIO * (escale * U + EPSK * Sv);
    }
    if (i < BHn * MM) {
        float T = 0.f;
#pragma unroll
        for (int seg = 0; seg < NSEG; seg++)
            T += g_ksump[(size_t)seg * BHn * MM + i];
        g_ksum[i] = RATIO * (escale * T + EPSK * (float)NSEQ);
    }
}

// ---------------- qf_kernel v2: dd on tensor cores (R12, unchanged) ----------------
#define QF_SMEM_BYTES 71744

__global__ __launch_bounds__(256, 3) void qf_kernel(
    const float* __restrict__ Q, const float* __restrict__ proj,
    __nv_bfloat16* __restrict__ QFh, __nv_bfloat16* __restrict__ QFl,
    float* __restrict__ Dinv)
{
    extern __shared__ __align__(128) char qsm[];
    const uint32_t smem_base = smem_u32(qsm);
    const uint32_t sPTh = smem_base;
    const uint32_t sPTl = smem_base + 32768;
    const uint32_t sXh  = smem_base + 65536;
    const uint32_t sXl  = smem_base + 67584;
    float* sKs   = (float*)(qsm + 69632);
    float* sDiag = (float*)(qsm + 70656);
    float* sMaxP = (float*)(qsm + 70720);
    float* sDpP  = (float*)(qsm + 71232);

    const int tid = threadIdx.x;
    const int bh  = blockIdx.x;
    const int nblk = blockIdx.y * 256;
    const int lane = tid & 31;
    const int w    = tid >> 5;

    {
        const float4* pr = (const float4*)(proj + tid * DD);
#pragma unroll
        for (int t = 0; t < 16; t++) {
            float4 v = pr[t];
            ushort h0 = bfu(v.x), h1 = bfu(v.y), h2 = bfu(v.z), h3 = bfu(v.w);
            ushort l0 = bfu(v.x - __bfloat162float(__ushort_as_bfloat16(h0)));
            ushort l1 = bfu(v.y - __bfloat162float(__ushort_as_bfloat16(h1)));
            ushort l2 = bfu(v.z - __bfloat162float(__ushort_as_bfloat16(h2)));
            ushort l3 = bfu(v.w - __bfloat162float(__ushort_as_bfloat16(h3)));
            uint2 hv, lv;
            hv.x = ((uint32_t)h1 << 16) | h0; hv.y = ((uint32_t)h3 << 16) | h2;
            lv.x = ((uint32_t)l1 << 16) | l0; lv.y = ((uint32_t)l3 << 16) | l2;
            uint32_t off = (uint32_t)(tid * 128 + (((t >> 1) ^ (tid & 7)) << 4) + (t & 1) * 8);
            *(uint2*)(qsm + off)         = hv;
            *(uint2*)(qsm + 32768 + off) = lv;
        }
        sKs[tid] = g_ksum[bh * MM + tid];
    }

    for (int it = 0; it < 16; it++) {
        const int n0 = nblk + it * 16;
        __syncthreads();

        {
            int row = tid >> 4;
            int t   = tid & 15;
            const float* qp = Q + ((size_t)bh * NSEQ + n0 + row) * DD + t * 4;
            float4 kv = *(const float4*)qp;
            kv.x *= SCQ; kv.y *= SCQ; kv.z *= SCQ; kv.w *= SCQ;
            float ssq = kv.x * kv.x + kv.y * kv.y + kv.z * kv.z + kv.w * kv.w;
#pragma unroll
            for (int o = 8; o > 0; o >>= 1) ssq += __shfl_xor_sync(0xffffffffu, ssq, o);
            if (t == 0) sDiag[row] = 0.5f * ssq;

            ushort h0 = bfu(kv.x), h1 = bfu(kv.y), h2 = bfu(kv.z), h3 = bfu(kv.w);
            ushort l0 = bfu(kv.x - __bfloat162float(__ushort_as_bfloat16(h0)));
            ushort l1 = bfu(kv.y - __bfloat162float(__ushort_as_bfloat16(h1)));
            ushort l2 = bfu(kv.z - __bfloat162float(__ushort_as_bfloat16(h2)));
            ushort l3 = bfu(kv.w - __bfloat162float(__ushort_as_bfloat16(h3)));
            uint2 hv, lv;
            hv.x = ((uint32_t)h1 << 16) | h0; hv.y = ((uint32_t)h3 << 16) | h2;
            lv.x = ((uint32_t)l1 << 16) | l0; lv.y = ((uint32_t)l3 << 16) | l2;
            uint32_t off = (uint32_t)(row * 128 + (((t >> 1) ^ (row & 7)) << 4) + (t & 1) * 8);
            *(uint2*)(qsm + 65536 + off) = hv;
            *(uint2*)(qsm + 67584 + off) = lv;
        }
        __syncthreads();

        float c[4][4];
#pragma unroll
        for (int j = 0; j < 4; j++)
#pragma unroll
            for (int q = 0; q < 4; q++) c[j][q] = 0.f;
        {
            const uint32_t pASrc[3] = {sXh, sXh, sXl};
            const uint32_t pBSrc[3] = {sPTh, sPTl, sPTh};
#pragma unroll
            for (int ph = 0; ph < 3; ph++) {
                const uint32_t cA = pASrc[ph];
                const uint32_t cB = pBSrc[ph];
#pragma unroll
                for (int ks = 0; ks < 4; ks++) {
                    int rowA = (((lane >> 3) & 1) << 3) + (lane & 7);
                    int pbA  = ks * 2 + ((lane >> 4) & 1);
                    uint32_t adA = cA + rowA * 128 + ((pbA ^ (rowA & 7)) << 4);
                    uint32_t af[4];
                    ldmx4(af, adA);
                    uint32_t bf[4][2];
#pragma unroll
                    for (int jb = 0; jb < 2; jb++) {
                        int rowB = w * 32 + jb * 16 + ((lane >> 4) << 3) + (lane & 7);
                        int pbB  = ks * 2 + ((lane >> 3) & 1);
                        uint32_t adB = cB + rowB * 128 + ((pbB ^ (rowB & 7)) << 4);
                        uint32_t t4[4];
                        ldmx4(t4, adB);
                        bf[jb * 2][0] = t4[0]; bf[jb * 2][1] = t4[1];
                        bf[jb * 2 + 1][0] = t4[2]; bf[jb * 2 + 1][1] = t4[3];
                    }
#pragma unroll
                    for (int j = 0; j < 4; j++)
                        mma16816(c[j], af, bf[j]);
                }
            }
        }

        const int r0 = lane >> 2;

        {
            float mx0 = -1e30f, mx1 = -1e30f;
#pragma unroll
            for (int j = 0; j < 4; j++) {
                mx0 = fmaxf(mx0, fmaxf(c[j][0], c[j][1]));
                mx1 = fmaxf(mx1, fmaxf(c[j][2], c[j][3]));
            }
            mx0 = fmaxf(mx0, __shfl_xor_sync(0xffffffffu, mx0, 1));
            mx0 = fmaxf(mx0, __shfl_xor_sync(0xffffffffu, mx0, 2));
            mx1 = fmaxf(mx1, __shfl_xor_sync(0xffffffffu, mx1, 1));
            mx1 = fmaxf(mx1, __shfl_xor_sync(0xffffffffu, mx1, 2));
            if ((lane & 3) == 0) {
                sMaxP[w * 16 + r0]     = mx0;
                sMaxP[w * 16 + r0 + 8] = mx1;
            }
        }
        __syncthreads();

        {
            float fmx0 = sMaxP[r0], fmx1 = sMaxP[r0 + 8];
#pragma unroll
            for (int ww = 1; ww < 8; ww++) {
                fmx0 = fmaxf(fmx0, sMaxP[ww * 16 + r0]);
                fmx1 = fmaxf(fmx1, sMaxP[ww * 16 + r0 + 8]);
            }
            const float sub0 = sDiag[r0] + fmx0;
            const float sub1 = sDiag[r0 + 8] + fmx1;
            const int mb = w * 32 + (lane & 3) * 2;
            const size_t baseA = ((size_t)bh * NSEQ + n0 + r0) * MM;
            const size_t baseB = baseA + 8 * MM;
            float dp0 = 0.f, dp1 = 0.f;
#pragma unroll
            for (int j = 0; j < 4; j++) {
                int m = mb + j * 8;
                float q0 = RATIO * (__expf(c[j][0] - sub0) + EPSK);
                float q1 = RATIO * (__expf(c[j][1] - sub0) + EPSK);
                float q2 = RATIO * (__expf(c[j][2] - sub1) + EPSK);
                float q3 = RATIO * (__expf(c[j][3] - sub1) + EPSK);
                dp0 += q0 * sKs[m] + q1 * sKs[m + 1];
                dp1 += q2 * sKs[m] + q3 * sKs[m + 1];
                ushort h0 = bfu(q0), h1 = bfu(q1), h2 = bfu(q2), h3 = bfu(q3);
                uint32_t hv0 = ((uint32_t)h1 << 16) | h0;
                uint32_t hv1 = ((uint32_t)h3 << 16) | h2;
                uint32_t lv0 = ((uint32_t)bfu(q1 - __bfloat162float(__ushort_as_bfloat16(h1))) << 16)
                             | bfu(q0 - __bfloat162float(__ushort_as_bfloat16(h0)));
                uint32_t lv1 = ((uint32_t)bfu(q3 - __bfloat162float(__ushort_as_bfloat16(h3))) << 16)
                             | bfu(q2 - __bfloat162float(__ushort_as_bfloat16(h2)));
                *(uint32_t*)(QFh + baseA + m) = hv0;
                *(uint32_t*)(QFl + baseA + m) = lv0;
                *(uint32_t*)(QFh + baseB + m) = hv1;
                *(uint32_t*)(QFl + baseB + m) = lv1;
            }
            dp0 += __shfl_xor_sync(0xffffffffu, dp0, 1);
            dp0 += __shfl_xor_sync(0xffffffffu, dp0, 2);
            dp1 += __shfl_xor_sync(0xffffffffu, dp1, 1);
            dp1 += __shfl_xor_sync(0xffffffffu, dp1, 2);
            if ((lane & 3) == 0) {
                sDpP[w * 16 + r0]     = dp0;
                sDpP[w * 16 + r0 + 8] = dp1;
            }
        }
        __syncthreads();

        if (tid < 16) {
            float s = sDpP[tid];
#pragma unroll
            for (int ww = 1; ww < 8; ww++) s += sDpP[ww * 16 + tid];
            Dinv[(size_t)bh * NSEQ + n0 + tid] = 1.f / s;
        }
    }
}

// ---------------- yv_gemm (R9, unchanged) ----------------
#define YV_NCHUNK 12
#define YV_ASTG  16384

__global__ __launch_bounds__(256, 2) void yv_gemm(
    const __nv_bfloat16* __restrict__ QFh, const __nv_bfloat16* __restrict__ QFl,
    __nv_bfloat16* __restrict__ OutH, __nv_bfloat16* __restrict__ OutL)
{
    extern __shared__ __align__(128) char gsm[];
    const uint32_t smem_base = smem_u32(gsm);
    const uint32_t sBH = smem_base + 49152;
    const uint32_t sBL = smem_base + 81920;

    const int tid  = threadIdx.x;
    const int lane = tid & 31;
    const int wid  = tid >> 5;
    const int wm   = wid & 1;
    const int wn   = wid >> 1;
    const int bh   = blockIdx.y;
    const int bm   = blockIdx.x * 128;
    const int b_   = bh >> 4;
    const int h_   = bh & 15;

    {
        const float* cbase = g_ctx + (size_t)bh * MM * DD;
#pragma unroll
        for (int t = 0; t < 64; t++) {
            int e = t * 256 + tid;
            int m = e >> 6, d = e & 63;
            float val = cbase[e];
            __nv_bfloat16 h = __float2bfloat16(val);
            __nv_bfloat16 l = __float2bfloat16(val - __bfloat162float(h));
            int mc = m & 63;
            uint32_t off = (uint32_t)((m >> 6) * 8192 + d * 128 + (((mc >> 3) ^ (d & 7)) << 4) + (mc & 7) * 2);
            *(ushort*)((char*)gsm + 49152 + off) = __bfloat16_as_ushort(h);
            *(ushort*)((char*)gsm + 81920 + off) = __bfloat16_as_ushort(l);
        }
    }

    const __nv_bfloat16* pA[3] = {QFh, QFh, QFl};

    float c[4][2][4];
#pragma unroll
    for (int i = 0; i < 4; i++)
#pragma unroll
        for (int j = 0; j < 2; j++)
#pragma unroll
            for (int q = 0; q < 4; q++) c[i][j][q] = 0.f;

    auto prefetchA = [&](int s, int stage) {
        if (s < YV_NCHUNK) {
            const int ph = s >> 2;
            const int kk = (s & 3) << 6;
            const __nv_bfloat16* gA = pA[ph] + (size_t)bh * NSEQ * MM;
            const uint32_t aB = smem_base + stage * YV_ASTG;
#pragma unroll
            for (int it = 0; it < 4; it++) {
                int idx = it * 256 + tid;
                int row = idx >> 3;
                int pb  = idx & 7;
                uint32_t doff = row * 128 + ((pb ^ (row & 7)) << 4);
                const void* srcA = gA + (size_t)(bm + row) * MM + kk + pb * 8;
                asm volatile("cp.async.cg.shared.global [%0], [%1], 16;" :: "r"(aB + doff), "l"(srcA));
            }
        }
        asm volatile("cp.async.commit_group;" ::: "memory");
    };

    prefetchA(0, 0);
    prefetchA(1, 1);
    __syncthreads();

    for (int s = 0; s < YV_NCHUNK; s++) {
        const int stage = s % 3;
        asm volatile("cp.async.wait_group 1;" ::: "memory");
        __syncthreads();
        prefetchA(s + 2, (s + 2) % 3);

        const uint32_t cA = smem_base + stage * YV_ASTG;
        const int ph = s >> 2;
        const uint32_t cBbase = (ph == 1) ? sBL : sBH;
        const uint32_t cB = cBbase + (uint32_t)((s & 3) * 8192);

#pragma unroll
        for (int ks = 0; ks < 4; ks++) {
            uint32_t bf[2][2];
            {
                int row = wn * 16 + ((lane >> 4) << 3) + (lane & 7);
                int pb  = ks * 2 + ((lane >> 3) & 1);
                uint32_t ad = cB + row * 128 + ((pb ^ (row & 7)) << 4);
                uint32_t t4[4];
                ldmx4(t4, ad);
                bf[0][0] = t4[0]; bf[0][1] = t4[1];
                bf[1][0] = t4[2]; bf[1][1] = t4[3];
            }
#pragma unroll
            for (int i = 0; i < 4; i++) {
                int r0 = wm * 64 + i * 16;
                int row = r0 + (((lane >> 3) & 1) << 3) + (lane & 7);
                int pb  = ks * 2 + ((lane >> 4) & 1);
                uint32_t ad = cA + row * 128 + ((pb ^ (row & 7)) << 4);
                uint32_t af[4];
                ldmx4(af, ad);
#pragma unroll
                for (int j = 0; j < 2; j++)
                    mma16816(c[i][j], af, bf[j]);
            }
        }
        __syncthreads();
    }

#pragma unroll
    for (int i = 0; i < 4; i++) {
        int rl = wm * 64 + i * 16 + (lane >> 2);
        int nA = bm + rl;
        int nB = nA + 8;
        float dA = g_dinv[(size_t)bh * NSEQ + nA];
        float dB = g_dinv[(size_t)bh * NSEQ + nB];
#pragma unroll
        for (int j = 0; j < 2; j++) {
            int col = wn * 16 + j * 8 + (lane & 3) * 2;
            float vA0 = c[i][j][0] * dA, vA1 = c[i][j][1] * dA;
            float vB0 = c[i][j][2] * dB, vB1 = c[i][j][3] * dB;
            __nv_bfloat16 hA0 = __float2bfloat16(vA0), hA1 = __float2bfloat16(vA1);
            __nv_bfloat16 hB0 = __float2bfloat16(vB0), hB1 = __float2bfloat16(vB1);
            uint32_t hvA = ((uint32_t)__bfloat16_as_ushort(hA1) << 16) | __bfloat16_as_ushort(hA0);
            uint32_t lvA = ((uint32_t)__bfloat16_as_ushort(__float2bfloat16(vA1 - __bfloat162float(hA1))) << 16)
                         | __bfloat16_as_ushort(__float2bfloat16(vA0 - __bfloat162float(hA0)));
            uint32_t hvB = ((uint32_t)__bfloat16_as_ushort(hB1) << 16) | __bfloat16_as_ushort(hB0);
            uint32_t lvB = ((uint32_t)__bfloat16_as_ushort(__float2bfloat16(vB1 - __bfloat162float(hB1))) << 16)
                         | __bfloat16_as_ushort(__float2bfloat16(vB0 - __bfloat162float(hB0)));
            size_t idxA = ((size_t)(b_ * NSEQ + nA)) * EE + h_ * DD + col;
            size_t idxB = ((size_t)(b_ * NSEQ + nB)) * EE + h_ * DD + col;
            *(uint32_t*)(OutH + idxA) = hvA;
            *(uint32_t*)(OutL + idxA) = lvA;
            *(uint32_t*)(OutH + idxB) = hvB;
            *(uint32_t*)(OutL + idxB) = lvB;
        }
    }
}

// ---------------- launch ----------------
extern "C" void kernel_launch(void* const* d_in, const int* in_sizes, int n_in,
                              void* d_out, int out_size) {
    const float* x    = (const float*)d_in[0];
    const float* Wq   = (const float*)d_in[1];
    const float* bq   = (const float*)d_in[2];
    const float* Wk   = (const float*)d_in[3];
    const float* bk   = (const float*)d_in[4];
    const float* Wv   = (const float*)d_in[5];
    const float* bv   = (const float*)d_in[6];
    const float* Wo   = (const float*)d_in[7];
    const float* bo   = (const float*)d_in[8];
    const float* proj = (const float*)d_in[9];
    float* out = (float*)d_out;

    float *pq, *pk, *pv, *pdinv;
    __nv_bfloat16 *pah, *pal, *pwh, *pwl, *pqfh, *pqfl;
    cudaGetSymbolAddress((void**)&pq,   g_q);
    cudaGetSymbolAddress((void**)&pk,   g_k);
    cudaGetSymbolAddress((void**)&pv,   g_v);
    cudaGetSymbolAddress((void**)&pdinv, g_dinv);
    cudaGetSymbolAddress((void**)&pah,  g_ah);
    cudaGetSymbolAddress((void**)&pal,  g_al);
    cudaGetSymbolAddress((void**)&pwh,  g_wh);
    cudaGetSymbolAddress((void**)&pwl,  g_wl);
    cudaGetSymbolAddress((void**)&pqfh, g_qfh);
    cudaGetSymbolAddress((void**)&pqfl, g_qfl);

    const int GEMM_SMEM = 3 * STG_BYTES;
    const int YV_SMEM   = 3 * YV_ASTG + 2 * 32768;
    cudaFuncSetAttribute(gemm_mma<0>, cudaFuncAttributeMaxDynamicSharedMemorySize, GEMM_SMEM);
    cudaFuncSetAttribute(gemm_mma<1>, cudaFuncAttributeMaxDynamicSharedMemorySize, GEMM_SMEM);
    cudaFuncSetAttribute(ctx_fused,  cudaFuncAttributeMaxDynamicSharedMemorySize, CTXF_SMEM_BYTES);
    cudaFuncSetAttribute(qf_kernel,  cudaFuncAttributeMaxDynamicSharedMemorySize, QF_SMEM_BYTES);
    cudaFuncSetAttribute(yv_gemm,    cudaFuncAttributeMaxDynamicSharedMemorySize, YV_SMEM);

    init_kernel<<<1, 32>>>();

    split_kernel<<<2048, 256>>>(x, pah, pal, TT * EE / 4);
    split3_kernel<<<1536, 256>>>(Wq, Wk, Wv, pwh, pwl, EE * EE / 4);

    // fused Q/K/V projection: one launch, 3072 CTAs (amortized launch tail)
    gemm_mma<1><<<dim3(24, TT / 128), 256, GEMM_SMEM>>>(
        pah, pal, pwh, pwl, bq, bk, bv, pq, pk, pv);

    ctx_fused<<<dim3(BHn, NSEG), 256, CTXF_SMEM_BYTES>>>(pk, pv, proj);
    ctx_reduce_kernel<<<(BHn * MM * DD + 255) / 256, 256>>>();

    qf_kernel<<<dim3(BHn, 16), 256, QF_SMEM_BYTES>>>(pq, proj, pqfh, pqfl, pdinv);

    yv_gemm<<<dim3(NSEQ / 128, BHn), 256, YV_SMEM>>>(pqfh, pqfl, pah, pal);

    split_kernel<<<512, 256>>>(Wo, pwh, pwl, EE * EE / 4);
    gemm_mma<0><<<dim3(8, TT / 128), 256, GEMM_SMEM>>>(
        pah, pal, pwh, pwl, bo, bo, bo, out, out, out);
}